// round 7
// baseline (speedup 1.0000x reference)
#include <cuda_runtime.h>
#include <cuda_fp16.h>
#include <cuda_fp8.h>
#include <math.h>
#include <stdint.h>

#define TOPN 1000
#define BBOX_CLAMP 4.135166556742356f
#define CROSS_SCALE 524288.0f       // 2^19 = 2048 * 256
#define INV_CROSS (1.0f/524288.0f)
typedef unsigned short u16;
typedef unsigned char u8;

// ---------------- scratch (device globals) ----------------
__device__ float g_c0[64*256*256];
__device__ float g_pool[64*128*128];
__device__ float g_c1[128*64*64];
__device__ float g_c2[256*32*32];
__device__ float g_feat[512*16*16];
__device__ float g_rpn[512*16*16];
__device__ float g_obj[9*16*16];
__device__ float g_bd[36*16*16];
__device__ float g_props[2304*4];
__device__ float g_scores[2304];
__device__ int   g_topidx[TOPN];
__device__ float g_rois[TOPN*4];
__device__ u16 g_Ah[1024u*25088u];   // fp16 hi of A (roi features)
__device__ u16 g_A8[1024u*25088u];   // fp8 pairs: bytes[32c+j]=al8, bytes[32c+16+j]=a8
__device__ u16 g_B1h[1024u*25088u];  // fp16 hi of fc1_w^T
__device__ u16 g_B18[1024u*25088u];  // fp8 pairs: bh8(x256) | bl8(x2^19)
__device__ u16 g_B2h[1024u*1024u];
__device__ u16 g_B28[1024u*1024u];
__device__ u16 g_h1h[1024u*1024u];
__device__ u16 g_h18[1024u*1024u];
__device__ float g_part[16u*1024u*1024u];
__device__ float g_h2[1024u*1024u];
__device__ float g_logits[TOPN*6];
__device__ float g_breg[TOPN*24];

__device__ __forceinline__ u8 to_fp8(float x) {
    return (u8)__nv_cvt_float_to_fp8(x, __NV_SATFINITE, __NV_E4M3);
}
// A-side split: hi fp16; byte pair (al*2048, a) in fp8
__device__ __forceinline__ void splitA(float v, u16& hi, u8* lo_b, u8* hi_b) {
    __half h = __float2half_rn(v);
    hi = *(u16*)&h;
    float res = (v - __half2float(h)) * 2048.0f;
    *lo_b = to_fp8(res);
    *hi_b = to_fp8(v);
}
// B-side split: hi fp16; byte pair (b*256, bl*2^19) in fp8
__device__ __forceinline__ void splitB(float v, u16& hi, u8* h_b, u8* l_b) {
    __half h = __float2half_rn(v);
    hi = *(u16*)&h;
    float res = (v - __half2float(h)) * CROSS_SCALE;
    *h_b = to_fp8(v * 256.0f);
    *l_b = to_fp8(res);
}

// ---------------- conv0 v2: smem-tiled 7x7 s2, 4x-outputs x 4oc per thread ----------------
__global__ void conv0v2_kernel(const float* __restrict__ img,
                               const float* __restrict__ w,
                               const float* __restrict__ b,
                               float* __restrict__ out) {
    __shared__ float tile[3][37][72];
    __shared__ float ws[4][147];
    int tx = threadIdx.x, ty = threadIdx.y;
    int tid = ty*8 + tx;
    int oc0 = blockIdx.z * 4;
    int x0 = blockIdx.x * 32;
    int y0 = blockIdx.y * 16;
    int ixs = 2*x0 - 3, iys = 2*y0 - 3;
    const float mean[3] = {0.485f, 0.456f, 0.406f};
    const float istd[3] = {1.0f/0.229f, 1.0f/0.224f, 1.0f/0.225f};

    for (int i = tid; i < 3*37*72; i += 128) {
        int c = i / (37*72); int rem = i % (37*72);
        int iy = rem / 72, ix = rem % 72;
        int gy = iys + iy, gx = ixs + ix;
        float v = 0.0f;
        if (gy >= 0 && gy < 512 && gx >= 0 && gx < 512 && ix < 69)
            v = (img[(c*512 + gy)*512 + gx] - mean[c]) * istd[c];
        tile[c][iy][ix] = v;
    }
    for (int i = tid; i < 4*147; i += 128)
        ws[i/147][i%147] = w[(size_t)(oc0 + i/147)*147 + i%147];
    __syncthreads();

    float acc[4][4];
    #pragma unroll
    for (int oc = 0; oc < 4; oc++) {
        float bb = b[oc0+oc];
        #pragma unroll
        for (int xo = 0; xo < 4; xo++) acc[oc][xo] = bb;
    }
    for (int c = 0; c < 3; c++) {
        #pragma unroll
        for (int ky = 0; ky < 7; ky++) {
            const float* row = tile[c][2*ty + ky];
            float v[13];
            #pragma unroll
            for (int j = 0; j < 13; j++) v[j] = row[8*tx + j];
            #pragma unroll
            for (int kx = 0; kx < 7; kx++) {
                float w0 = ws[0][c*49 + ky*7 + kx];
                float w1 = ws[1][c*49 + ky*7 + kx];
                float w2 = ws[2][c*49 + ky*7 + kx];
                float w3 = ws[3][c*49 + ky*7 + kx];
                #pragma unroll
                for (int xo = 0; xo < 4; xo++) {
                    float vv = v[2*xo + kx];
                    acc[0][xo] = fmaf(vv, w0, acc[0][xo]);
                    acc[1][xo] = fmaf(vv, w1, acc[1][xo]);
                    acc[2][xo] = fmaf(vv, w2, acc[2][xo]);
                    acc[3][xo] = fmaf(vv, w3, acc[3][xo]);
                }
            }
        }
    }
    int y = y0 + ty;
    #pragma unroll
    for (int oc = 0; oc < 4; oc++)
        #pragma unroll
        for (int xo = 0; xo < 4; xo++)
            out[(size_t)(oc0+oc)*65536 + y*256 + x0 + tx*4 + xo] = fmaxf(acc[oc][xo], 0.0f);
}

// ---------------- maxpool 3x3 s2 p1 ----------------
__global__ void maxpool_kernel(const float* __restrict__ in, float* __restrict__ out) {
    int idx = blockIdx.x * 256 + threadIdx.x;
    if (idx >= 64*128*128) return;
    int x = idx & 127;
    int y = (idx >> 7) & 127;
    int c = idx >> 14;
    float m = -INFINITY;
    #pragma unroll
    for (int dy = 0; dy < 3; dy++) {
        int iy = 2*y - 1 + dy;
        if (iy < 0 || iy >= 256) continue;
        #pragma unroll
        for (int dx = 0; dx < 3; dx++) {
            int ix = 2*x - 1 + dx;
            if (ix < 0 || ix >= 256) continue;
            m = fmaxf(m, in[(c*256 + iy)*256 + ix]);
        }
    }
    out[idx] = m;
}

// ---------------- 3x3 conv: 4 output channels per thread ----------------
__global__ void conv3x3v2_kernel(const float* __restrict__ in,
                                 const float* __restrict__ w,
                                 const float* __restrict__ b,
                                 float* __restrict__ out,
                                 int Cin, int Hin, int Hout, int stride, int chunk) {
    extern __shared__ float ws[];
    int oc0 = blockIdx.z * 4;
    int tid = threadIdx.y * 16 + threadIdx.x;
    int x = blockIdx.x * 16 + threadIdx.x;
    int y = blockIdx.y * 16 + threadIdx.y;
    int iy0 = y*stride - 1, ix0 = x*stride - 1;
    int chunk9 = chunk * 9;
    float acc0 = b[oc0+0], acc1 = b[oc0+1], acc2 = b[oc0+2], acc3 = b[oc0+3];

    for (int c0 = 0; c0 < Cin; c0 += chunk) {
        __syncthreads();
        for (int i = tid; i < 4*chunk9; i += 256) {
            int o = i / chunk9, j = i - o*chunk9;
            ws[i] = w[(size_t)(oc0+o)*Cin*9 + (size_t)c0*9 + j];
        }
        __syncthreads();
        const float* wp0 = ws;
        const float* wp1 = ws + chunk9;
        const float* wp2 = ws + 2*chunk9;
        const float* wp3 = ws + 3*chunk9;
        for (int cl = 0; cl < chunk; cl++) {
            const float* ip = in + (size_t)(c0+cl)*Hin*Hin;
            float v[9];
            #pragma unroll
            for (int ky = 0; ky < 3; ky++) {
                int iy = iy0 + ky;
                bool oky = (iy >= 0 && iy < Hin);
                #pragma unroll
                for (int kx = 0; kx < 3; kx++) {
                    int ix = ix0 + kx;
                    v[ky*3+kx] = (oky && ix >= 0 && ix < Hin) ? ip[iy*Hin + ix] : 0.0f;
                }
            }
            int base = cl*9;
            #pragma unroll
            for (int k = 0; k < 9; k++) {
                float vk = v[k];
                acc0 = fmaf(vk, wp0[base+k], acc0);
                acc1 = fmaf(vk, wp1[base+k], acc1);
                acc2 = fmaf(vk, wp2[base+k], acc2);
                acc3 = fmaf(vk, wp3[base+k], acc3);
            }
        }
    }
    size_t pix = (size_t)y*Hout + x;
    size_t plane = (size_t)Hout*Hout;
    out[(size_t)(oc0+0)*plane + pix] = fmaxf(acc0, 0.0f);
    out[(size_t)(oc0+1)*plane + pix] = fmaxf(acc1, 0.0f);
    out[(size_t)(oc0+2)*plane + pix] = fmaxf(acc2, 0.0f);
    out[(size_t)(oc0+3)*plane + pix] = fmaxf(acc3, 0.0f);
}

// ---------------- 1x1 conv over 16x16 plane ----------------
__global__ void conv1x1_kernel(const float* __restrict__ in,
                               const float* __restrict__ w,
                               const float* __restrict__ b,
                               float* __restrict__ out, int Cin) {
    int p = threadIdx.x;
    int o = blockIdx.x;
    float acc = b[o];
    for (int c = 0; c < Cin; c++)
        acc = fmaf(in[c*256 + p], w[o*Cin + c], acc);
    out[o*256 + p] = acc;
}

// ---------------- RPN decode ----------------
__global__ void rpn_decode_kernel(const float* __restrict__ obj,
                                  const float* __restrict__ bd,
                                  float* __restrict__ props,
                                  float* __restrict__ scores) {
    int i = blockIdx.x * 256 + threadIdx.x;
    if (i >= 2304) return;
    int a = i % 9;
    int cell = i / 9;
    int wq = cell % 16;
    int hq = cell / 16;
    int pix = hq*16 + wq;
    scores[i] = obj[a*256 + pix];

    const float ratios[3] = {0.5f, 1.0f, 2.0f};
    int r = a / 3, s = a % 3;
    float scale = 128.0f * (float)(1 << s);
    float hr = sqrtf(ratios[r]);
    float wr = 1.0f / hr;
    float hw = rintf(wr * scale * 0.5f);
    float hh = rintf(hr * scale * 0.5f);
    float sx = (float)(wq * 32), sy = (float)(hq * 32);
    float W = 2.0f*hw, H = 2.0f*hh;
    float cx = sx, cy = sy;

    float dx = bd[(a*4+0)*256 + pix];
    float dy = bd[(a*4+1)*256 + pix];
    float dw = fminf(bd[(a*4+2)*256 + pix], BBOX_CLAMP);
    float dh = fminf(bd[(a*4+3)*256 + pix], BBOX_CLAMP);
    float pcx = dx*W + cx, pcy = dy*H + cy;
    float pw = expf(dw)*W, ph = expf(dh)*H;
    props[i*4+0] = pcx - 0.5f*pw;
    props[i*4+1] = pcy - 0.5f*ph;
    props[i*4+2] = pcx + 0.5f*pw;
    props[i*4+3] = pcy + 0.5f*ph;
}

// ---------------- top-k bitonic ----------------
__device__ __forceinline__ bool tk_lt(float sa, int ia, float sb, int ib) {
    return (sa > sb) || (sa == sb && ia < ib);
}
__global__ void topk_kernel(const float* __restrict__ scores, int* __restrict__ topidx) {
    __shared__ float s[4096];
    __shared__ int   ind[4096];
    int tid = threadIdx.x;
    for (int i = tid; i < 4096; i += 1024) {
        s[i] = (i < 2304) ? scores[i] : -INFINITY;
        ind[i] = i;
    }
    __syncthreads();
    for (int k = 2; k <= 4096; k <<= 1) {
        for (int j = k >> 1; j > 0; j >>= 1) {
            for (int base = 0; base < 4096; base += 1024) {
                int i = base + tid;
                int ixj = i ^ j;
                if (ixj > i) {
                    bool up = ((i & k) == 0);
                    float si = s[i], sj = s[ixj];
                    int ii = ind[i], ij = ind[ixj];
                    bool swp = up ? tk_lt(sj, ij, si, ii) : tk_lt(si, ii, sj, ij);
                    if (swp) { s[i] = sj; s[ixj] = si; ind[i] = ij; ind[ixj] = ii; }
                }
            }
            __syncthreads();
        }
    }
    for (int i = tid; i < TOPN; i += 1024) topidx[i] = ind[i];
}

__global__ void gather_rois_kernel(const float* __restrict__ props,
                                   const int* __restrict__ topidx,
                                   float* __restrict__ rois) {
    int i = blockIdx.x * 256 + threadIdx.x;
    if (i >= TOPN) return;
    int idx = topidx[i];
    #pragma unroll
    for (int k = 0; k < 4; k++)
        rois[i*4+k] = fminf(fmaxf(props[idx*4+k], 0.0f), 512.0f);
}

// ---------------- ROI align -> split A (fp16 hi + fp8 pair bytes) ----------------
__global__ void roi_align2_kernel(const float* __restrict__ feat,
                                  const float* __restrict__ rois,
                                  u16* __restrict__ Ah, u16* __restrict__ A8) {
    __shared__ float ftile[16*256];
    __shared__ int   sry[7][4]; __shared__ float swy[7][4];
    __shared__ int   srx[7][4]; __shared__ float swx[7][4];
    int rr = blockIdx.x;
    int tid = threadIdx.x;
    u8* A8b = (u8*)A8;
    if (tid < 28) {
        int i = tid % 14;
        bool isY = tid >= 14;
        float c1 = rois[rr*4 + (isY ? 1 : 0)];
        float c2 = rois[rr*4 + (isY ? 3 : 2)];
        float lo = c1 * (1.0f/32.0f);
        float hi = c2 * (1.0f/32.0f);
        float sz = fmaxf(hi - lo, 1.0f);
        float g = ((float)i + 0.5f) / 14.0f;
        float p = fminf(fmaxf(lo + g*sz, 0.0f), 15.0f);
        int p0 = (int)floorf(p);
        int p1 = min(p0 + 1, 15);
        float l = p - (float)p0;
        int pp = i >> 1, sl = (i & 1) * 2;
        float wh = 0.5f * (1.0f - l), wl = 0.5f * l;
        if (isY) { sry[pp][sl] = p0; sry[pp][sl+1] = p1; swy[pp][sl] = wh; swy[pp][sl+1] = wl; }
        else     { srx[pp][sl] = p0; srx[pp][sl+1] = p1; swx[pp][sl] = wh; swx[pp][sl+1] = wl; }
    }
    __syncthreads();
    for (int ci = 0; ci < 32; ci++) {
        const float4* src = (const float4*)(feat + (size_t)ci*16*256);
        float4* dst = (float4*)ftile;
        for (int i = tid; i < 1024; i += 256) dst[i] = src[i];
        __syncthreads();
        for (int t = tid; t < 784; t += 256) {
            int cl = t / 49, p = t % 49;
            int py = p / 7, px = p % 7;
            const float* f = ftile + cl*256;
            float acc = 0.0f;
            #pragma unroll
            for (int a = 0; a < 4; a++) {
                const float* frow = f + sry[py][a]*16;
                float s = 0.0f;
                #pragma unroll
                for (int bb = 0; bb < 4; bb++)
                    s = fmaf(swx[px][bb], frow[srx[px][bb]], s);
                acc = fmaf(swy[py][a], s, acc);
            }
            int k = (ci*16 + cl)*49 + p;
            size_t o = (size_t)rr*25088 + k;
            u8* pb = A8b + (size_t)rr*50176 + 32*(k >> 4) + (k & 15);
            splitA(acc, Ah[o], pb, pb + 16);
        }
        __syncthreads();
    }
}

// zero pad rows [1000,1024)
__global__ void padA_kernel(u16* __restrict__ Ah, u16* __restrict__ A8) {
    size_t idx = (size_t)blockIdx.x * 256 + threadIdx.x;
    size_t total = 24u*25088u;
    if (idx >= total) return;
    size_t o = (size_t)1000*25088 + idx;
    Ah[o] = 0; A8[o] = 0;
}

// ---------------- transpose + split weights (fp16 hi + fp8 pair bytes) ----------------
__global__ void tsplit_kernel(const float* __restrict__ W,
                              u16* __restrict__ Th, u16* __restrict__ T8,
                              int K, int N) {
    __shared__ float t[32][33];
    int n0 = blockIdx.x * 32, k0 = blockIdx.y * 32;
    int tx = threadIdx.x, ty = threadIdx.y;
    u8* T8b = (u8*)T8;
    #pragma unroll
    for (int i = 0; i < 4; i++)
        t[ty + 8*i][tx] = W[(size_t)(k0 + ty + 8*i)*N + n0 + tx];
    __syncthreads();
    #pragma unroll
    for (int i = 0; i < 4; i++) {
        float v = t[tx][ty + 8*i];
        int n = n0 + ty + 8*i;
        int k = k0 + tx;
        u8* pb = T8b + (size_t)n*2*K + 32*(k >> 4) + (k & 15);
        splitB(v, Th[(size_t)n*K + k], pb, pb + 16);
    }
}

// ---------------- split-precision tensor-core GEMM ----------------
// main: f16 hi x f16 hi -> f32; cross: one fp8 m16n8k32 = al*bh + a*bl (scale 2^19)
__device__ __forceinline__ void mma16816_f32(float& d0, float& d1, float& d2, float& d3,
                                             uint32_t a0, uint32_t a1, uint32_t a2, uint32_t a3,
                                             uint32_t b0, uint32_t b1) {
    asm volatile("mma.sync.aligned.m16n8k16.row.col.f32.f16.f16.f32 "
                 "{%0,%1,%2,%3}, {%4,%5,%6,%7}, {%8,%9}, {%0,%1,%2,%3};\n"
                 : "+f"(d0), "+f"(d1), "+f"(d2), "+f"(d3)
                 : "r"(a0), "r"(a1), "r"(a2), "r"(a3), "r"(b0), "r"(b1));
}
__device__ __forceinline__ void mma16832_e4m3(float& d0, float& d1, float& d2, float& d3,
                                              uint32_t a0, uint32_t a1, uint32_t a2, uint32_t a3,
                                              uint32_t b0, uint32_t b1) {
    asm volatile("mma.sync.aligned.m16n8k32.row.col.f32.e4m3.e4m3.f32 "
                 "{%0,%1,%2,%3}, {%4,%5,%6,%7}, {%8,%9}, {%0,%1,%2,%3};\n"
                 : "+f"(d0), "+f"(d1), "+f"(d2), "+f"(d3)
                 : "r"(a0), "r"(a1), "r"(a2), "r"(a3), "r"(b0), "r"(b1));
}
__device__ __forceinline__ void cpasync16(uint32_t dst, const void* src) {
    asm volatile("cp.async.cg.shared.global [%0], [%1], 16;\n" :: "r"(dst), "l"(src));
}
__device__ __forceinline__ void ldsm_x4(uint32_t& r0, uint32_t& r1, uint32_t& r2, uint32_t& r3,
                                        uint32_t addr) {
    asm volatile("ldmatrix.sync.aligned.m8n8.x4.shared.b16 {%0,%1,%2,%3}, [%4];\n"
                 : "=r"(r0), "=r"(r1), "=r"(r2), "=r"(r3) : "r"(addr));
}

#define LDK 24   // u16 elems per smem row (48B; stride-48 hits all eight 16B banks)

__global__ void __launch_bounds__(256, 1)
gemm_split_kernel(const u16* __restrict__ Ah, const u16* __restrict__ A8,
                  const u16* __restrict__ Bh, const u16* __restrict__ B8,
                  float* __restrict__ part, int K, int stages) {
    __shared__ __align__(16) u16 sm[2][4][128*LDK];
    int tid = threadIdx.x;
    int wid = tid >> 5, lane = tid & 31;
    int wm = (wid & 1) * 64;
    int wn = (wid >> 1) * 32;
    int g = lane >> 2, tig = lane & 3;
    int r8 = lane & 7, q = lane >> 3;
    int bm = blockIdx.y * 128, bn = blockIdx.x * 128;
    int kbase = blockIdx.z * stages * 16;

    float acc[16][4];     // main (f16 hi x hi)
    float accx[16][4];    // cross (fp8), scale 2^-19
    #pragma unroll
    for (int i = 0; i < 16; i++)
        #pragma unroll
        for (int j = 0; j < 4; j++) { acc[i][j] = 0.0f; accx[i][j] = 0.0f; }

    uint32_t smb = (uint32_t)__cvta_generic_to_shared(&sm[0][0][0]);
    const uint32_t MAT = 128*LDK*2;
    const uint32_t BUF = 4*MAT;
    uint32_t offA = (uint32_t)(((wm + (q & 1)*8 + r8)*LDK + (q >> 1)*8) * 2);
    uint32_t offB = (uint32_t)(((wn + (q >> 1)*8 + r8)*LDK + (q & 1)*8) * 2);

    auto load_stage = [&](int buf, int s) {
        int kpos0 = kbase + s * 16;
        #pragma unroll
        for (int l = 0; l < 4; l++) {
            int idx = l * 256 + tid;
            int pl = idx >> 8;
            int rr = (idx & 255) >> 1;
            int half = idx & 1;
            int kpos = kpos0 + half * 8;
            const u16* src;
            if (pl == 0)      src = Ah + (size_t)(bm + rr)*K + kpos;
            else if (pl == 1) src = A8 + (size_t)(bm + rr)*K + kpos;
            else if (pl == 2) src = Bh + (size_t)(bn + rr)*K + kpos;
            else              src = B8 + (size_t)(bn + rr)*K + kpos;
            uint32_t dst = (uint32_t)__cvta_generic_to_shared(&sm[buf][pl][rr*LDK + half*8]);
            cpasync16(dst, src);
        }
        asm volatile("cp.async.commit_group;\n");
    };

    load_stage(0, 0);

    for (int s = 0; s < stages; s++) {
        if (s + 1 < stages) {
            load_stage((s + 1) & 1, s + 1);
            asm volatile("cp.async.wait_group 1;\n");
        } else {
            asm volatile("cp.async.wait_group 0;\n");
        }
        __syncthreads();
        uint32_t base = smb + (uint32_t)(s & 1)*BUF;
        uint32_t aAh = base + offA;
        uint32_t aA8 = base + MAT + offA;
        uint32_t aBh = base + 2*MAT + offB;
        uint32_t aB8 = base + 3*MAT + offB;

        uint32_t bh[4][2], b8[4][2], ah[4][4], a8[4][4];
        #pragma unroll
        for (int p = 0; p < 2; p++) {
            ldsm_x4(bh[2*p][0], bh[2*p][1], bh[2*p+1][0], bh[2*p+1][1], aBh + p*16*LDK*2);
            ldsm_x4(b8[2*p][0], b8[2*p][1], b8[2*p+1][0], b8[2*p+1][1], aB8 + p*16*LDK*2);
        }
        #pragma unroll
        for (int mi = 0; mi < 4; mi++) {
            ldsm_x4(ah[mi][0], ah[mi][1], ah[mi][2], ah[mi][3], aAh + mi*16*LDK*2);
            ldsm_x4(a8[mi][0], a8[mi][1], a8[mi][2], a8[mi][3], aA8 + mi*16*LDK*2);
        }

        // main pass: f16 hi x hi -> f32
        #pragma unroll
        for (int mi = 0; mi < 4; mi++)
            #pragma unroll
            for (int ni = 0; ni < 4; ni++) {
                float* d = acc[mi*4 + ni];
                mma16816_f32(d[0], d[1], d[2], d[3],
                             ah[mi][0], ah[mi][1], ah[mi][2], ah[mi][3], bh[ni][0], bh[ni][1]);
            }
        // cross pass: one fp8 k32 MMA = al*bh + a*bl (scale 2^19)
        #pragma unroll
        for (int mi = 0; mi < 4; mi++)
            #pragma unroll
            for (int ni = 0; ni < 4; ni++) {
                float* d = accx[mi*4 + ni];
                mma16832_e4m3(d[0], d[1], d[2], d[3],
                              a8[mi][0], a8[mi][1], a8[mi][2], a8[mi][3], b8[ni][0], b8[ni][1]);
            }
        __syncthreads();
    }

    float* cbase = part + ((size_t)blockIdx.z << 20);
    #pragma unroll
    for (int mi = 0; mi < 4; mi++) {
        #pragma unroll
        for (int ni = 0; ni < 4; ni++) {
            int row = bm + wm + mi*16 + g;
            int col = bn + wn + ni*8 + 2*tig;
            float* d = acc[mi*4 + ni];
            float* x = accx[mi*4 + ni];
            *(float2*)&cbase[(size_t)row*1024 + col] =
                make_float2(fmaf(x[0], INV_CROSS, d[0]), fmaf(x[1], INV_CROSS, d[1]));
            *(float2*)&cbase[(size_t)(row+8)*1024 + col] =
                make_float2(fmaf(x[2], INV_CROSS, d[2]), fmaf(x[3], INV_CROSS, d[3]));
        }
    }
}

// reduce fc1 partials -> relu -> split h1 (A-side format)
__global__ void reduce1_kernel(const float* __restrict__ part,
                               const float* __restrict__ bias,
                               u16* __restrict__ Hh, u16* __restrict__ H8) {
    size_t idx = (size_t)blockIdx.x * 256 + threadIdx.x;
    int n = (int)(idx & 1023);
    float s = bias[n];
    #pragma unroll
    for (int i = 0; i < 16; i++) s += part[((size_t)i << 20) + idx];
    s = fmaxf(s, 0.0f);
    int r = (int)(idx >> 10);
    u8* pb = (u8*)H8 + (size_t)r*2048 + 32*(n >> 4) + (n & 15);
    splitA(s, Hh[idx], pb, pb + 16);
}

// reduce fc2 partials -> relu -> f32 h2
__global__ void reduce2_kernel(const float* __restrict__ part,
                               const float* __restrict__ bias,
                               float* __restrict__ H) {
    size_t idx = (size_t)blockIdx.x * 256 + threadIdx.x;
    int n = (int)(idx & 1023);
    float s = bias[n];
    #pragma unroll
    for (int i = 0; i < 4; i++) s += part[((size_t)i << 20) + idx];
    H[idx] = fmaxf(s, 0.0f);
}

// ---------------- cls + bbox heads ----------------
__global__ void fc_small_kernel(const float* __restrict__ h,
                                const float* __restrict__ clsw, const float* __restrict__ clsb,
                                const float* __restrict__ bbw, const float* __restrict__ bbb,
                                float* __restrict__ logits, float* __restrict__ breg) {
    int t = blockIdx.x * 128 + threadIdx.x;
    if (t >= TOPN * 30) return;
    int r = t / 30, j = t % 30;
    const float* hp = h + (size_t)r*1024;
    if (j < 6) {
        float acc = clsb[j];
        for (int k = 0; k < 1024; k++) acc = fmaf(hp[k], clsw[k*6 + j], acc);
        logits[r*6 + j] = acc;
    } else {
        int q = j - 6;
        float acc = bbb[q];
        for (int k = 0; k < 1024; k++) acc = fmaf(hp[k], bbw[k*24 + q], acc);
        breg[r*24 + q] = acc;
    }
}

// ---------------- final ----------------
__global__ void final_kernel(const float* __restrict__ rois,
                             const float* __restrict__ logits,
                             const float* __restrict__ breg,
                             float* __restrict__ out) {
    int r = blockIdx.x * 128 + threadIdx.x;
    if (r >= TOPN) return;
    float l[6];
    float m = -INFINITY;
    #pragma unroll
    for (int i = 0; i < 6; i++) { l[i] = logits[r*6 + i]; m = fmaxf(m, l[i]); }
    float ssum = 0.0f;
    #pragma unroll
    for (int i = 0; i < 6; i++) { l[i] = expf(l[i] - m); ssum += l[i]; }
    float inv = 1.0f / ssum;

    float x1 = rois[r*4+0], y1 = rois[r*4+1], x2 = rois[r*4+2], y2 = rois[r*4+3];
    float W = x2 - x1, H = y2 - y1;
    float cx = x1 + 0.5f*W, cy = y1 + 0.5f*H;
    #pragma unroll
    for (int c = 1; c < 6; c++) {
        float dx = breg[r*24 + c*4+0] / 10.0f;
        float dy = breg[r*24 + c*4+1] / 10.0f;
        float dw = fminf(breg[r*24 + c*4+2] / 5.0f, BBOX_CLAMP);
        float dh = fminf(breg[r*24 + c*4+3] / 5.0f, BBOX_CLAMP);
        float pcx = dx*W + cx, pcy = dy*H + cy;
        float pw = expf(dw)*W, ph = expf(dh)*H;
        float bx1 = fminf(fmaxf(pcx - 0.5f*pw, 0.0f), 512.0f);
        float by1 = fminf(fmaxf(pcy - 0.5f*ph, 0.0f), 512.0f);
        float bx2 = fminf(fmaxf(pcx + 0.5f*pw, 0.0f), 512.0f);
        float by2 = fminf(fmaxf(pcy + 0.5f*ph, 0.0f), 512.0f);
        int o = r*25 + (c-1)*5;
        out[o+0] = bx1; out[o+1] = by1; out[o+2] = bx2; out[o+3] = by2;
        out[o+4] = l[c] * inv;
    }
}

// ---------------- launcher ----------------
extern "C" void kernel_launch(void* const* d_in, const int* in_sizes, int n_in,
                              void* d_out, int out_size) {
    const float* images     = (const float*)d_in[0];
    const float* c0_w       = (const float*)d_in[1];
    const float* c0_b       = (const float*)d_in[2];
    const float* c1_w       = (const float*)d_in[3];
    const float* c1_b       = (const float*)d_in[4];
    const float* c2_w       = (const float*)d_in[5];
    const float* c2_b       = (const float*)d_in[6];
    const float* c3_w       = (const float*)d_in[7];
    const float* c3_b       = (const float*)d_in[8];
    const float* rpn_conv_w = (const float*)d_in[9];
    const float* rpn_conv_b = (const float*)d_in[10];
    const float* rpn_cls_w  = (const float*)d_in[11];
    const float* rpn_cls_b  = (const float*)d_in[12];
    const float* rpn_bbox_w = (const float*)d_in[13];
    const float* rpn_bbox_b = (const float*)d_in[14];
    const float* fc1_w      = (const float*)d_in[15];
    const float* fc1_b      = (const float*)d_in[16];
    const float* fc2_w      = (const float*)d_in[17];
    const float* fc2_b      = (const float*)d_in[18];
    const float* cls_w      = (const float*)d_in[19];
    const float* cls_b      = (const float*)d_in[20];
    const float* bbox_w     = (const float*)d_in[21];
    const float* bbox_b     = (const float*)d_in[22];
    float* out = (float*)d_out;

    float *p_c0, *p_pool, *p_c1, *p_c2, *p_feat, *p_rpn, *p_obj, *p_bd;
    float *p_props, *p_scores, *p_rois, *p_part, *p_h2, *p_logits, *p_breg;
    int *p_topidx;
    u16 *p_Ah, *p_A8, *p_B1h, *p_B18, *p_B2h, *p_B28, *p_h1h, *p_h18;
    cudaGetSymbolAddress((void**)&p_c0, g_c0);
    cudaGetSymbolAddress((void**)&p_pool, g_pool);
    cudaGetSymbolAddress((void**)&p_c1, g_c1);
    cudaGetSymbolAddress((void**)&p_c2, g_c2);
    cudaGetSymbolAddress((void**)&p_feat, g_feat);
    cudaGetSymbolAddress((void**)&p_rpn, g_rpn);
    cudaGetSymbolAddress((void**)&p_obj, g_obj);
    cudaGetSymbolAddress((void**)&p_bd, g_bd);
    cudaGetSymbolAddress((void**)&p_props, g_props);
    cudaGetSymbolAddress((void**)&p_scores, g_scores);
    cudaGetSymbolAddress((void**)&p_topidx, g_topidx);
    cudaGetSymbolAddress((void**)&p_rois, g_rois);
    cudaGetSymbolAddress((void**)&p_Ah, g_Ah);
    cudaGetSymbolAddress((void**)&p_A8, g_A8);
    cudaGetSymbolAddress((void**)&p_B1h, g_B1h);
    cudaGetSymbolAddress((void**)&p_B18, g_B18);
    cudaGetSymbolAddress((void**)&p_B2h, g_B2h);
    cudaGetSymbolAddress((void**)&p_B28, g_B28);
    cudaGetSymbolAddress((void**)&p_h1h, g_h1h);
    cudaGetSymbolAddress((void**)&p_h18, g_h18);
    cudaGetSymbolAddress((void**)&p_part, g_part);
    cudaGetSymbolAddress((void**)&p_h2, g_h2);
    cudaGetSymbolAddress((void**)&p_logits, g_logits);
    cudaGetSymbolAddress((void**)&p_breg, g_breg);

    // weight transpose+split
    tsplit_kernel<<<dim3(1024/32, 25088/32), dim3(32,8)>>>(fc1_w, p_B1h, p_B18, 25088, 1024);
    tsplit_kernel<<<dim3(1024/32, 1024/32),  dim3(32,8)>>>(fc2_w, p_B2h, p_B28, 1024, 1024);

    // backbone
    conv0v2_kernel<<<dim3(8,16,16), dim3(8,16)>>>(images, c0_w, c0_b, p_c0);
    maxpool_kernel<<<(64*128*128 + 255)/256, 256>>>(p_c0, p_pool);
    conv3x3v2_kernel<<<dim3(4,4,32), dim3(16,16),  4*64*9*4>>>(p_pool, c1_w, c1_b, p_c1, 64, 128, 64, 2, 64);
    conv3x3v2_kernel<<<dim3(2,2,64), dim3(16,16), 4*128*9*4>>>(p_c1, c2_w, c2_b, p_c2, 128, 64, 32, 2, 128);
    conv3x3v2_kernel<<<dim3(1,1,128), dim3(16,16), 4*128*9*4>>>(p_c2, c3_w, c3_b, p_feat, 256, 32, 16, 2, 128);

    // RPN
    conv3x3v2_kernel<<<dim3(1,1,128), dim3(16,16), 4*128*9*4>>>(p_feat, rpn_conv_w, rpn_conv_b, p_rpn, 512, 16, 16, 1, 128);
    conv1x1_kernel<<<9, 256>>>(p_rpn, rpn_cls_w, rpn_cls_b, p_obj, 512);
    conv1x1_kernel<<<36, 256>>>(p_rpn, rpn_bbox_w, rpn_bbox_b, p_bd, 512);

    // proposals
    rpn_decode_kernel<<<9, 256>>>(p_obj, p_bd, p_props, p_scores);
    topk_kernel<<<1, 1024>>>(p_scores, p_topidx);
    gather_rois_kernel<<<4, 256>>>(p_props, p_topidx, p_rois);

    // roi align -> split A
    roi_align2_kernel<<<TOPN, 256>>>(p_feat, p_rois, p_Ah, p_A8);
    padA_kernel<<<(24*25088 + 255)/256, 256>>>(p_Ah, p_A8);

    // fc1: K=25088, z=16 -> stages 98
    gemm_split_kernel<<<dim3(8,8,16), 256>>>(p_Ah, p_A8, p_B1h, p_B18, p_part, 25088, 98);
    reduce1_kernel<<<(1024*1024)/256, 256>>>(p_part, fc1_b, p_h1h, p_h18);

    // fc2: K=1024, z=4 -> stages 16
    gemm_split_kernel<<<dim3(8,8,4), 256>>>(p_h1h, p_h18, p_B2h, p_B28, p_part, 1024, 16);
    reduce2_kernel<<<(1024*1024)/256, 256>>>(p_part, fc2_b, p_h2);

    fc_small_kernel<<<(TOPN*30 + 127)/128, 128>>>(p_h2, cls_w, cls_b, bbox_w, bbox_b, p_logits, p_breg);
    final_kernel<<<(TOPN + 127)/128, 128>>>(p_rois, p_logits, p_breg, out);
}

// round 8
// speedup vs baseline: 1.3734x; 1.3734x over previous
#include <cuda_runtime.h>
#include <cuda_fp16.h>
#include <math.h>
#include <stdint.h>

#define TOPN 1000
#define BBOX_CLAMP 4.135166556742356f
typedef unsigned short u16;

// ---------------- scratch (device globals) ----------------
__device__ float g_c0[64*256*256];
__device__ float g_pool[64*128*128];
__device__ float g_c1[128*64*64];
__device__ float g_c2[256*32*32];
__device__ float g_feat[512*16*16];
__device__ float g_rpn[512*16*16];
__device__ float g_obj[9*16*16];
__device__ float g_bd[36*16*16];
__device__ float g_props[2304*4];
__device__ float g_scores[2304];
__device__ int   g_topidx[TOPN];
__device__ float g_rois[TOPN*4];
__device__ u16 g_Ah[1024u*25088u];   // fp16 roi features [1024][25088]
__device__ u16 g_B1h[1024u*25088u];  // fp16 fc1_w^T [1024][25088]
__device__ u16 g_B2h[1024u*1024u];   // fp16 fc2_w^T
__device__ u16 g_h1h[1024u*1024u];   // fp16 h1
__device__ float g_part[16u*1024u*1024u];
__device__ float g_h2[1024u*1024u];
__device__ float g_logits[TOPN*6];
__device__ float g_breg[TOPN*24];

// ---------------- conv0 v2: smem-tiled 7x7 s2, 4x-outputs x 4oc per thread ----------------
__global__ void conv0v2_kernel(const float* __restrict__ img,
                               const float* __restrict__ w,
                               const float* __restrict__ b,
                               float* __restrict__ out) {
    __shared__ float tile[3][37][72];
    __shared__ float ws[4][147];
    int tx = threadIdx.x, ty = threadIdx.y;
    int tid = ty*8 + tx;
    int oc0 = blockIdx.z * 4;
    int x0 = blockIdx.x * 32;
    int y0 = blockIdx.y * 16;
    int ixs = 2*x0 - 3, iys = 2*y0 - 3;
    const float mean[3] = {0.485f, 0.456f, 0.406f};
    const float istd[3] = {1.0f/0.229f, 1.0f/0.224f, 1.0f/0.225f};

    for (int i = tid; i < 3*37*72; i += 128) {
        int c = i / (37*72); int rem = i % (37*72);
        int iy = rem / 72, ix = rem % 72;
        int gy = iys + iy, gx = ixs + ix;
        float v = 0.0f;
        if (gy >= 0 && gy < 512 && gx >= 0 && gx < 512 && ix < 69)
            v = (img[(c*512 + gy)*512 + gx] - mean[c]) * istd[c];
        tile[c][iy][ix] = v;
    }
    for (int i = tid; i < 4*147; i += 128)
        ws[i/147][i%147] = w[(size_t)(oc0 + i/147)*147 + i%147];
    __syncthreads();

    float acc[4][4];
    #pragma unroll
    for (int oc = 0; oc < 4; oc++) {
        float bb = b[oc0+oc];
        #pragma unroll
        for (int xo = 0; xo < 4; xo++) acc[oc][xo] = bb;
    }
    for (int c = 0; c < 3; c++) {
        #pragma unroll
        for (int ky = 0; ky < 7; ky++) {
            const float* row = tile[c][2*ty + ky];
            float v[13];
            #pragma unroll
            for (int j = 0; j < 13; j++) v[j] = row[8*tx + j];
            #pragma unroll
            for (int kx = 0; kx < 7; kx++) {
                float w0 = ws[0][c*49 + ky*7 + kx];
                float w1 = ws[1][c*49 + ky*7 + kx];
                float w2 = ws[2][c*49 + ky*7 + kx];
                float w3 = ws[3][c*49 + ky*7 + kx];
                #pragma unroll
                for (int xo = 0; xo < 4; xo++) {
                    float vv = v[2*xo + kx];
                    acc[0][xo] = fmaf(vv, w0, acc[0][xo]);
                    acc[1][xo] = fmaf(vv, w1, acc[1][xo]);
                    acc[2][xo] = fmaf(vv, w2, acc[2][xo]);
                    acc[3][xo] = fmaf(vv, w3, acc[3][xo]);
                }
            }
        }
    }
    int y = y0 + ty;
    #pragma unroll
    for (int oc = 0; oc < 4; oc++)
        #pragma unroll
        for (int xo = 0; xo < 4; xo++)
            out[(size_t)(oc0+oc)*65536 + y*256 + x0 + tx*4 + xo] = fmaxf(acc[oc][xo], 0.0f);
}

// ---------------- maxpool 3x3 s2 p1 ----------------
__global__ void maxpool_kernel(const float* __restrict__ in, float* __restrict__ out) {
    int idx = blockIdx.x * 256 + threadIdx.x;
    if (idx >= 64*128*128) return;
    int x = idx & 127;
    int y = (idx >> 7) & 127;
    int c = idx >> 14;
    float m = -INFINITY;
    #pragma unroll
    for (int dy = 0; dy < 3; dy++) {
        int iy = 2*y - 1 + dy;
        if (iy < 0 || iy >= 256) continue;
        #pragma unroll
        for (int dx = 0; dx < 3; dx++) {
            int ix = 2*x - 1 + dx;
            if (ix < 0 || ix >= 256) continue;
            m = fmaxf(m, in[(c*256 + iy)*256 + ix]);
        }
    }
    out[idx] = m;
}

// ---------------- 3x3 conv: 4 output channels per thread ----------------
__global__ void conv3x3v2_kernel(const float* __restrict__ in,
                                 const float* __restrict__ w,
                                 const float* __restrict__ b,
                                 float* __restrict__ out,
                                 int Cin, int Hin, int Hout, int stride, int chunk) {
    extern __shared__ float ws[];
    int oc0 = blockIdx.z * 4;
    int tid = threadIdx.y * 16 + threadIdx.x;
    int x = blockIdx.x * 16 + threadIdx.x;
    int y = blockIdx.y * 16 + threadIdx.y;
    int iy0 = y*stride - 1, ix0 = x*stride - 1;
    int chunk9 = chunk * 9;
    float acc0 = b[oc0+0], acc1 = b[oc0+1], acc2 = b[oc0+2], acc3 = b[oc0+3];

    for (int c0 = 0; c0 < Cin; c0 += chunk) {
        __syncthreads();
        for (int i = tid; i < 4*chunk9; i += 256) {
            int o = i / chunk9, j = i - o*chunk9;
            ws[i] = w[(size_t)(oc0+o)*Cin*9 + (size_t)c0*9 + j];
        }
        __syncthreads();
        const float* wp0 = ws;
        const float* wp1 = ws + chunk9;
        const float* wp2 = ws + 2*chunk9;
        const float* wp3 = ws + 3*chunk9;
        for (int cl = 0; cl < chunk; cl++) {
            const float* ip = in + (size_t)(c0+cl)*Hin*Hin;
            float v[9];
            #pragma unroll
            for (int ky = 0; ky < 3; ky++) {
                int iy = iy0 + ky;
                bool oky = (iy >= 0 && iy < Hin);
                #pragma unroll
                for (int kx = 0; kx < 3; kx++) {
                    int ix = ix0 + kx;
                    v[ky*3+kx] = (oky && ix >= 0 && ix < Hin) ? ip[iy*Hin + ix] : 0.0f;
                }
            }
            int base = cl*9;
            #pragma unroll
            for (int k = 0; k < 9; k++) {
                float vk = v[k];
                acc0 = fmaf(vk, wp0[base+k], acc0);
                acc1 = fmaf(vk, wp1[base+k], acc1);
                acc2 = fmaf(vk, wp2[base+k], acc2);
                acc3 = fmaf(vk, wp3[base+k], acc3);
            }
        }
    }
    size_t pix = (size_t)y*Hout + x;
    size_t plane = (size_t)Hout*Hout;
    out[(size_t)(oc0+0)*plane + pix] = fmaxf(acc0, 0.0f);
    out[(size_t)(oc0+1)*plane + pix] = fmaxf(acc1, 0.0f);
    out[(size_t)(oc0+2)*plane + pix] = fmaxf(acc2, 0.0f);
    out[(size_t)(oc0+3)*plane + pix] = fmaxf(acc3, 0.0f);
}

// ---------------- 1x1 conv over 16x16 plane ----------------
__global__ void conv1x1_kernel(const float* __restrict__ in,
                               const float* __restrict__ w,
                               const float* __restrict__ b,
                               float* __restrict__ out, int Cin) {
    int p = threadIdx.x;
    int o = blockIdx.x;
    float acc = b[o];
    for (int c = 0; c < Cin; c++)
        acc = fmaf(in[c*256 + p], w[o*Cin + c], acc);
    out[o*256 + p] = acc;
}

// ---------------- RPN decode ----------------
__global__ void rpn_decode_kernel(const float* __restrict__ obj,
                                  const float* __restrict__ bd,
                                  float* __restrict__ props,
                                  float* __restrict__ scores) {
    int i = blockIdx.x * 256 + threadIdx.x;
    if (i >= 2304) return;
    int a = i % 9;
    int cell = i / 9;
    int wq = cell % 16;
    int hq = cell / 16;
    int pix = hq*16 + wq;
    scores[i] = obj[a*256 + pix];

    const float ratios[3] = {0.5f, 1.0f, 2.0f};
    int r = a / 3, s = a % 3;
    float scale = 128.0f * (float)(1 << s);
    float hr = sqrtf(ratios[r]);
    float wr = 1.0f / hr;
    float hw = rintf(wr * scale * 0.5f);
    float hh = rintf(hr * scale * 0.5f);
    float sx = (float)(wq * 32), sy = (float)(hq * 32);
    float W = 2.0f*hw, H = 2.0f*hh;
    float cx = sx, cy = sy;

    float dx = bd[(a*4+0)*256 + pix];
    float dy = bd[(a*4+1)*256 + pix];
    float dw = fminf(bd[(a*4+2)*256 + pix], BBOX_CLAMP);
    float dh = fminf(bd[(a*4+3)*256 + pix], BBOX_CLAMP);
    float pcx = dx*W + cx, pcy = dy*H + cy;
    float pw = expf(dw)*W, ph = expf(dh)*H;
    props[i*4+0] = pcx - 0.5f*pw;
    props[i*4+1] = pcy - 0.5f*ph;
    props[i*4+2] = pcx + 0.5f*pw;
    props[i*4+3] = pcy + 0.5f*ph;
}

// ---------------- top-k bitonic ----------------
__device__ __forceinline__ bool tk_lt(float sa, int ia, float sb, int ib) {
    return (sa > sb) || (sa == sb && ia < ib);
}
__global__ void topk_kernel(const float* __restrict__ scores, int* __restrict__ topidx) {
    __shared__ float s[4096];
    __shared__ int   ind[4096];
    int tid = threadIdx.x;
    for (int i = tid; i < 4096; i += 1024) {
        s[i] = (i < 2304) ? scores[i] : -INFINITY;
        ind[i] = i;
    }
    __syncthreads();
    for (int k = 2; k <= 4096; k <<= 1) {
        for (int j = k >> 1; j > 0; j >>= 1) {
            for (int base = 0; base < 4096; base += 1024) {
                int i = base + tid;
                int ixj = i ^ j;
                if (ixj > i) {
                    bool up = ((i & k) == 0);
                    float si = s[i], sj = s[ixj];
                    int ii = ind[i], ij = ind[ixj];
                    bool swp = up ? tk_lt(sj, ij, si, ii) : tk_lt(si, ii, sj, ij);
                    if (swp) { s[i] = sj; s[ixj] = si; ind[i] = ij; ind[ixj] = ii; }
                }
            }
            __syncthreads();
        }
    }
    for (int i = tid; i < TOPN; i += 1024) topidx[i] = ind[i];
}

__global__ void gather_rois_kernel(const float* __restrict__ props,
                                   const int* __restrict__ topidx,
                                   float* __restrict__ rois) {
    int i = blockIdx.x * 256 + threadIdx.x;
    if (i >= TOPN) return;
    int idx = topidx[i];
    #pragma unroll
    for (int k = 0; k < 4; k++)
        rois[i*4+k] = fminf(fmaxf(props[idx*4+k], 0.0f), 512.0f);
}

// ---------------- ROI align -> fp16 A matrix ----------------
__global__ void roi_align2_kernel(const float* __restrict__ feat,
                                  const float* __restrict__ rois,
                                  u16* __restrict__ Ah) {
    __shared__ float ftile[16*256];
    __shared__ int   sry[7][4]; __shared__ float swy[7][4];
    __shared__ int   srx[7][4]; __shared__ float swx[7][4];
    int rr = blockIdx.x;
    int tid = threadIdx.x;
    if (tid < 28) {
        int i = tid % 14;
        bool isY = tid >= 14;
        float c1 = rois[rr*4 + (isY ? 1 : 0)];
        float c2 = rois[rr*4 + (isY ? 3 : 2)];
        float lo = c1 * (1.0f/32.0f);
        float hi = c2 * (1.0f/32.0f);
        float sz = fmaxf(hi - lo, 1.0f);
        float g = ((float)i + 0.5f) / 14.0f;
        float p = fminf(fmaxf(lo + g*sz, 0.0f), 15.0f);
        int p0 = (int)floorf(p);
        int p1 = min(p0 + 1, 15);
        float l = p - (float)p0;
        int pp = i >> 1, sl = (i & 1) * 2;
        float wh = 0.5f * (1.0f - l), wl = 0.5f * l;
        if (isY) { sry[pp][sl] = p0; sry[pp][sl+1] = p1; swy[pp][sl] = wh; swy[pp][sl+1] = wl; }
        else     { srx[pp][sl] = p0; srx[pp][sl+1] = p1; swx[pp][sl] = wh; swx[pp][sl+1] = wl; }
    }
    __syncthreads();
    for (int ci = 0; ci < 32; ci++) {
        const float4* src = (const float4*)(feat + (size_t)ci*16*256);
        float4* dst = (float4*)ftile;
        for (int i = tid; i < 1024; i += 256) dst[i] = src[i];
        __syncthreads();
        for (int t = tid; t < 784; t += 256) {
            int cl = t / 49, p = t % 49;
            int py = p / 7, px = p % 7;
            const float* f = ftile + cl*256;
            float acc = 0.0f;
            #pragma unroll
            for (int a = 0; a < 4; a++) {
                const float* frow = f + sry[py][a]*16;
                float s = 0.0f;
                #pragma unroll
                for (int bb = 0; bb < 4; bb++)
                    s = fmaf(swx[px][bb], frow[srx[px][bb]], s);
                acc = fmaf(swy[py][a], s, acc);
            }
            __half h = __float2half_rn(acc);
            Ah[(size_t)rr*25088 + (size_t)(ci*16 + cl)*49 + p] = *(u16*)&h;
        }
        __syncthreads();
    }
}

// zero pad rows [1000,1024)
__global__ void padA_kernel(u16* __restrict__ Ah) {
    size_t idx = (size_t)blockIdx.x * 256 + threadIdx.x;
    size_t total = 24u*25088u;
    if (idx >= total) return;
    Ah[(size_t)1000*25088 + idx] = 0;
}

// ---------------- transpose + fp16 weights: W[K][N] -> T[N][K] ----------------
__global__ void tsplit_kernel(const float* __restrict__ W,
                              u16* __restrict__ Th, int K, int N) {
    __shared__ float t[32][33];
    int n0 = blockIdx.x * 32, k0 = blockIdx.y * 32;
    int tx = threadIdx.x, ty = threadIdx.y;
    #pragma unroll
    for (int i = 0; i < 4; i++)
        t[ty + 8*i][tx] = W[(size_t)(k0 + ty + 8*i)*N + n0 + tx];
    __syncthreads();
    #pragma unroll
    for (int i = 0; i < 4; i++) {
        __half h = __float2half_rn(t[tx][ty + 8*i]);
        Th[(size_t)(n0 + ty + 8*i)*K + k0 + tx] = *(u16*)&h;
    }
}

// ---------------- single-pass fp16 tensor-core GEMM ----------------
__device__ __forceinline__ void mma16816_f32(float& d0, float& d1, float& d2, float& d3,
                                             uint32_t a0, uint32_t a1, uint32_t a2, uint32_t a3,
                                             uint32_t b0, uint32_t b1) {
    asm volatile("mma.sync.aligned.m16n8k16.row.col.f32.f16.f16.f32 "
                 "{%0,%1,%2,%3}, {%4,%5,%6,%7}, {%8,%9}, {%0,%1,%2,%3};\n"
                 : "+f"(d0), "+f"(d1), "+f"(d2), "+f"(d3)
                 : "r"(a0), "r"(a1), "r"(a2), "r"(a3), "r"(b0), "r"(b1));
}
__device__ __forceinline__ void cpasync16(uint32_t dst, const void* src) {
    asm volatile("cp.async.cg.shared.global [%0], [%1], 16;\n" :: "r"(dst), "l"(src));
}
__device__ __forceinline__ void ldsm_x4(uint32_t& r0, uint32_t& r1, uint32_t& r2, uint32_t& r3,
                                        uint32_t addr) {
    asm volatile("ldmatrix.sync.aligned.m8n8.x4.shared.b16 {%0,%1,%2,%3}, [%4];\n"
                 : "=r"(r0), "=r"(r1), "=r"(r2), "=r"(r3) : "r"(addr));
}

#define LDK 24   // fp16 elems per smem row (48B; stride-48 hits all eight 16B banks)

__global__ void __launch_bounds__(256)
gemm_fp16_kernel(const u16* __restrict__ A, const u16* __restrict__ B,
                 float* __restrict__ part, int K, int stages) {
    __shared__ __align__(16) u16 sm[2][2][128*LDK];
    int tid = threadIdx.x;
    int wid = tid >> 5, lane = tid & 31;
    int wm = (wid & 1) * 64;
    int wn = (wid >> 1) * 32;
    int g = lane >> 2, tig = lane & 3;
    int r8 = lane & 7, q = lane >> 3;
    int bm = blockIdx.y * 128, bn = blockIdx.x * 128;
    int kbase = blockIdx.z * stages * 16;

    float acc[16][4];
    #pragma unroll
    for (int i = 0; i < 16; i++)
        #pragma unroll
        for (int j = 0; j < 4; j++) acc[i][j] = 0.0f;

    uint32_t smb = (uint32_t)__cvta_generic_to_shared(&sm[0][0][0]);
    const uint32_t MAT = 128*LDK*2;
    const uint32_t BUF = 2*MAT;
    uint32_t offA = (uint32_t)(((wm + (q & 1)*8 + r8)*LDK + (q >> 1)*8) * 2);
    uint32_t offB = (uint32_t)(((wn + (q >> 1)*8 + r8)*LDK + (q & 1)*8) * 2);

    auto load_stage = [&](int buf, int s) {
        int kpos0 = kbase + s * 16;
        #pragma unroll
        for (int l = 0; l < 2; l++) {
            int idx = l * 256 + tid;
            int pl = idx >> 8;
            int rr = (idx & 255) >> 1;
            int half = idx & 1;
            const u16* src = (pl ? B + (size_t)(bn + rr)*K : A + (size_t)(bm + rr)*K)
                             + kpos0 + half*8;
            uint32_t dst = (uint32_t)__cvta_generic_to_shared(&sm[buf][pl][rr*LDK + half*8]);
            cpasync16(dst, src);
        }
        asm volatile("cp.async.commit_group;\n");
    };

    load_stage(0, 0);

    for (int s = 0; s < stages; s++) {
        if (s + 1 < stages) {
            load_stage((s + 1) & 1, s + 1);
            asm volatile("cp.async.wait_group 1;\n");
        } else {
            asm volatile("cp.async.wait_group 0;\n");
        }
        __syncthreads();
        uint32_t base = smb + (uint32_t)(s & 1)*BUF;
        uint32_t aA = base + offA;
        uint32_t aB = base + MAT + offB;

        uint32_t bh[4][2], ah[4][4];
        #pragma unroll
        for (int p = 0; p < 2; p++)
            ldsm_x4(bh[2*p][0], bh[2*p][1], bh[2*p+1][0], bh[2*p+1][1], aB + p*16*LDK*2);
        #pragma unroll
        for (int mi = 0; mi < 4; mi++)
            ldsm_x4(ah[mi][0], ah[mi][1], ah[mi][2], ah[mi][3], aA + mi*16*LDK*2);

        #pragma unroll
        for (int mi = 0; mi < 4; mi++)
            #pragma unroll
            for (int ni = 0; ni < 4; ni++) {
                float* d = acc[mi*4 + ni];
                mma16816_f32(d[0], d[1], d[2], d[3],
                             ah[mi][0], ah[mi][1], ah[mi][2], ah[mi][3], bh[ni][0], bh[ni][1]);
            }
        __syncthreads();
    }

    float* cbase = part + ((size_t)blockIdx.z << 20);
    #pragma unroll
    for (int mi = 0; mi < 4; mi++) {
        #pragma unroll
        for (int ni = 0; ni < 4; ni++) {
            int row = bm + wm + mi*16 + g;
            int col = bn + wn + ni*8 + 2*tig;
            float* d = acc[mi*4 + ni];
            *(float2*)&cbase[(size_t)row*1024 + col]     = make_float2(d[0], d[1]);
            *(float2*)&cbase[(size_t)(row+8)*1024 + col] = make_float2(d[2], d[3]);
        }
    }
}

// reduce fc1 partials -> relu -> fp16 h1
__global__ void reduce1_kernel(const float* __restrict__ part,
                               const float* __restrict__ bias,
                               u16* __restrict__ Hh) {
    size_t idx = (size_t)blockIdx.x * 256 + threadIdx.x;
    int n = (int)(idx & 1023);
    float s = bias[n];
    #pragma unroll
    for (int i = 0; i < 16; i++) s += part[((size_t)i << 20) + idx];
    s = fmaxf(s, 0.0f);
    __half h = __float2half_rn(s);
    Hh[idx] = *(u16*)&h;
}

// reduce fc2 partials -> relu -> f32 h2
__global__ void reduce2_kernel(const float* __restrict__ part,
                               const float* __restrict__ bias,
                               float* __restrict__ H) {
    size_t idx = (size_t)blockIdx.x * 256 + threadIdx.x;
    int n = (int)(idx & 1023);
    float s = bias[n];
    #pragma unroll
    for (int i = 0; i < 4; i++) s += part[((size_t)i << 20) + idx];
    H[idx] = fmaxf(s, 0.0f);
}

// ---------------- cls + bbox heads ----------------
__global__ void fc_small_kernel(const float* __restrict__ h,
                                const float* __restrict__ clsw, const float* __restrict__ clsb,
                                const float* __restrict__ bbw, const float* __restrict__ bbb,
                                float* __restrict__ logits, float* __restrict__ breg) {
    int t = blockIdx.x * 128 + threadIdx.x;
    if (t >= TOPN * 30) return;
    int r = t / 30, j = t % 30;
    const float* hp = h + (size_t)r*1024;
    if (j < 6) {
        float acc = clsb[j];
        for (int k = 0; k < 1024; k++) acc = fmaf(hp[k], clsw[k*6 + j], acc);
        logits[r*6 + j] = acc;
    } else {
        int q = j - 6;
        float acc = bbb[q];
        for (int k = 0; k < 1024; k++) acc = fmaf(hp[k], bbw[k*24 + q], acc);
        breg[r*24 + q] = acc;
    }
}

// ---------------- final ----------------
__global__ void final_kernel(const float* __restrict__ rois,
                             const float* __restrict__ logits,
                             const float* __restrict__ breg,
                             float* __restrict__ out) {
    int r = blockIdx.x * 128 + threadIdx.x;
    if (r >= TOPN) return;
    float l[6];
    float m = -INFINITY;
    #pragma unroll
    for (int i = 0; i < 6; i++) { l[i] = logits[r*6 + i]; m = fmaxf(m, l[i]); }
    float ssum = 0.0f;
    #pragma unroll
    for (int i = 0; i < 6; i++) { l[i] = expf(l[i] - m); ssum += l[i]; }
    float inv = 1.0f / ssum;

    float x1 = rois[r*4+0], y1 = rois[r*4+1], x2 = rois[r*4+2], y2 = rois[r*4+3];
    float W = x2 - x1, H = y2 - y1;
    float cx = x1 + 0.5f*W, cy = y1 + 0.5f*H;
    #pragma unroll
    for (int c = 1; c < 6; c++) {
        float dx = breg[r*24 + c*4+0] / 10.0f;
        float dy = breg[r*24 + c*4+1] / 10.0f;
        float dw = fminf(breg[r*24 + c*4+2] / 5.0f, BBOX_CLAMP);
        float dh = fminf(breg[r*24 + c*4+3] / 5.0f, BBOX_CLAMP);
        float pcx = dx*W + cx, pcy = dy*H + cy;
        float pw = expf(dw)*W, ph = expf(dh)*H;
        float bx1 = fminf(fmaxf(pcx - 0.5f*pw, 0.0f), 512.0f);
        float by1 = fminf(fmaxf(pcy - 0.5f*ph, 0.0f), 512.0f);
        float bx2 = fminf(fmaxf(pcx + 0.5f*pw, 0.0f), 512.0f);
        float by2 = fminf(fmaxf(pcy + 0.5f*ph, 0.0f), 512.0f);
        int o = r*25 + (c-1)*5;
        out[o+0] = bx1; out[o+1] = by1; out[o+2] = bx2; out[o+3] = by2;
        out[o+4] = l[c] * inv;
    }
}

// ---------------- launcher ----------------
extern "C" void kernel_launch(void* const* d_in, const int* in_sizes, int n_in,
                              void* d_out, int out_size) {
    const float* images     = (const float*)d_in[0];
    const float* c0_w       = (const float*)d_in[1];
    const float* c0_b       = (const float*)d_in[2];
    const float* c1_w       = (const float*)d_in[3];
    const float* c1_b       = (const float*)d_in[4];
    const float* c2_w       = (const float*)d_in[5];
    const float* c2_b       = (const float*)d_in[6];
    const float* c3_w       = (const float*)d_in[7];
    const float* c3_b       = (const float*)d_in[8];
    const float* rpn_conv_w = (const float*)d_in[9];
    const float* rpn_conv_b = (const float*)d_in[10];
    const float* rpn_cls_w  = (const float*)d_in[11];
    const float* rpn_cls_b  = (const float*)d_in[12];
    const float* rpn_bbox_w = (const float*)d_in[13];
    const float* rpn_bbox_b = (const float*)d_in[14];
    const float* fc1_w      = (const float*)d_in[15];
    const float* fc1_b      = (const float*)d_in[16];
    const float* fc2_w      = (const float*)d_in[17];
    const float* fc2_b      = (const float*)d_in[18];
    const float* cls_w      = (const float*)d_in[19];
    const float* cls_b      = (const float*)d_in[20];
    const float* bbox_w     = (const float*)d_in[21];
    const float* bbox_b     = (const float*)d_in[22];
    float* out = (float*)d_out;

    float *p_c0, *p_pool, *p_c1, *p_c2, *p_feat, *p_rpn, *p_obj, *p_bd;
    float *p_props, *p_scores, *p_rois, *p_part, *p_h2, *p_logits, *p_breg;
    int *p_topidx;
    u16 *p_Ah, *p_B1h, *p_B2h, *p_h1h;
    cudaGetSymbolAddress((void**)&p_c0, g_c0);
    cudaGetSymbolAddress((void**)&p_pool, g_pool);
    cudaGetSymbolAddress((void**)&p_c1, g_c1);
    cudaGetSymbolAddress((void**)&p_c2, g_c2);
    cudaGetSymbolAddress((void**)&p_feat, g_feat);
    cudaGetSymbolAddress((void**)&p_rpn, g_rpn);
    cudaGetSymbolAddress((void**)&p_obj, g_obj);
    cudaGetSymbolAddress((void**)&p_bd, g_bd);
    cudaGetSymbolAddress((void**)&p_props, g_props);
    cudaGetSymbolAddress((void**)&p_scores, g_scores);
    cudaGetSymbolAddress((void**)&p_topidx, g_topidx);
    cudaGetSymbolAddress((void**)&p_rois, g_rois);
    cudaGetSymbolAddress((void**)&p_Ah, g_Ah);
    cudaGetSymbolAddress((void**)&p_B1h, g_B1h);
    cudaGetSymbolAddress((void**)&p_B2h, g_B2h);
    cudaGetSymbolAddress((void**)&p_h1h, g_h1h);
    cudaGetSymbolAddress((void**)&p_part, g_part);
    cudaGetSymbolAddress((void**)&p_h2, g_h2);
    cudaGetSymbolAddress((void**)&p_logits, g_logits);
    cudaGetSymbolAddress((void**)&p_breg, g_breg);

    // weight transpose -> fp16
    tsplit_kernel<<<dim3(1024/32, 25088/32), dim3(32,8)>>>(fc1_w, p_B1h, 25088, 1024);
    tsplit_kernel<<<dim3(1024/32, 1024/32),  dim3(32,8)>>>(fc2_w, p_B2h, 1024, 1024);

    // backbone
    conv0v2_kernel<<<dim3(8,16,16), dim3(8,16)>>>(images, c0_w, c0_b, p_c0);
    maxpool_kernel<<<(64*128*128 + 255)/256, 256>>>(p_c0, p_pool);
    conv3x3v2_kernel<<<dim3(4,4,32), dim3(16,16),  4*64*9*4>>>(p_pool, c1_w, c1_b, p_c1, 64, 128, 64, 2, 64);
    conv3x3v2_kernel<<<dim3(2,2,64), dim3(16,16), 4*128*9*4>>>(p_c1, c2_w, c2_b, p_c2, 128, 64, 32, 2, 128);
    conv3x3v2_kernel<<<dim3(1,1,128), dim3(16,16), 4*128*9*4>>>(p_c2, c3_w, c3_b, p_feat, 256, 32, 16, 2, 128);

    // RPN
    conv3x3v2_kernel<<<dim3(1,1,128), dim3(16,16), 4*128*9*4>>>(p_feat, rpn_conv_w, rpn_conv_b, p_rpn, 512, 16, 16, 1, 128);
    conv1x1_kernel<<<9, 256>>>(p_rpn, rpn_cls_w, rpn_cls_b, p_obj, 512);
    conv1x1_kernel<<<36, 256>>>(p_rpn, rpn_bbox_w, rpn_bbox_b, p_bd, 512);

    // proposals
    rpn_decode_kernel<<<9, 256>>>(p_obj, p_bd, p_props, p_scores);
    topk_kernel<<<1, 1024>>>(p_scores, p_topidx);
    gather_rois_kernel<<<4, 256>>>(p_props, p_topidx, p_rois);

    // roi align -> fp16 A
    roi_align2_kernel<<<TOPN, 256>>>(p_feat, p_rois, p_Ah);
    padA_kernel<<<(24*25088 + 255)/256, 256>>>(p_Ah);

    // fc1: K=25088, z=16 -> stages 98
    gemm_fp16_kernel<<<dim3(8,8,16), 256>>>(p_Ah, p_B1h, p_part, 25088, 98);
    reduce1_kernel<<<(1024*1024)/256, 256>>>(p_part, fc1_b, p_h1h);

    // fc2: K=1024, z=4 -> stages 16
    gemm_fp16_kernel<<<dim3(8,8,4), 256>>>(p_h1h, p_B2h, p_part, 1024, 16);
    reduce2_kernel<<<(1024*1024)/256, 256>>>(p_part, fc2_b, p_h2);

    fc_small_kernel<<<(TOPN*30 + 127)/128, 128>>>(p_h2, cls_w, cls_b, bbox_w, bbox_b, p_logits, p_breg);
    final_kernel<<<(TOPN + 127)/128, 128>>>(p_rois, p_logits, p_breg, out);
}

// round 9
// speedup vs baseline: 1.5450x; 1.1249x over previous
#include <cuda_runtime.h>
#include <cuda_fp16.h>
#include <math.h>
#include <stdint.h>

#define TOPN 1000
#define BBOX_CLAMP 4.135166556742356f
typedef unsigned short u16;

// ---------------- scratch (device globals) ----------------
__device__ float g_c0[64*256*256];
__device__ float g_pool[64*128*128];
__device__ float g_c1[128*64*64];
__device__ float g_c2[256*32*32];
__device__ float g_feat[512*16*16];
__device__ float g_rpn[512*16*16];
__device__ float g_cpart[524288];    // conv channel-split partials (max 2 MB)
__device__ float g_obj[9*16*16];
__device__ float g_bd[36*16*16];
__device__ float g_props[2304*4];
__device__ float g_scores[2304];
__device__ int   g_topidx[TOPN];
__device__ float g_rois[TOPN*4];
__device__ u16 g_Ah[1024u*25088u];
__device__ u16 g_B1h[1024u*25088u];
__device__ u16 g_B2h[1024u*1024u];
__device__ u16 g_h1h[1024u*1024u];
__device__ float g_part[16u*1024u*1024u];
__device__ float g_h2[1024u*1024u];
__device__ float g_logits[TOPN*6];
__device__ float g_breg[TOPN*24];

// ---------------- conv0: smem-tiled 7x7 s2 ----------------
__global__ void conv0v2_kernel(const float* __restrict__ img,
                               const float* __restrict__ w,
                               const float* __restrict__ b,
                               float* __restrict__ out) {
    __shared__ float tile[3][37][72];
    __shared__ float ws[4][147];
    int tx = threadIdx.x, ty = threadIdx.y;
    int tid = ty*8 + tx;
    int oc0 = blockIdx.z * 4;
    int x0 = blockIdx.x * 32;
    int y0 = blockIdx.y * 16;
    int ixs = 2*x0 - 3, iys = 2*y0 - 3;
    const float mean[3] = {0.485f, 0.456f, 0.406f};
    const float istd[3] = {1.0f/0.229f, 1.0f/0.224f, 1.0f/0.225f};

    for (int i = tid; i < 3*37*72; i += 128) {
        int c = i / (37*72); int rem = i % (37*72);
        int iy = rem / 72, ix = rem % 72;
        int gy = iys + iy, gx = ixs + ix;
        float v = 0.0f;
        if (gy >= 0 && gy < 512 && gx >= 0 && gx < 512 && ix < 69)
            v = (img[(c*512 + gy)*512 + gx] - mean[c]) * istd[c];
        tile[c][iy][ix] = v;
    }
    for (int i = tid; i < 4*147; i += 128)
        ws[i/147][i%147] = w[(size_t)(oc0 + i/147)*147 + i%147];
    __syncthreads();

    float acc[4][4];
    #pragma unroll
    for (int oc = 0; oc < 4; oc++) {
        float bb = b[oc0+oc];
        #pragma unroll
        for (int xo = 0; xo < 4; xo++) acc[oc][xo] = bb;
    }
    for (int c = 0; c < 3; c++) {
        #pragma unroll
        for (int ky = 0; ky < 7; ky++) {
            const float* row = tile[c][2*ty + ky];
            float v[13];
            #pragma unroll
            for (int j = 0; j < 13; j++) v[j] = row[8*tx + j];
            #pragma unroll
            for (int kx = 0; kx < 7; kx++) {
                float w0 = ws[0][c*49 + ky*7 + kx];
                float w1 = ws[1][c*49 + ky*7 + kx];
                float w2 = ws[2][c*49 + ky*7 + kx];
                float w3 = ws[3][c*49 + ky*7 + kx];
                #pragma unroll
                for (int xo = 0; xo < 4; xo++) {
                    float vv = v[2*xo + kx];
                    acc[0][xo] = fmaf(vv, w0, acc[0][xo]);
                    acc[1][xo] = fmaf(vv, w1, acc[1][xo]);
                    acc[2][xo] = fmaf(vv, w2, acc[2][xo]);
                    acc[3][xo] = fmaf(vv, w3, acc[3][xo]);
                }
            }
        }
    }
    int y = y0 + ty;
    #pragma unroll
    for (int oc = 0; oc < 4; oc++)
        #pragma unroll
        for (int xo = 0; xo < 4; xo++)
            out[(size_t)(oc0+oc)*65536 + y*256 + x0 + tx*4 + xo] = fmaxf(acc[oc][xo], 0.0f);
}

// ---------------- maxpool 3x3 s2 p1 ----------------
__global__ void maxpool_kernel(const float* __restrict__ in, float* __restrict__ out) {
    int idx = blockIdx.x * 256 + threadIdx.x;
    if (idx >= 64*128*128) return;
    int x = idx & 127;
    int y = (idx >> 7) & 127;
    int c = idx >> 14;
    float m = -INFINITY;
    #pragma unroll
    for (int dy = 0; dy < 3; dy++) {
        int iy = 2*y - 1 + dy;
        if (iy < 0 || iy >= 256) continue;
        #pragma unroll
        for (int dx = 0; dx < 3; dx++) {
            int ix = 2*x - 1 + dx;
            if (ix < 0 || ix >= 256) continue;
            m = fmaxf(m, in[(c*256 + iy)*256 + ix]);
        }
    }
    out[idx] = m;
}

// ---------------- 3x3 conv v3: smem input tile, 16x16 spatial x 8 oc, channel-split ----------------
#define CCH 4
__global__ void __launch_bounds__(256)
conv3x3s_kernel(const float* __restrict__ in, const float* __restrict__ w,
                const float* __restrict__ bias,
                float* __restrict__ out, float* __restrict__ partial,
                int Cin, int Hin, int Hout, int stride, int Cout, int cs) {
    extern __shared__ float sm[];
    int nocg = Cout >> 3;
    int ocg = blockIdx.z % nocg, slice = blockIdx.z / nocg;
    int oc0 = ocg * 8;
    int tid = threadIdx.x;
    int tx = tid & 15, ty = tid >> 4;
    int x0 = blockIdx.x * 16, y0 = blockIdx.y * 16;
    int TH = stride*15 + 3;               // 33 (s2) or 18 (s1)
    int TWP = (stride == 2) ? 36 : 20;    // padded row width
    float* tile = sm;                     // [CCH][TH][TWP]
    float* ws = sm + CCH*TH*TWP;          // [8][CCH][9]
    int iys = y0*stride - 1, ixs = x0*stride - 1;
    int cps = Cin / cs;
    int cbeg = slice * cps;
    int tsz = TH * TWP;

    float acc[8];
    #pragma unroll
    for (int oc = 0; oc < 8; oc++) acc[oc] = 0.0f;

    for (int c0 = 0; c0 < cps; c0 += CCH) {
        __syncthreads();
        for (int i = tid; i < CCH*tsz; i += 256) {
            int c = i / tsz;
            int rem = i - c*tsz;
            int r = rem / TWP, col = rem - r*TWP;
            int gy = iys + r, gx = ixs + col;
            float v = 0.0f;
            if (col < TH && gy >= 0 && gy < Hin && gx >= 0 && gx < Hin)
                v = in[(size_t)(cbeg + c0 + c)*Hin*Hin + gy*Hin + gx];
            tile[i] = v;
        }
        for (int i = tid; i < 8*CCH*9; i += 256) {
            int oc = i / (CCH*9);
            int rem = i - oc*CCH*9;
            int c = rem / 9, k = rem - c*9;
            ws[i] = w[(size_t)(oc0 + oc)*Cin*9 + (size_t)(cbeg + c0 + c)*9 + k];
        }
        __syncthreads();
        #pragma unroll
        for (int cl = 0; cl < CCH; cl++) {
            const float* tb = tile + cl*tsz;
            float v[9];
            #pragma unroll
            for (int ky = 0; ky < 3; ky++)
                #pragma unroll
                for (int kx = 0; kx < 3; kx++)
                    v[ky*3+kx] = tb[(stride*ty + ky)*TWP + stride*tx + kx];
            const float* wp = ws + cl*9;
            #pragma unroll
            for (int oc = 0; oc < 8; oc++)
                #pragma unroll
                for (int k = 0; k < 9; k++)
                    acc[oc] = fmaf(v[k], wp[oc*CCH*9 + k], acc[oc]);
        }
    }

    size_t HW = (size_t)Hout*Hout;
    size_t pix = (size_t)(y0 + ty)*Hout + x0 + tx;
    if (cs == 1) {
        #pragma unroll
        for (int oc = 0; oc < 8; oc++)
            out[(size_t)(oc0+oc)*HW + pix] = fmaxf(acc[oc] + bias[oc0+oc], 0.0f);
    } else {
        #pragma unroll
        for (int oc = 0; oc < 8; oc++)
            partial[(size_t)slice*Cout*HW + (size_t)(oc0+oc)*HW + pix] = acc[oc];
    }
}

// reduce conv partials -> bias + relu
__global__ void creduce_kernel(const float* __restrict__ partial,
                               const float* __restrict__ bias,
                               float* __restrict__ out, int HW, int ns, int total) {
    int idx = blockIdx.x * 256 + threadIdx.x;
    if (idx >= total) return;
    int oc = idx / HW;
    float s = bias[oc];
    for (int i = 0; i < ns; i++) s += partial[(size_t)i*total + idx];
    out[idx] = fmaxf(s, 0.0f);
}

// ---------------- 1x1 conv over 16x16 plane ----------------
__global__ void conv1x1_kernel(const float* __restrict__ in,
                               const float* __restrict__ w,
                               const float* __restrict__ b,
                               float* __restrict__ out, int Cin) {
    int p = threadIdx.x;
    int o = blockIdx.x;
    float acc = b[o];
    for (int c = 0; c < Cin; c++)
        acc = fmaf(in[c*256 + p], w[o*Cin + c], acc);
    out[o*256 + p] = acc;
}

// ---------------- RPN decode ----------------
__global__ void rpn_decode_kernel(const float* __restrict__ obj,
                                  const float* __restrict__ bd,
                                  float* __restrict__ props,
                                  float* __restrict__ scores) {
    int i = blockIdx.x * 256 + threadIdx.x;
    if (i >= 2304) return;
    int a = i % 9;
    int cell = i / 9;
    int wq = cell % 16;
    int hq = cell / 16;
    int pix = hq*16 + wq;
    scores[i] = obj[a*256 + pix];

    const float ratios[3] = {0.5f, 1.0f, 2.0f};
    int r = a / 3, s = a % 3;
    float scale = 128.0f * (float)(1 << s);
    float hr = sqrtf(ratios[r]);
    float wr = 1.0f / hr;
    float hw = rintf(wr * scale * 0.5f);
    float hh = rintf(hr * scale * 0.5f);
    float sx = (float)(wq * 32), sy = (float)(hq * 32);
    float W = 2.0f*hw, H = 2.0f*hh;
    float cx = sx, cy = sy;

    float dx = bd[(a*4+0)*256 + pix];
    float dy = bd[(a*4+1)*256 + pix];
    float dw = fminf(bd[(a*4+2)*256 + pix], BBOX_CLAMP);
    float dh = fminf(bd[(a*4+3)*256 + pix], BBOX_CLAMP);
    float pcx = dx*W + cx, pcy = dy*H + cy;
    float pw = expf(dw)*W, ph = expf(dh)*H;
    props[i*4+0] = pcx - 0.5f*pw;
    props[i*4+1] = pcy - 0.5f*ph;
    props[i*4+2] = pcx + 0.5f*pw;
    props[i*4+3] = pcy + 0.5f*ph;
}

// ---------------- top-k bitonic ----------------
__device__ __forceinline__ bool tk_lt(float sa, int ia, float sb, int ib) {
    return (sa > sb) || (sa == sb && ia < ib);
}
__global__ void topk_kernel(const float* __restrict__ scores, int* __restrict__ topidx) {
    __shared__ float s[4096];
    __shared__ int   ind[4096];
    int tid = threadIdx.x;
    for (int i = tid; i < 4096; i += 1024) {
        s[i] = (i < 2304) ? scores[i] : -INFINITY;
        ind[i] = i;
    }
    __syncthreads();
    for (int k = 2; k <= 4096; k <<= 1) {
        for (int j = k >> 1; j > 0; j >>= 1) {
            for (int base = 0; base < 4096; base += 1024) {
                int i = base + tid;
                int ixj = i ^ j;
                if (ixj > i) {
                    bool up = ((i & k) == 0);
                    float si = s[i], sj = s[ixj];
                    int ii = ind[i], ij = ind[ixj];
                    bool swp = up ? tk_lt(sj, ij, si, ii) : tk_lt(si, ii, sj, ij);
                    if (swp) { s[i] = sj; s[ixj] = si; ind[i] = ij; ind[ixj] = ii; }
                }
            }
            __syncthreads();
        }
    }
    for (int i = tid; i < TOPN; i += 1024) topidx[i] = ind[i];
}

__global__ void gather_rois_kernel(const float* __restrict__ props,
                                   const int* __restrict__ topidx,
                                   float* __restrict__ rois) {
    int i = blockIdx.x * 256 + threadIdx.x;
    if (i >= TOPN) return;
    int idx = topidx[i];
    #pragma unroll
    for (int k = 0; k < 4; k++)
        rois[i*4+k] = fminf(fmaxf(props[idx*4+k], 0.0f), 512.0f);
}

// ---------------- ROI align -> fp16 A matrix ----------------
__global__ void roi_align2_kernel(const float* __restrict__ feat,
                                  const float* __restrict__ rois,
                                  u16* __restrict__ Ah) {
    __shared__ float ftile[16*256];
    __shared__ int   sry[7][4]; __shared__ float swy[7][4];
    __shared__ int   srx[7][4]; __shared__ float swx[7][4];
    int rr = blockIdx.x;
    int tid = threadIdx.x;
    if (tid < 28) {
        int i = tid % 14;
        bool isY = tid >= 14;
        float c1 = rois[rr*4 + (isY ? 1 : 0)];
        float c2 = rois[rr*4 + (isY ? 3 : 2)];
        float lo = c1 * (1.0f/32.0f);
        float hi = c2 * (1.0f/32.0f);
        float sz = fmaxf(hi - lo, 1.0f);
        float g = ((float)i + 0.5f) / 14.0f;
        float p = fminf(fmaxf(lo + g*sz, 0.0f), 15.0f);
        int p0 = (int)floorf(p);
        int p1 = min(p0 + 1, 15);
        float l = p - (float)p0;
        int pp = i >> 1, sl = (i & 1) * 2;
        float wh = 0.5f * (1.0f - l), wl = 0.5f * l;
        if (isY) { sry[pp][sl] = p0; sry[pp][sl+1] = p1; swy[pp][sl] = wh; swy[pp][sl+1] = wl; }
        else     { srx[pp][sl] = p0; srx[pp][sl+1] = p1; swx[pp][sl] = wh; swx[pp][sl+1] = wl; }
    }
    __syncthreads();
    for (int ci = 0; ci < 32; ci++) {
        const float4* src = (const float4*)(feat + (size_t)ci*16*256);
        float4* dst = (float4*)ftile;
        for (int i = tid; i < 1024; i += 256) dst[i] = src[i];
        __syncthreads();
        for (int t = tid; t < 784; t += 256) {
            int cl = t / 49, p = t % 49;
            int py = p / 7, px = p % 7;
            const float* f = ftile + cl*256;
            float acc = 0.0f;
            #pragma unroll
            for (int a = 0; a < 4; a++) {
                const float* frow = f + sry[py][a]*16;
                float s = 0.0f;
                #pragma unroll
                for (int bb = 0; bb < 4; bb++)
                    s = fmaf(swx[px][bb], frow[srx[px][bb]], s);
                acc = fmaf(swy[py][a], s, acc);
            }
            __half h = __float2half_rn(acc);
            Ah[(size_t)rr*25088 + (size_t)(ci*16 + cl)*49 + p] = *(u16*)&h;
        }
        __syncthreads();
    }
}

// zero pad rows [1000,1024)
__global__ void padA_kernel(u16* __restrict__ Ah) {
    size_t idx = (size_t)blockIdx.x * 256 + threadIdx.x;
    size_t total = 24u*25088u;
    if (idx >= total) return;
    Ah[(size_t)1000*25088 + idx] = 0;
}

// ---------------- transpose + fp16 weights: W[K][N] -> T[N][K] ----------------
__global__ void tsplit_kernel(const float* __restrict__ W,
                              u16* __restrict__ Th, int K, int N) {
    __shared__ float t[32][33];
    int n0 = blockIdx.x * 32, k0 = blockIdx.y * 32;
    int tx = threadIdx.x, ty = threadIdx.y;
    #pragma unroll
    for (int i = 0; i < 4; i++)
        t[ty + 8*i][tx] = W[(size_t)(k0 + ty + 8*i)*N + n0 + tx];
    __syncthreads();
    #pragma unroll
    for (int i = 0; i < 4; i++) {
        __half h = __float2half_rn(t[tx][ty + 8*i]);
        Th[(size_t)(n0 + ty + 8*i)*K + k0 + tx] = *(u16*)&h;
    }
}

// ---------------- single-pass fp16 tensor-core GEMM ----------------
__device__ __forceinline__ void mma16816_f32(float& d0, float& d1, float& d2, float& d3,
                                             uint32_t a0, uint32_t a1, uint32_t a2, uint32_t a3,
                                             uint32_t b0, uint32_t b1) {
    asm volatile("mma.sync.aligned.m16n8k16.row.col.f32.f16.f16.f32 "
                 "{%0,%1,%2,%3}, {%4,%5,%6,%7}, {%8,%9}, {%0,%1,%2,%3};\n"
                 : "+f"(d0), "+f"(d1), "+f"(d2), "+f"(d3)
                 : "r"(a0), "r"(a1), "r"(a2), "r"(a3), "r"(b0), "r"(b1));
}
__device__ __forceinline__ void cpasync16(uint32_t dst, const void* src) {
    asm volatile("cp.async.cg.shared.global [%0], [%1], 16;\n" :: "r"(dst), "l"(src));
}
__device__ __forceinline__ void ldsm_x4(uint32_t& r0, uint32_t& r1, uint32_t& r2, uint32_t& r3,
                                        uint32_t addr) {
    asm volatile("ldmatrix.sync.aligned.m8n8.x4.shared.b16 {%0,%1,%2,%3}, [%4];\n"
                 : "=r"(r0), "=r"(r1), "=r"(r2), "=r"(r3) : "r"(addr));
}

#define LDK 24

__global__ void __launch_bounds__(256)
gemm_fp16_kernel(const u16* __restrict__ A, const u16* __restrict__ B,
                 float* __restrict__ part, int K, int stages) {
    __shared__ __align__(16) u16 sm[2][2][128*LDK];
    int tid = threadIdx.x;
    int wid = tid >> 5, lane = tid & 31;
    int wm = (wid & 1) * 64;
    int wn = (wid >> 1) * 32;
    int g = lane >> 2, tig = lane & 3;
    int r8 = lane & 7, q = lane >> 3;
    int bm = blockIdx.y * 128, bn = blockIdx.x * 128;
    int kbase = blockIdx.z * stages * 16;

    float acc[16][4];
    #pragma unroll
    for (int i = 0; i < 16; i++)
        #pragma unroll
        for (int j = 0; j < 4; j++) acc[i][j] = 0.0f;

    uint32_t smb = (uint32_t)__cvta_generic_to_shared(&sm[0][0][0]);
    const uint32_t MAT = 128*LDK*2;
    const uint32_t BUF = 2*MAT;
    uint32_t offA = (uint32_t)(((wm + (q & 1)*8 + r8)*LDK + (q >> 1)*8) * 2);
    uint32_t offB = (uint32_t)(((wn + (q >> 1)*8 + r8)*LDK + (q & 1)*8) * 2);

    auto load_stage = [&](int buf, int s) {
        int kpos0 = kbase + s * 16;
        #pragma unroll
        for (int l = 0; l < 2; l++) {
            int idx = l * 256 + tid;
            int pl = idx >> 8;
            int rr = (idx & 255) >> 1;
            int half = idx & 1;
            const u16* src = (pl ? B + (size_t)(bn + rr)*K : A + (size_t)(bm + rr)*K)
                             + kpos0 + half*8;
            uint32_t dst = (uint32_t)__cvta_generic_to_shared(&sm[buf][pl][rr*LDK + half*8]);
            cpasync16(dst, src);
        }
        asm volatile("cp.async.commit_group;\n");
    };

    load_stage(0, 0);

    for (int s = 0; s < stages; s++) {
        if (s + 1 < stages) {
            load_stage((s + 1) & 1, s + 1);
            asm volatile("cp.async.wait_group 1;\n");
        } else {
            asm volatile("cp.async.wait_group 0;\n");
        }
        __syncthreads();
        uint32_t base = smb + (uint32_t)(s & 1)*BUF;
        uint32_t aA = base + offA;
        uint32_t aB = base + MAT + offB;

        uint32_t bh[4][2], ah[4][4];
        #pragma unroll
        for (int p = 0; p < 2; p++)
            ldsm_x4(bh[2*p][0], bh[2*p][1], bh[2*p+1][0], bh[2*p+1][1], aB + p*16*LDK*2);
        #pragma unroll
        for (int mi = 0; mi < 4; mi++)
            ldsm_x4(ah[mi][0], ah[mi][1], ah[mi][2], ah[mi][3], aA + mi*16*LDK*2);

        #pragma unroll
        for (int mi = 0; mi < 4; mi++)
            #pragma unroll
            for (int ni = 0; ni < 4; ni++) {
                float* d = acc[mi*4 + ni];
                mma16816_f32(d[0], d[1], d[2], d[3],
                             ah[mi][0], ah[mi][1], ah[mi][2], ah[mi][3], bh[ni][0], bh[ni][1]);
            }
        __syncthreads();
    }

    float* cbase = part + ((size_t)blockIdx.z << 20);
    #pragma unroll
    for (int mi = 0; mi < 4; mi++) {
        #pragma unroll
        for (int ni = 0; ni < 4; ni++) {
            int row = bm + wm + mi*16 + g;
            int col = bn + wn + ni*8 + 2*tig;
            float* d = acc[mi*4 + ni];
            *(float2*)&cbase[(size_t)row*1024 + col]     = make_float2(d[0], d[1]);
            *(float2*)&cbase[(size_t)(row+8)*1024 + col] = make_float2(d[2], d[3]);
        }
    }
}

// reduce fc1 partials -> relu -> fp16 h1
__global__ void reduce1_kernel(const float* __restrict__ part,
                               const float* __restrict__ bias,
                               u16* __restrict__ Hh) {
    size_t idx = (size_t)blockIdx.x * 256 + threadIdx.x;
    int n = (int)(idx & 1023);
    float s = bias[n];
    #pragma unroll
    for (int i = 0; i < 16; i++) s += part[((size_t)i << 20) + idx];
    s = fmaxf(s, 0.0f);
    __half h = __float2half_rn(s);
    Hh[idx] = *(u16*)&h;
}

// reduce fc2 partials -> relu -> f32 h2
__global__ void reduce2_kernel(const float* __restrict__ part,
                               const float* __restrict__ bias,
                               float* __restrict__ H) {
    size_t idx = (size_t)blockIdx.x * 256 + threadIdx.x;
    int n = (int)(idx & 1023);
    float s = bias[n];
    #pragma unroll
    for (int i = 0; i < 4; i++) s += part[((size_t)i << 20) + idx];
    H[idx] = fmaxf(s, 0.0f);
}

// ---------------- cls + bbox heads: block per roi ----------------
__global__ void __launch_bounds__(256)
fc_small2_kernel(const float* __restrict__ h,
                 const float* __restrict__ clsw, const float* __restrict__ clsb,
                 const float* __restrict__ bbw, const float* __restrict__ bbb,
                 float* __restrict__ logits, float* __restrict__ breg) {
    __shared__ float hs[1024];
    int r = blockIdx.x;
    int tid = threadIdx.x;
    const float* hp = h + (size_t)r*1024;
    for (int i = tid; i < 1024; i += 256) hs[i] = hp[i];
    __syncthreads();
    if (tid < 240) {
        int j = tid >> 3, part = tid & 7;
        float acc = 0.0f;
        if (j < 6) {
            for (int k = part; k < 1024; k += 8)
                acc = fmaf(hs[k], clsw[k*6 + j], acc);
        } else {
            int q = j - 6;
            for (int k = part; k < 1024; k += 8)
                acc = fmaf(hs[k], bbw[k*24 + q], acc);
        }
        #pragma unroll
        for (int off = 4; off; off >>= 1)
            acc += __shfl_down_sync(0xffffffff, acc, off);
        if (part == 0) {
            if (j < 6) logits[r*6 + j] = acc + clsb[j];
            else       breg[r*24 + (j-6)] = acc + bbb[j-6];
        }
    }
}

// ---------------- final ----------------
__global__ void final_kernel(const float* __restrict__ rois,
                             const float* __restrict__ logits,
                             const float* __restrict__ breg,
                             float* __restrict__ out) {
    int r = blockIdx.x * 128 + threadIdx.x;
    if (r >= TOPN) return;
    float l[6];
    float m = -INFINITY;
    #pragma unroll
    for (int i = 0; i < 6; i++) { l[i] = logits[r*6 + i]; m = fmaxf(m, l[i]); }
    float ssum = 0.0f;
    #pragma unroll
    for (int i = 0; i < 6; i++) { l[i] = expf(l[i] - m); ssum += l[i]; }
    float inv = 1.0f / ssum;

    float x1 = rois[r*4+0], y1 = rois[r*4+1], x2 = rois[r*4+2], y2 = rois[r*4+3];
    float W = x2 - x1, H = y2 - y1;
    float cx = x1 + 0.5f*W, cy = y1 + 0.5f*H;
    #pragma unroll
    for (int c = 1; c < 6; c++) {
        float dx = breg[r*24 + c*4+0] / 10.0f;
        float dy = breg[r*24 + c*4+1] / 10.0f;
        float dw = fminf(breg[r*24 + c*4+2] / 5.0f, BBOX_CLAMP);
        float dh = fminf(breg[r*24 + c*4+3] / 5.0f, BBOX_CLAMP);
        float pcx = dx*W + cx, pcy = dy*H + cy;
        float pw = expf(dw)*W, ph = expf(dh)*H;
        float bx1 = fminf(fmaxf(pcx - 0.5f*pw, 0.0f), 512.0f);
        float by1 = fminf(fmaxf(pcy - 0.5f*ph, 0.0f), 512.0f);
        float bx2 = fminf(fmaxf(pcx + 0.5f*pw, 0.0f), 512.0f);
        float by2 = fminf(fmaxf(pcy + 0.5f*ph, 0.0f), 512.0f);
        int o = r*25 + (c-1)*5;
        out[o+0] = bx1; out[o+1] = by1; out[o+2] = bx2; out[o+3] = by2;
        out[o+4] = l[c] * inv;
    }
}

// ---------------- launcher ----------------
extern "C" void kernel_launch(void* const* d_in, const int* in_sizes, int n_in,
                              void* d_out, int out_size) {
    const float* images     = (const float*)d_in[0];
    const float* c0_w       = (const float*)d_in[1];
    const float* c0_b       = (const float*)d_in[2];
    const float* c1_w       = (const float*)d_in[3];
    const float* c1_b       = (const float*)d_in[4];
    const float* c2_w       = (const float*)d_in[5];
    const float* c2_b       = (const float*)d_in[6];
    const float* c3_w       = (const float*)d_in[7];
    const float* c3_b       = (const float*)d_in[8];
    const float* rpn_conv_w = (const float*)d_in[9];
    const float* rpn_conv_b = (const float*)d_in[10];
    const float* rpn_cls_w  = (const float*)d_in[11];
    const float* rpn_cls_b  = (const float*)d_in[12];
    const float* rpn_bbox_w = (const float*)d_in[13];
    const float* rpn_bbox_b = (const float*)d_in[14];
    const float* fc1_w      = (const float*)d_in[15];
    const float* fc1_b      = (const float*)d_in[16];
    const float* fc2_w      = (const float*)d_in[17];
    const float* fc2_b      = (const float*)d_in[18];
    const float* cls_w      = (const float*)d_in[19];
    const float* cls_b      = (const float*)d_in[20];
    const float* bbox_w     = (const float*)d_in[21];
    const float* bbox_b     = (const float*)d_in[22];
    float* out = (float*)d_out;

    float *p_c0, *p_pool, *p_c1, *p_c2, *p_feat, *p_rpn, *p_cpart, *p_obj, *p_bd;
    float *p_props, *p_scores, *p_rois, *p_part, *p_h2, *p_logits, *p_breg;
    int *p_topidx;
    u16 *p_Ah, *p_B1h, *p_B2h, *p_h1h;
    cudaGetSymbolAddress((void**)&p_c0, g_c0);
    cudaGetSymbolAddress((void**)&p_pool, g_pool);
    cudaGetSymbolAddress((void**)&p_c1, g_c1);
    cudaGetSymbolAddress((void**)&p_c2, g_c2);
    cudaGetSymbolAddress((void**)&p_feat, g_feat);
    cudaGetSymbolAddress((void**)&p_rpn, g_rpn);
    cudaGetSymbolAddress((void**)&p_cpart, g_cpart);
    cudaGetSymbolAddress((void**)&p_obj, g_obj);
    cudaGetSymbolAddress((void**)&p_bd, g_bd);
    cudaGetSymbolAddress((void**)&p_props, g_props);
    cudaGetSymbolAddress((void**)&p_scores, g_scores);
    cudaGetSymbolAddress((void**)&p_topidx, g_topidx);
    cudaGetSymbolAddress((void**)&p_rois, g_rois);
    cudaGetSymbolAddress((void**)&p_Ah, g_Ah);
    cudaGetSymbolAddress((void**)&p_B1h, g_B1h);
    cudaGetSymbolAddress((void**)&p_B2h, g_B2h);
    cudaGetSymbolAddress((void**)&p_h1h, g_h1h);
    cudaGetSymbolAddress((void**)&p_part, g_part);
    cudaGetSymbolAddress((void**)&p_h2, g_h2);
    cudaGetSymbolAddress((void**)&p_logits, g_logits);
    cudaGetSymbolAddress((void**)&p_breg, g_breg);

    const int SM_S2 = (CCH*33*36 + 8*CCH*9) * 4;   // stride-2 smem
    const int SM_S1 = (CCH*18*20 + 8*CCH*9) * 4;   // stride-1 smem

    // backbone (ordered so launch #4 = c2 conv for ncu capture)
    conv0v2_kernel<<<dim3(8,16,16), dim3(8,16)>>>(images, c0_w, c0_b, p_c0);
    maxpool_kernel<<<(64*128*128 + 255)/256, 256>>>(p_c0, p_pool);
    // c1: 64->128, 128->64, s2, CS=1 (direct write)
    conv3x3s_kernel<<<dim3(4,4,16), 256, SM_S2>>>(p_pool, c1_w, c1_b, p_c1, p_cpart,
                                                  64, 128, 64, 2, 128, 1);
    // c2: 128->256, 64->32, s2, CS=2
    conv3x3s_kernel<<<dim3(2,2,64), 256, SM_S2>>>(p_c1, c2_w, c2_b, p_c2, p_cpart,
                                                  128, 64, 32, 2, 256, 2);
    creduce_kernel<<<(256*1024+255)/256, 256>>>(p_cpart, c2_b, p_c2, 1024, 2, 256*1024);
    // c3: 256->512, 32->16, s2, CS=4
    conv3x3s_kernel<<<dim3(1,1,256), 256, SM_S2>>>(p_c2, c3_w, c3_b, p_feat, p_cpart,
                                                   256, 32, 16, 2, 512, 4);
    creduce_kernel<<<(512*256+255)/256, 256>>>(p_cpart, c3_b, p_feat, 256, 4, 512*256);
    // rpn: 512->512, 16->16, s1, CS=4
    conv3x3s_kernel<<<dim3(1,1,256), 256, SM_S1>>>(p_feat, rpn_conv_w, rpn_conv_b, p_rpn, p_cpart,
                                                   512, 16, 16, 1, 512, 4);
    creduce_kernel<<<(512*256+255)/256, 256>>>(p_cpart, rpn_conv_b, p_rpn, 256, 4, 512*256);

    conv1x1_kernel<<<9, 256>>>(p_rpn, rpn_cls_w, rpn_cls_b, p_obj, 512);
    conv1x1_kernel<<<36, 256>>>(p_rpn, rpn_bbox_w, rpn_bbox_b, p_bd, 512);

    // proposals
    rpn_decode_kernel<<<9, 256>>>(p_obj, p_bd, p_props, p_scores);
    topk_kernel<<<1, 1024>>>(p_scores, p_topidx);
    gather_rois_kernel<<<4, 256>>>(p_props, p_topidx, p_rois);

    // roi align -> fp16 A
    roi_align2_kernel<<<TOPN, 256>>>(p_feat, p_rois, p_Ah);
    padA_kernel<<<(24*25088 + 255)/256, 256>>>(p_Ah);

    // weight transpose -> fp16 (moved late; no dependency on backbone)
    tsplit_kernel<<<dim3(1024/32, 25088/32), dim3(32,8)>>>(fc1_w, p_B1h, 25088, 1024);
    tsplit_kernel<<<dim3(1024/32, 1024/32),  dim3(32,8)>>>(fc2_w, p_B2h, 1024, 1024);

    // fc1: K=25088, z=16 -> stages 98
    gemm_fp16_kernel<<<dim3(8,8,16), 256>>>(p_Ah, p_B1h, p_part, 25088, 98);
    reduce1_kernel<<<(1024*1024)/256, 256>>>(p_part, fc1_b, p_h1h);

    // fc2: K=1024, z=4 -> stages 16
    gemm_fp16_kernel<<<dim3(8,8,4), 256>>>(p_h1h, p_B2h, p_part, 1024, 16);
    reduce2_kernel<<<(1024*1024)/256, 256>>>(p_part, fc2_b, p_h2);

    fc_small2_kernel<<<TOPN, 256>>>(p_h2, cls_w, cls_b, bbox_w, bbox_b, p_logits, p_breg);
    final_kernel<<<(TOPN + 127)/128, 128>>>(p_rois, p_logits, p_breg, out);
}

// round 10
// speedup vs baseline: 1.8018x; 1.1662x over previous
#include <cuda_runtime.h>
#include <cuda_fp16.h>
#include <math.h>
#include <stdint.h>

#define TOPN 1000
#define BBOX_CLAMP 4.135166556742356f
typedef unsigned short u16;

// ---------------- scratch (device globals) ----------------
__device__ float g_c0[64*256*256];
__device__ float g_pool[64*128*128];
__device__ float g_c1[128*64*64];
__device__ float g_c2[256*32*32];
__device__ float g_feat[512*16*16];
__device__ float g_rpn[512*16*16];
__device__ float g_cpart[1048576];   // conv channel-split partials (4 MB)
__device__ float g_obj[9*16*16];
__device__ float g_bd[36*16*16];
__device__ float g_props[2304*4];
__device__ float g_scores[2304];
__device__ int   g_topidx[TOPN];
__device__ float g_rois[TOPN*4];
__device__ u16 g_Ah[1024u*25088u];
__device__ u16 g_B1h[1024u*25088u];
__device__ u16 g_B2h[1024u*1024u];
__device__ u16 g_h1h[1024u*1024u];
__device__ float g_part[16u*1024u*1024u];
__device__ float g_h2[1024u*1024u];
__device__ float g_logits[TOPN*6];
__device__ float g_breg[TOPN*24];

// ---------------- conv0: smem-tiled 7x7 s2 ----------------
__global__ void conv0v2_kernel(const float* __restrict__ img,
                               const float* __restrict__ w,
                               const float* __restrict__ b,
                               float* __restrict__ out) {
    __shared__ float tile[3][37][72];
    __shared__ float ws[4][147];
    int tx = threadIdx.x, ty = threadIdx.y;
    int tid = ty*8 + tx;
    int oc0 = blockIdx.z * 4;
    int x0 = blockIdx.x * 32;
    int y0 = blockIdx.y * 16;
    int ixs = 2*x0 - 3, iys = 2*y0 - 3;
    const float mean[3] = {0.485f, 0.456f, 0.406f};
    const float istd[3] = {1.0f/0.229f, 1.0f/0.224f, 1.0f/0.225f};

    for (int i = tid; i < 3*37*72; i += 128) {
        int c = i / (37*72); int rem = i % (37*72);
        int iy = rem / 72, ix = rem % 72;
        int gy = iys + iy, gx = ixs + ix;
        float v = 0.0f;
        if (gy >= 0 && gy < 512 && gx >= 0 && gx < 512 && ix < 69)
            v = (img[(c*512 + gy)*512 + gx] - mean[c]) * istd[c];
        tile[c][iy][ix] = v;
    }
    for (int i = tid; i < 4*147; i += 128)
        ws[i/147][i%147] = w[(size_t)(oc0 + i/147)*147 + i%147];
    __syncthreads();

    float acc[4][4];
    #pragma unroll
    for (int oc = 0; oc < 4; oc++) {
        float bb = b[oc0+oc];
        #pragma unroll
        for (int xo = 0; xo < 4; xo++) acc[oc][xo] = bb;
    }
    for (int c = 0; c < 3; c++) {
        #pragma unroll
        for (int ky = 0; ky < 7; ky++) {
            const float* row = tile[c][2*ty + ky];
            float v[13];
            #pragma unroll
            for (int j = 0; j < 13; j++) v[j] = row[8*tx + j];
            #pragma unroll
            for (int kx = 0; kx < 7; kx++) {
                float w0 = ws[0][c*49 + ky*7 + kx];
                float w1 = ws[1][c*49 + ky*7 + kx];
                float w2 = ws[2][c*49 + ky*7 + kx];
                float w3 = ws[3][c*49 + ky*7 + kx];
                #pragma unroll
                for (int xo = 0; xo < 4; xo++) {
                    float vv = v[2*xo + kx];
                    acc[0][xo] = fmaf(vv, w0, acc[0][xo]);
                    acc[1][xo] = fmaf(vv, w1, acc[1][xo]);
                    acc[2][xo] = fmaf(vv, w2, acc[2][xo]);
                    acc[3][xo] = fmaf(vv, w3, acc[3][xo]);
                }
            }
        }
    }
    int y = y0 + ty;
    #pragma unroll
    for (int oc = 0; oc < 4; oc++)
        #pragma unroll
        for (int xo = 0; xo < 4; xo++)
            out[(size_t)(oc0+oc)*65536 + y*256 + x0 + tx*4 + xo] = fmaxf(acc[oc][xo], 0.0f);
}

// ---------------- maxpool 3x3 s2 p1 ----------------
__global__ void maxpool_kernel(const float* __restrict__ in, float* __restrict__ out) {
    int idx = blockIdx.x * 256 + threadIdx.x;
    if (idx >= 64*128*128) return;
    int x = idx & 127;
    int y = (idx >> 7) & 127;
    int c = idx >> 14;
    float m = -INFINITY;
    #pragma unroll
    for (int dy = 0; dy < 3; dy++) {
        int iy = 2*y - 1 + dy;
        if (iy < 0 || iy >= 256) continue;
        #pragma unroll
        for (int dx = 0; dx < 3; dx++) {
            int ix = 2*x - 1 + dx;
            if (ix < 0 || ix >= 256) continue;
            m = fmaxf(m, in[(c*256 + iy)*256 + ix]);
        }
    }
    out[idx] = m;
}

// ---------------- 3x3 conv v4: templated stride, constexpr tile geometry ----------------
#define CCH 4
template<int STRIDE>
__global__ void __launch_bounds__(256)
conv3x3t_kernel(const float* __restrict__ in, const float* __restrict__ w,
                const float* __restrict__ bias,
                float* __restrict__ out, float* __restrict__ partial,
                int Cin, int Hin, int Hout, int Cout, int cs) {
    constexpr int TH  = STRIDE*15 + 3;
    constexpr int TWP = (STRIDE == 2) ? 36 : 20;
    constexpr int TSZ = TH * TWP;
    __shared__ float tile[CCH*TSZ];
    __shared__ float ws[8*CCH*9];
    int nocg = Cout >> 3;
    int ocg = blockIdx.z % nocg, slice = blockIdx.z / nocg;
    int oc0 = ocg * 8;
    int tid = threadIdx.x;
    int tx = tid & 15, ty = tid >> 4;
    int x0 = blockIdx.x * 16, y0 = blockIdx.y * 16;
    int iys = y0*STRIDE - 1, ixs = x0*STRIDE - 1;
    int cps = Cin / cs;
    int cbeg = slice * cps;

    float acc[8];
    #pragma unroll
    for (int oc = 0; oc < 8; oc++) acc[oc] = 0.0f;

    for (int c0 = 0; c0 < cps; c0 += CCH) {
        __syncthreads();
        #pragma unroll 4
        for (int i = tid; i < CCH*TSZ; i += 256) {
            int c = i / TSZ;
            int rem = i - c*TSZ;
            int r = rem / TWP, col = rem - r*TWP;
            int gy = iys + r, gx = ixs + col;
            float v = 0.0f;
            if (col < TH && gy >= 0 && gy < Hin && gx >= 0 && gx < Hin)
                v = in[(size_t)(cbeg + c0 + c)*Hin*Hin + gy*Hin + gx];
            tile[i] = v;
        }
        for (int i = tid; i < 8*CCH*9; i += 256) {
            int oc = i / (CCH*9);
            int rem = i - oc*CCH*9;
            int c = rem / 9, k = rem - c*9;
            ws[i] = w[(size_t)(oc0 + oc)*Cin*9 + (size_t)(cbeg + c0 + c)*9 + k];
        }
        __syncthreads();
        #pragma unroll
        for (int cl = 0; cl < CCH; cl++) {
            const float* tb = tile + cl*TSZ;
            float v[9];
            #pragma unroll
            for (int ky = 0; ky < 3; ky++)
                #pragma unroll
                for (int kx = 0; kx < 3; kx++)
                    v[ky*3+kx] = tb[(STRIDE*ty + ky)*TWP + STRIDE*tx + kx];
            const float* wp = ws + cl*9;
            #pragma unroll
            for (int oc = 0; oc < 8; oc++)
                #pragma unroll
                for (int k = 0; k < 9; k++)
                    acc[oc] = fmaf(v[k], wp[oc*CCH*9 + k], acc[oc]);
        }
    }

    size_t HW = (size_t)Hout*Hout;
    size_t pix = (size_t)(y0 + ty)*Hout + x0 + tx;
    if (cs == 1) {
        #pragma unroll
        for (int oc = 0; oc < 8; oc++)
            out[(size_t)(oc0+oc)*HW + pix] = fmaxf(acc[oc] + bias[oc0+oc], 0.0f);
    } else {
        #pragma unroll
        for (int oc = 0; oc < 8; oc++)
            partial[(size_t)slice*Cout*HW + (size_t)(oc0+oc)*HW + pix] = acc[oc];
    }
}

// reduce conv partials -> bias + relu
__global__ void creduce_kernel(const float* __restrict__ partial,
                               const float* __restrict__ bias,
                               float* __restrict__ out, int HW, int ns, int total) {
    int idx = blockIdx.x * 256 + threadIdx.x;
    if (idx >= total) return;
    int oc = idx / HW;
    float s = bias[oc];
    for (int i = 0; i < ns; i++) s += partial[(size_t)i*total + idx];
    out[idx] = fmaxf(s, 0.0f);
}

// ---------------- 1x1 conv over 16x16 plane ----------------
__global__ void conv1x1_kernel(const float* __restrict__ in,
                               const float* __restrict__ w,
                               const float* __restrict__ b,
                               float* __restrict__ out, int Cin) {
    int p = threadIdx.x;
    int o = blockIdx.x;
    float acc = b[o];
    for (int c = 0; c < Cin; c++)
        acc = fmaf(in[c*256 + p], w[o*Cin + c], acc);
    out[o*256 + p] = acc;
}

// ---------------- RPN decode ----------------
__global__ void rpn_decode_kernel(const float* __restrict__ obj,
                                  const float* __restrict__ bd,
                                  float* __restrict__ props,
                                  float* __restrict__ scores) {
    int i = blockIdx.x * 256 + threadIdx.x;
    if (i >= 2304) return;
    int a = i % 9;
    int cell = i / 9;
    int wq = cell % 16;
    int hq = cell / 16;
    int pix = hq*16 + wq;
    scores[i] = obj[a*256 + pix];

    const float ratios[3] = {0.5f, 1.0f, 2.0f};
    int r = a / 3, s = a % 3;
    float scale = 128.0f * (float)(1 << s);
    float hr = sqrtf(ratios[r]);
    float wr = 1.0f / hr;
    float hw = rintf(wr * scale * 0.5f);
    float hh = rintf(hr * scale * 0.5f);
    float sx = (float)(wq * 32), sy = (float)(hq * 32);
    float W = 2.0f*hw, H = 2.0f*hh;
    float cx = sx, cy = sy;

    float dx = bd[(a*4+0)*256 + pix];
    float dy = bd[(a*4+1)*256 + pix];
    float dw = fminf(bd[(a*4+2)*256 + pix], BBOX_CLAMP);
    float dh = fminf(bd[(a*4+3)*256 + pix], BBOX_CLAMP);
    float pcx = dx*W + cx, pcy = dy*H + cy;
    float pw = expf(dw)*W, ph = expf(dh)*H;
    props[i*4+0] = pcx - 0.5f*pw;
    props[i*4+1] = pcy - 0.5f*ph;
    props[i*4+2] = pcx + 0.5f*pw;
    props[i*4+3] = pcy + 0.5f*ph;
}

// ---------------- top-k bitonic ----------------
__device__ __forceinline__ bool tk_lt(float sa, int ia, float sb, int ib) {
    return (sa > sb) || (sa == sb && ia < ib);
}
__global__ void topk_kernel(const float* __restrict__ scores, int* __restrict__ topidx) {
    __shared__ float s[4096];
    __shared__ int   ind[4096];
    int tid = threadIdx.x;
    for (int i = tid; i < 4096; i += 1024) {
        s[i] = (i < 2304) ? scores[i] : -INFINITY;
        ind[i] = i;
    }
    __syncthreads();
    for (int k = 2; k <= 4096; k <<= 1) {
        for (int j = k >> 1; j > 0; j >>= 1) {
            for (int base = 0; base < 4096; base += 1024) {
                int i = base + tid;
                int ixj = i ^ j;
                if (ixj > i) {
                    bool up = ((i & k) == 0);
                    float si = s[i], sj = s[ixj];
                    int ii = ind[i], ij = ind[ixj];
                    bool swp = up ? tk_lt(sj, ij, si, ii) : tk_lt(si, ii, sj, ij);
                    if (swp) { s[i] = sj; s[ixj] = si; ind[i] = ij; ind[ixj] = ii; }
                }
            }
            __syncthreads();
        }
    }
    for (int i = tid; i < TOPN; i += 1024) topidx[i] = ind[i];
}

__global__ void gather_rois_kernel(const float* __restrict__ props,
                                   const int* __restrict__ topidx,
                                   float* __restrict__ rois) {
    int i = blockIdx.x * 256 + threadIdx.x;
    if (i >= TOPN) return;
    int idx = topidx[i];
    #pragma unroll
    for (int k = 0; k < 4; k++)
        rois[i*4+k] = fminf(fmaxf(props[idx*4+k], 0.0f), 512.0f);
}

// ---------------- ROI align -> fp16 A matrix ----------------
__global__ void roi_align2_kernel(const float* __restrict__ feat,
                                  const float* __restrict__ rois,
                                  u16* __restrict__ Ah) {
    __shared__ float ftile[16*256];
    __shared__ int   sry[7][4]; __shared__ float swy[7][4];
    __shared__ int   srx[7][4]; __shared__ float swx[7][4];
    int rr = blockIdx.x;
    int tid = threadIdx.x;
    if (tid < 28) {
        int i = tid % 14;
        bool isY = tid >= 14;
        float c1 = rois[rr*4 + (isY ? 1 : 0)];
        float c2 = rois[rr*4 + (isY ? 3 : 2)];
        float lo = c1 * (1.0f/32.0f);
        float hi = c2 * (1.0f/32.0f);
        float sz = fmaxf(hi - lo, 1.0f);
        float g = ((float)i + 0.5f) / 14.0f;
        float p = fminf(fmaxf(lo + g*sz, 0.0f), 15.0f);
        int p0 = (int)floorf(p);
        int p1 = min(p0 + 1, 15);
        float l = p - (float)p0;
        int pp = i >> 1, sl = (i & 1) * 2;
        float wh = 0.5f * (1.0f - l), wl = 0.5f * l;
        if (isY) { sry[pp][sl] = p0; sry[pp][sl+1] = p1; swy[pp][sl] = wh; swy[pp][sl+1] = wl; }
        else     { srx[pp][sl] = p0; srx[pp][sl+1] = p1; swx[pp][sl] = wh; swx[pp][sl+1] = wl; }
    }
    __syncthreads();
    for (int ci = 0; ci < 32; ci++) {
        const float4* src = (const float4*)(feat + (size_t)ci*16*256);
        float4* dst = (float4*)ftile;
        for (int i = tid; i < 1024; i += 256) dst[i] = src[i];
        __syncthreads();
        for (int t = tid; t < 784; t += 256) {
            int cl = t / 49, p = t % 49;
            int py = p / 7, px = p % 7;
            const float* f = ftile + cl*256;
            float acc = 0.0f;
            #pragma unroll
            for (int a = 0; a < 4; a++) {
                const float* frow = f + sry[py][a]*16;
                float s = 0.0f;
                #pragma unroll
                for (int bb = 0; bb < 4; bb++)
                    s = fmaf(swx[px][bb], frow[srx[px][bb]], s);
                acc = fmaf(swy[py][a], s, acc);
            }
            __half h = __float2half_rn(acc);
            Ah[(size_t)rr*25088 + (size_t)(ci*16 + cl)*49 + p] = *(u16*)&h;
        }
        __syncthreads();
    }
}

// zero pad rows [1000,1024)
__global__ void padA_kernel(u16* __restrict__ Ah) {
    size_t idx = (size_t)blockIdx.x * 256 + threadIdx.x;
    size_t total = 24u*25088u;
    if (idx >= total) return;
    Ah[(size_t)1000*25088 + idx] = 0;
}

// ---------------- transpose + fp16 weights ----------------
__global__ void tsplit_kernel(const float* __restrict__ W,
                              u16* __restrict__ Th, int K, int N) {
    __shared__ float t[32][33];
    int n0 = blockIdx.x * 32, k0 = blockIdx.y * 32;
    int tx = threadIdx.x, ty = threadIdx.y;
    #pragma unroll
    for (int i = 0; i < 4; i++)
        t[ty + 8*i][tx] = W[(size_t)(k0 + ty + 8*i)*N + n0 + tx];
    __syncthreads();
    #pragma unroll
    for (int i = 0; i < 4; i++) {
        __half h = __float2half_rn(t[tx][ty + 8*i]);
        Th[(size_t)(n0 + ty + 8*i)*K + k0 + tx] = *(u16*)&h;
    }
}

// ---------------- single-pass fp16 tensor-core GEMM ----------------
__device__ __forceinline__ void mma16816_f32(float& d0, float& d1, float& d2, float& d3,
                                             uint32_t a0, uint32_t a1, uint32_t a2, uint32_t a3,
                                             uint32_t b0, uint32_t b1) {
    asm volatile("mma.sync.aligned.m16n8k16.row.col.f32.f16.f16.f32 "
                 "{%0,%1,%2,%3}, {%4,%5,%6,%7}, {%8,%9}, {%0,%1,%2,%3};\n"
                 : "+f"(d0), "+f"(d1), "+f"(d2), "+f"(d3)
                 : "r"(a0), "r"(a1), "r"(a2), "r"(a3), "r"(b0), "r"(b1));
}
__device__ __forceinline__ void cpasync16(uint32_t dst, const void* src) {
    asm volatile("cp.async.cg.shared.global [%0], [%1], 16;\n" :: "r"(dst), "l"(src));
}
__device__ __forceinline__ void ldsm_x4(uint32_t& r0, uint32_t& r1, uint32_t& r2, uint32_t& r3,
                                        uint32_t addr) {
    asm volatile("ldmatrix.sync.aligned.m8n8.x4.shared.b16 {%0,%1,%2,%3}, [%4];\n"
                 : "=r"(r0), "=r"(r1), "=r"(r2), "=r"(r3) : "r"(addr));
}

#define LDK 24

__global__ void __launch_bounds__(256)
gemm_fp16_kernel(const u16* __restrict__ A, const u16* __restrict__ B,
                 float* __restrict__ part, int K, int stages) {
    __shared__ __align__(16) u16 sm[2][2][128*LDK];
    int tid = threadIdx.x;
    int wid = tid >> 5, lane = tid & 31;
    int wm = (wid & 1) * 64;
    int wn = (wid >> 1) * 32;
    int g = lane >> 2, tig = lane & 3;
    int r8 = lane & 7, q = lane >> 3;
    int bm = blockIdx.y * 128, bn = blockIdx.x * 128;
    int kbase = blockIdx.z * stages * 16;

    float acc[16][4];
    #pragma unroll
    for (int i = 0; i < 16; i++)
        #pragma unroll
        for (int j = 0; j < 4; j++) acc[i][j] = 0.0f;

    uint32_t smb = (uint32_t)__cvta_generic_to_shared(&sm[0][0][0]);
    const uint32_t MAT = 128*LDK*2;
    const uint32_t BUF = 2*MAT;
    uint32_t offA = (uint32_t)(((wm + (q & 1)*8 + r8)*LDK + (q >> 1)*8) * 2);
    uint32_t offB = (uint32_t)(((wn + (q >> 1)*8 + r8)*LDK + (q & 1)*8) * 2);

    auto load_stage = [&](int buf, int s) {
        int kpos0 = kbase + s * 16;
        #pragma unroll
        for (int l = 0; l < 2; l++) {
            int idx = l * 256 + tid;
            int pl = idx >> 8;
            int rr = (idx & 255) >> 1;
            int half = idx & 1;
            const u16* src = (pl ? B + (size_t)(bn + rr)*K : A + (size_t)(bm + rr)*K)
                             + kpos0 + half*8;
            uint32_t dst = (uint32_t)__cvta_generic_to_shared(&sm[buf][pl][rr*LDK + half*8]);
            cpasync16(dst, src);
        }
        asm volatile("cp.async.commit_group;\n");
    };

    load_stage(0, 0);

    for (int s = 0; s < stages; s++) {
        if (s + 1 < stages) {
            load_stage((s + 1) & 1, s + 1);
            asm volatile("cp.async.wait_group 1;\n");
        } else {
            asm volatile("cp.async.wait_group 0;\n");
        }
        __syncthreads();
        uint32_t base = smb + (uint32_t)(s & 1)*BUF;
        uint32_t aA = base + offA;
        uint32_t aB = base + MAT + offB;

        uint32_t bh[4][2], ah[4][4];
        #pragma unroll
        for (int p = 0; p < 2; p++)
            ldsm_x4(bh[2*p][0], bh[2*p][1], bh[2*p+1][0], bh[2*p+1][1], aB + p*16*LDK*2);
        #pragma unroll
        for (int mi = 0; mi < 4; mi++)
            ldsm_x4(ah[mi][0], ah[mi][1], ah[mi][2], ah[mi][3], aA + mi*16*LDK*2);

        #pragma unroll
        for (int mi = 0; mi < 4; mi++)
            #pragma unroll
            for (int ni = 0; ni < 4; ni++) {
                float* d = acc[mi*4 + ni];
                mma16816_f32(d[0], d[1], d[2], d[3],
                             ah[mi][0], ah[mi][1], ah[mi][2], ah[mi][3], bh[ni][0], bh[ni][1]);
            }
        __syncthreads();
    }

    float* cbase = part + ((size_t)blockIdx.z << 20);
    #pragma unroll
    for (int mi = 0; mi < 4; mi++) {
        #pragma unroll
        for (int ni = 0; ni < 4; ni++) {
            int row = bm + wm + mi*16 + g;
            int col = bn + wn + ni*8 + 2*tig;
            float* d = acc[mi*4 + ni];
            *(float2*)&cbase[(size_t)row*1024 + col]     = make_float2(d[0], d[1]);
            *(float2*)&cbase[(size_t)(row+8)*1024 + col] = make_float2(d[2], d[3]);
        }
    }
}

// reduce fc1 partials -> relu -> fp16 h1
__global__ void reduce1_kernel(const float* __restrict__ part,
                               const float* __restrict__ bias,
                               u16* __restrict__ Hh) {
    size_t idx = (size_t)blockIdx.x * 256 + threadIdx.x;
    int n = (int)(idx & 1023);
    float s = bias[n];
    #pragma unroll
    for (int i = 0; i < 16; i++) s += part[((size_t)i << 20) + idx];
    s = fmaxf(s, 0.0f);
    __half h = __float2half_rn(s);
    Hh[idx] = *(u16*)&h;
}

// reduce fc2 partials -> relu -> f32 h2
__global__ void reduce2_kernel(const float* __restrict__ part,
                               const float* __restrict__ bias,
                               float* __restrict__ H) {
    size_t idx = (size_t)blockIdx.x * 256 + threadIdx.x;
    int n = (int)(idx & 1023);
    float s = bias[n];
    #pragma unroll
    for (int i = 0; i < 4; i++) s += part[((size_t)i << 20) + idx];
    H[idx] = fmaxf(s, 0.0f);
}

// ---------------- cls + bbox heads: block per roi ----------------
__global__ void __launch_bounds__(256)
fc_small2_kernel(const float* __restrict__ h,
                 const float* __restrict__ clsw, const float* __restrict__ clsb,
                 const float* __restrict__ bbw, const float* __restrict__ bbb,
                 float* __restrict__ logits, float* __restrict__ breg) {
    __shared__ float hs[1024];
    int r = blockIdx.x;
    int tid = threadIdx.x;
    const float* hp = h + (size_t)r*1024;
    for (int i = tid; i < 1024; i += 256) hs[i] = hp[i];
    __syncthreads();
    if (tid < 240) {
        int j = tid >> 3, part = tid & 7;
        float acc = 0.0f;
        if (j < 6) {
            for (int k = part; k < 1024; k += 8)
                acc = fmaf(hs[k], clsw[k*6 + j], acc);
        } else {
            int q = j - 6;
            for (int k = part; k < 1024; k += 8)
                acc = fmaf(hs[k], bbw[k*24 + q], acc);
        }
        #pragma unroll
        for (int off = 4; off; off >>= 1)
            acc += __shfl_down_sync(0xffffffff, acc, off);
        if (part == 0) {
            if (j < 6) logits[r*6 + j] = acc + clsb[j];
            else       breg[r*24 + (j-6)] = acc + bbb[j-6];
        }
    }
}

// ---------------- final ----------------
__global__ void final_kernel(const float* __restrict__ rois,
                             const float* __restrict__ logits,
                             const float* __restrict__ breg,
                             float* __restrict__ out) {
    int r = blockIdx.x * 128 + threadIdx.x;
    if (r >= TOPN) return;
    float l[6];
    float m = -INFINITY;
    #pragma unroll
    for (int i = 0; i < 6; i++) { l[i] = logits[r*6 + i]; m = fmaxf(m, l[i]); }
    float ssum = 0.0f;
    #pragma unroll
    for (int i = 0; i < 6; i++) { l[i] = expf(l[i] - m); ssum += l[i]; }
    float inv = 1.0f / ssum;

    float x1 = rois[r*4+0], y1 = rois[r*4+1], x2 = rois[r*4+2], y2 = rois[r*4+3];
    float W = x2 - x1, H = y2 - y1;
    float cx = x1 + 0.5f*W, cy = y1 + 0.5f*H;
    #pragma unroll
    for (int c = 1; c < 6; c++) {
        float dx = breg[r*24 + c*4+0] / 10.0f;
        float dy = breg[r*24 + c*4+1] / 10.0f;
        float dw = fminf(breg[r*24 + c*4+2] / 5.0f, BBOX_CLAMP);
        float dh = fminf(breg[r*24 + c*4+3] / 5.0f, BBOX_CLAMP);
        float pcx = dx*W + cx, pcy = dy*H + cy;
        float pw = expf(dw)*W, ph = expf(dh)*H;
        float bx1 = fminf(fmaxf(pcx - 0.5f*pw, 0.0f), 512.0f);
        float by1 = fminf(fmaxf(pcy - 0.5f*ph, 0.0f), 512.0f);
        float bx2 = fminf(fmaxf(pcx + 0.5f*pw, 0.0f), 512.0f);
        float by2 = fminf(fmaxf(pcy + 0.5f*ph, 0.0f), 512.0f);
        int o = r*25 + (c-1)*5;
        out[o+0] = bx1; out[o+1] = by1; out[o+2] = bx2; out[o+3] = by2;
        out[o+4] = l[c] * inv;
    }
}

// ---------------- launcher ----------------
extern "C" void kernel_launch(void* const* d_in, const int* in_sizes, int n_in,
                              void* d_out, int out_size) {
    const float* images     = (const float*)d_in[0];
    const float* c0_w       = (const float*)d_in[1];
    const float* c0_b       = (const float*)d_in[2];
    const float* c1_w       = (const float*)d_in[3];
    const float* c1_b       = (const float*)d_in[4];
    const float* c2_w       = (const float*)d_in[5];
    const float* c2_b       = (const float*)d_in[6];
    const float* c3_w       = (const float*)d_in[7];
    const float* c3_b       = (const float*)d_in[8];
    const float* rpn_conv_w = (const float*)d_in[9];
    const float* rpn_conv_b = (const float*)d_in[10];
    const float* rpn_cls_w  = (const float*)d_in[11];
    const float* rpn_cls_b  = (const float*)d_in[12];
    const float* rpn_bbox_w = (const float*)d_in[13];
    const float* rpn_bbox_b = (const float*)d_in[14];
    const float* fc1_w      = (const float*)d_in[15];
    const float* fc1_b      = (const float*)d_in[16];
    const float* fc2_w      = (const float*)d_in[17];
    const float* fc2_b      = (const float*)d_in[18];
    const float* cls_w      = (const float*)d_in[19];
    const float* cls_b      = (const float*)d_in[20];
    const float* bbox_w     = (const float*)d_in[21];
    const float* bbox_b     = (const float*)d_in[22];
    float* out = (float*)d_out;

    float *p_c0, *p_pool, *p_c1, *p_c2, *p_feat, *p_rpn, *p_cpart, *p_obj, *p_bd;
    float *p_props, *p_scores, *p_rois, *p_part, *p_h2, *p_logits, *p_breg;
    int *p_topidx;
    u16 *p_Ah, *p_B1h, *p_B2h, *p_h1h;
    cudaGetSymbolAddress((void**)&p_c0, g_c0);
    cudaGetSymbolAddress((void**)&p_pool, g_pool);
    cudaGetSymbolAddress((void**)&p_c1, g_c1);
    cudaGetSymbolAddress((void**)&p_c2, g_c2);
    cudaGetSymbolAddress((void**)&p_feat, g_feat);
    cudaGetSymbolAddress((void**)&p_rpn, g_rpn);
    cudaGetSymbolAddress((void**)&p_cpart, g_cpart);
    cudaGetSymbolAddress((void**)&p_obj, g_obj);
    cudaGetSymbolAddress((void**)&p_bd, g_bd);
    cudaGetSymbolAddress((void**)&p_props, g_props);
    cudaGetSymbolAddress((void**)&p_scores, g_scores);
    cudaGetSymbolAddress((void**)&p_topidx, g_topidx);
    cudaGetSymbolAddress((void**)&p_rois, g_rois);
    cudaGetSymbolAddress((void**)&p_Ah, g_Ah);
    cudaGetSymbolAddress((void**)&p_B1h, g_B1h);
    cudaGetSymbolAddress((void**)&p_B2h, g_B2h);
    cudaGetSymbolAddress((void**)&p_h1h, g_h1h);
    cudaGetSymbolAddress((void**)&p_part, g_part);
    cudaGetSymbolAddress((void**)&p_h2, g_h2);
    cudaGetSymbolAddress((void**)&p_logits, g_logits);
    cudaGetSymbolAddress((void**)&p_breg, g_breg);

    // backbone
    conv0v2_kernel<<<dim3(8,16,16), dim3(8,16)>>>(images, c0_w, c0_b, p_c0);
    maxpool_kernel<<<(64*128*128 + 255)/256, 256>>>(p_c0, p_pool);
    // c1: 64->128, 128->64, s2, CS=2 -> 512 CTAs
    conv3x3t_kernel<2><<<dim3(4,4,32), 256>>>(p_pool, c1_w, c1_b, p_c1, p_cpart,
                                              64, 128, 64, 128, 2);
    creduce_kernel<<<(128*4096+255)/256, 256>>>(p_cpart, c1_b, p_c1, 4096, 2, 128*4096);
    // c2: 128->256, 64->32, s2, CS=4 -> 512 CTAs
    conv3x3t_kernel<2><<<dim3(2,2,128), 256>>>(p_c1, c2_w, c2_b, p_c2, p_cpart,
                                               128, 64, 32, 256, 4);
    creduce_kernel<<<(256*1024+255)/256, 256>>>(p_cpart, c2_b, p_c2, 1024, 4, 256*1024);
    // c3: 256->512, 32->16, s2, CS=8 -> 512 CTAs   (ncu capture slot: launch #7)
    conv3x3t_kernel<2><<<dim3(1,1,512), 256>>>(p_c2, c3_w, c3_b, p_feat, p_cpart,
                                               256, 32, 16, 512, 8);
    creduce_kernel<<<(512*256+255)/256, 256>>>(p_cpart, c3_b, p_feat, 256, 8, 512*256);
    // rpn: 512->512, 16->16, s1, CS=8 -> 512 CTAs
    conv3x3t_kernel<1><<<dim3(1,1,512), 256>>>(p_feat, rpn_conv_w, rpn_conv_b, p_rpn, p_cpart,
                                               512, 16, 16, 512, 8);
    creduce_kernel<<<(512*256+255)/256, 256>>>(p_cpart, rpn_conv_b, p_rpn, 256, 8, 512*256);

    conv1x1_kernel<<<9, 256>>>(p_rpn, rpn_cls_w, rpn_cls_b, p_obj, 512);
    conv1x1_kernel<<<36, 256>>>(p_rpn, rpn_bbox_w, rpn_bbox_b, p_bd, 512);

    // proposals
    rpn_decode_kernel<<<9, 256>>>(p_obj, p_bd, p_props, p_scores);
    topk_kernel<<<1, 1024>>>(p_scores, p_topidx);
    gather_rois_kernel<<<4, 256>>>(p_props, p_topidx, p_rois);

    // roi align -> fp16 A
    roi_align2_kernel<<<TOPN, 256>>>(p_feat, p_rois, p_Ah);
    padA_kernel<<<(24*25088 + 255)/256, 256>>>(p_Ah);

    // weight transpose -> fp16
    tsplit_kernel<<<dim3(1024/32, 25088/32), dim3(32,8)>>>(fc1_w, p_B1h, 25088, 1024);
    tsplit_kernel<<<dim3(1024/32, 1024/32),  dim3(32,8)>>>(fc2_w, p_B2h, 1024, 1024);

    // fc1: K=25088, z=16 -> stages 98
    gemm_fp16_kernel<<<dim3(8,8,16), 256>>>(p_Ah, p_B1h, p_part, 25088, 98);
    reduce1_kernel<<<(1024*1024)/256, 256>>>(p_part, fc1_b, p_h1h);

    // fc2: K=1024, z=4 -> stages 16
    gemm_fp16_kernel<<<dim3(8,8,4), 256>>>(p_h1h, p_B2h, p_part, 1024, 16);
    reduce2_kernel<<<(1024*1024)/256, 256>>>(p_part, fc2_b, p_h2);

    fc_small2_kernel<<<TOPN, 256>>>(p_h2, cls_w, cls_b, bbox_w, bbox_b, p_logits, p_breg);
    final_kernel<<<(TOPN + 127)/128, 128>>>(p_rois, p_logits, p_breg, out);
}

// round 11
// speedup vs baseline: 1.9231x; 1.0673x over previous
#include <cuda_runtime.h>
#include <cuda_fp16.h>
#include <math.h>
#include <stdint.h>

#define TOPN 1000
#define BBOX_CLAMP 4.135166556742356f
typedef unsigned short u16;

// ---------------- scratch (device globals) ----------------
__device__ float g_c0[64*256*256];
__device__ float g_pool[64*128*128];
__device__ float g_c1[128*64*64];
__device__ float g_c2[256*32*32];
__device__ float g_feat[512*16*16];
__device__ float g_rpn[512*16*16];
__device__ float g_cpart[1048576];
__device__ float g_obj[9*16*16];
__device__ float g_bd[36*16*16];
__device__ float g_props[2304*4];
__device__ float g_scores[2304];
__device__ int   g_topidx[TOPN];
__device__ float g_rois[TOPN*4];
__device__ int   g_geoi[1024*56];
__device__ float g_geow[1024*56];
__device__ u16 g_Ah[1024u*25088u];
__device__ u16 g_B1h[1024u*25088u];
__device__ u16 g_B2h[1024u*1024u];
__device__ u16 g_h1h[1024u*1024u];
__device__ float g_part[16u*1024u*1024u];
__device__ float g_h2[1024u*1024u];
__device__ float g_logits[TOPN*6];
__device__ float g_breg[TOPN*24];

// ---------------- conv0: smem-tiled 7x7 s2 ----------------
__global__ void conv0v2_kernel(const float* __restrict__ img,
                               const float* __restrict__ w,
                               const float* __restrict__ b,
                               float* __restrict__ out) {
    __shared__ float tile[3][37][72];
    __shared__ float ws[4][147];
    int tx = threadIdx.x, ty = threadIdx.y;
    int tid = ty*8 + tx;
    int oc0 = blockIdx.z * 4;
    int x0 = blockIdx.x * 32;
    int y0 = blockIdx.y * 16;
    int ixs = 2*x0 - 3, iys = 2*y0 - 3;
    const float mean[3] = {0.485f, 0.456f, 0.406f};
    const float istd[3] = {1.0f/0.229f, 1.0f/0.224f, 1.0f/0.225f};

    for (int i = tid; i < 3*37*72; i += 128) {
        int c = i / (37*72); int rem = i % (37*72);
        int iy = rem / 72, ix = rem % 72;
        int gy = iys + iy, gx = ixs + ix;
        float v = 0.0f;
        if (gy >= 0 && gy < 512 && gx >= 0 && gx < 512 && ix < 69)
            v = (img[(c*512 + gy)*512 + gx] - mean[c]) * istd[c];
        tile[c][iy][ix] = v;
    }
    for (int i = tid; i < 4*147; i += 128)
        ws[i/147][i%147] = w[(size_t)(oc0 + i/147)*147 + i%147];
    __syncthreads();

    float acc[4][4];
    #pragma unroll
    for (int oc = 0; oc < 4; oc++) {
        float bb = b[oc0+oc];
        #pragma unroll
        for (int xo = 0; xo < 4; xo++) acc[oc][xo] = bb;
    }
    for (int c = 0; c < 3; c++) {
        #pragma unroll
        for (int ky = 0; ky < 7; ky++) {
            const float* row = tile[c][2*ty + ky];
            float v[13];
            #pragma unroll
            for (int j = 0; j < 13; j++) v[j] = row[8*tx + j];
            #pragma unroll
            for (int kx = 0; kx < 7; kx++) {
                float w0 = ws[0][c*49 + ky*7 + kx];
                float w1 = ws[1][c*49 + ky*7 + kx];
                float w2 = ws[2][c*49 + ky*7 + kx];
                float w3 = ws[3][c*49 + ky*7 + kx];
                #pragma unroll
                for (int xo = 0; xo < 4; xo++) {
                    float vv = v[2*xo + kx];
                    acc[0][xo] = fmaf(vv, w0, acc[0][xo]);
                    acc[1][xo] = fmaf(vv, w1, acc[1][xo]);
                    acc[2][xo] = fmaf(vv, w2, acc[2][xo]);
                    acc[3][xo] = fmaf(vv, w3, acc[3][xo]);
                }
            }
        }
    }
    int y = y0 + ty;
    #pragma unroll
    for (int oc = 0; oc < 4; oc++)
        #pragma unroll
        for (int xo = 0; xo < 4; xo++)
            out[(size_t)(oc0+oc)*65536 + y*256 + x0 + tx*4 + xo] = fmaxf(acc[oc][xo], 0.0f);
}

// ---------------- maxpool 3x3 s2 p1 ----------------
__global__ void maxpool_kernel(const float* __restrict__ in, float* __restrict__ out) {
    int idx = blockIdx.x * 256 + threadIdx.x;
    if (idx >= 64*128*128) return;
    int x = idx & 127;
    int y = (idx >> 7) & 127;
    int c = idx >> 14;
    float m = -INFINITY;
    #pragma unroll
    for (int dy = 0; dy < 3; dy++) {
        int iy = 2*y - 1 + dy;
        if (iy < 0 || iy >= 256) continue;
        #pragma unroll
        for (int dx = 0; dx < 3; dx++) {
            int ix = 2*x - 1 + dx;
            if (ix < 0 || ix >= 256) continue;
            m = fmaxf(m, in[(c*256 + iy)*256 + ix]);
        }
    }
    out[idx] = m;
}

// ---------------- 3x3 conv: templated stride ----------------
#define CCH 4
template<int STRIDE>
__global__ void __launch_bounds__(256)
conv3x3t_kernel(const float* __restrict__ in, const float* __restrict__ w,
                const float* __restrict__ bias,
                float* __restrict__ out, float* __restrict__ partial,
                int Cin, int Hin, int Hout, int Cout, int cs) {
    constexpr int TH  = STRIDE*15 + 3;
    constexpr int TWP = (STRIDE == 2) ? 36 : 20;
    constexpr int TSZ = TH * TWP;
    __shared__ float tile[CCH*TSZ];
    __shared__ float ws[8*CCH*9];
    int nocg = Cout >> 3;
    int ocg = blockIdx.z % nocg, slice = blockIdx.z / nocg;
    int oc0 = ocg * 8;
    int tid = threadIdx.x;
    int tx = tid & 15, ty = tid >> 4;
    int x0 = blockIdx.x * 16, y0 = blockIdx.y * 16;
    int iys = y0*STRIDE - 1, ixs = x0*STRIDE - 1;
    int cps = Cin / cs;
    int cbeg = slice * cps;

    float acc[8];
    #pragma unroll
    for (int oc = 0; oc < 8; oc++) acc[oc] = 0.0f;

    for (int c0 = 0; c0 < cps; c0 += CCH) {
        __syncthreads();
        #pragma unroll 4
        for (int i = tid; i < CCH*TSZ; i += 256) {
            int c = i / TSZ;
            int rem = i - c*TSZ;
            int r = rem / TWP, col = rem - r*TWP;
            int gy = iys + r, gx = ixs + col;
            float v = 0.0f;
            if (col < TH && gy >= 0 && gy < Hin && gx >= 0 && gx < Hin)
                v = in[(size_t)(cbeg + c0 + c)*Hin*Hin + gy*Hin + gx];
            tile[i] = v;
        }
        for (int i = tid; i < 8*CCH*9; i += 256) {
            int oc = i / (CCH*9);
            int rem = i - oc*CCH*9;
            int c = rem / 9, k = rem - c*9;
            ws[i] = w[(size_t)(oc0 + oc)*Cin*9 + (size_t)(cbeg + c0 + c)*9 + k];
        }
        __syncthreads();
        #pragma unroll
        for (int cl = 0; cl < CCH; cl++) {
            const float* tb = tile + cl*TSZ;
            float v[9];
            #pragma unroll
            for (int ky = 0; ky < 3; ky++)
                #pragma unroll
                for (int kx = 0; kx < 3; kx++)
                    v[ky*3+kx] = tb[(STRIDE*ty + ky)*TWP + STRIDE*tx + kx];
            const float* wp = ws + cl*9;
            #pragma unroll
            for (int oc = 0; oc < 8; oc++)
                #pragma unroll
                for (int k = 0; k < 9; k++)
                    acc[oc] = fmaf(v[k], wp[oc*CCH*9 + k], acc[oc]);
        }
    }

    size_t HW = (size_t)Hout*Hout;
    size_t pix = (size_t)(y0 + ty)*Hout + x0 + tx;
    if (cs == 1) {
        #pragma unroll
        for (int oc = 0; oc < 8; oc++)
            out[(size_t)(oc0+oc)*HW + pix] = fmaxf(acc[oc] + bias[oc0+oc], 0.0f);
    } else {
        #pragma unroll
        for (int oc = 0; oc < 8; oc++)
            partial[(size_t)slice*Cout*HW + (size_t)(oc0+oc)*HW + pix] = acc[oc];
    }
}

// reduce conv partials -> bias + relu
__global__ void creduce_kernel(const float* __restrict__ partial,
                               const float* __restrict__ bias,
                               float* __restrict__ out, int HW, int ns, int total) {
    int idx = blockIdx.x * 256 + threadIdx.x;
    if (idx >= total) return;
    int oc = idx / HW;
    float s = bias[oc];
    for (int i = 0; i < ns; i++) s += partial[(size_t)i*total + idx];
    out[idx] = fmaxf(s, 0.0f);
}

// ---------------- merged RPN 1x1 heads (obj 9ch + bd 36ch) ----------------
__global__ void rpnheads_kernel(const float* __restrict__ in,
                                const float* __restrict__ clsw, const float* __restrict__ clsb,
                                const float* __restrict__ bbw, const float* __restrict__ bbb,
                                float* __restrict__ obj, float* __restrict__ bd) {
    int o = blockIdx.x;
    int p = threadIdx.x;
    const float* w;
    float acc;
    if (o < 9) { w = clsw + o*512; acc = clsb[o]; }
    else       { w = bbw + (o-9)*512; acc = bbb[o-9]; }
    for (int c = 0; c < 512; c++)
        acc = fmaf(in[c*256 + p], w[c], acc);
    if (o < 9) obj[o*256 + p] = acc;
    else       bd[(o-9)*256 + p] = acc;
}

// ---------------- RPN decode ----------------
__global__ void rpn_decode_kernel(const float* __restrict__ obj,
                                  const float* __restrict__ bd,
                                  float* __restrict__ props,
                                  float* __restrict__ scores) {
    int i = blockIdx.x * 256 + threadIdx.x;
    if (i >= 2304) return;
    int a = i % 9;
    int cell = i / 9;
    int wq = cell % 16;
    int hq = cell / 16;
    int pix = hq*16 + wq;
    scores[i] = obj[a*256 + pix];

    const float ratios[3] = {0.5f, 1.0f, 2.0f};
    int r = a / 3, s = a % 3;
    float scale = 128.0f * (float)(1 << s);
    float hr = sqrtf(ratios[r]);
    float wr = 1.0f / hr;
    float hw = rintf(wr * scale * 0.5f);
    float hh = rintf(hr * scale * 0.5f);
    float sx = (float)(wq * 32), sy = (float)(hq * 32);
    float W = 2.0f*hw, H = 2.0f*hh;
    float cx = sx, cy = sy;

    float dx = bd[(a*4+0)*256 + pix];
    float dy = bd[(a*4+1)*256 + pix];
    float dw = fminf(bd[(a*4+2)*256 + pix], BBOX_CLAMP);
    float dh = fminf(bd[(a*4+3)*256 + pix], BBOX_CLAMP);
    float pcx = dx*W + cx, pcy = dy*H + cy;
    float pw = expf(dw)*W, ph = expf(dh)*H;
    props[i*4+0] = pcx - 0.5f*pw;
    props[i*4+1] = pcy - 0.5f*ph;
    props[i*4+2] = pcx + 0.5f*pw;
    props[i*4+3] = pcy + 0.5f*ph;
}

// ---------------- top-k bitonic ----------------
__device__ __forceinline__ bool tk_lt(float sa, int ia, float sb, int ib) {
    return (sa > sb) || (sa == sb && ia < ib);
}
__global__ void topk_kernel(const float* __restrict__ scores, int* __restrict__ topidx) {
    __shared__ float s[4096];
    __shared__ int   ind[4096];
    int tid = threadIdx.x;
    for (int i = tid; i < 4096; i += 1024) {
        s[i] = (i < 2304) ? scores[i] : -INFINITY;
        ind[i] = i;
    }
    __syncthreads();
    for (int k = 2; k <= 4096; k <<= 1) {
        for (int j = k >> 1; j > 0; j >>= 1) {
            for (int base = 0; base < 4096; base += 1024) {
                int i = base + tid;
                int ixj = i ^ j;
                if (ixj > i) {
                    bool up = ((i & k) == 0);
                    float si = s[i], sj = s[ixj];
                    int ii = ind[i], ij = ind[ixj];
                    bool swp = up ? tk_lt(sj, ij, si, ii) : tk_lt(si, ii, sj, ij);
                    if (swp) { s[i] = sj; s[ixj] = si; ind[i] = ij; ind[ixj] = ii; }
                }
            }
            __syncthreads();
        }
    }
    for (int i = tid; i < TOPN; i += 1024) topidx[i] = ind[i];
}

__global__ void gather_rois_kernel(const float* __restrict__ props,
                                   const int* __restrict__ topidx,
                                   float* __restrict__ rois) {
    int i = blockIdx.x * 256 + threadIdx.x;
    if (i >= TOPN) return;
    int idx = topidx[i];
    #pragma unroll
    for (int k = 0; k < 4; k++)
        rois[i*4+k] = fminf(fmaxf(props[idx*4+k], 0.0f), 512.0f);
}

// ---------------- roi geometry precompute (1024 rois, >=1000 zeroed) ----------------
__global__ void roigeo_kernel(const float* __restrict__ rois,
                              int* __restrict__ geoi, float* __restrict__ geow) {
    int t = blockIdx.x * 256 + threadIdx.x;
    if (t >= 1024*28) return;
    int rr = t / 28, i = t % 28;
    int ii = i % 14;
    bool isY = i >= 14;
    int pp = ii >> 1, sl = (ii & 1) * 2;
    int base = rr*56 + (isY ? 28 : 0) + pp*4 + sl;
    if (rr >= TOPN) {
        geoi[base] = 0; geoi[base+1] = 0;
        geow[base] = 0.0f; geow[base+1] = 0.0f;
        return;
    }
    float c1 = rois[rr*4 + (isY ? 1 : 0)];
    float c2 = rois[rr*4 + (isY ? 3 : 2)];
    float lo = c1 * (1.0f/32.0f);
    float hi = c2 * (1.0f/32.0f);
    float sz = fmaxf(hi - lo, 1.0f);
    float g = ((float)ii + 0.5f) / 14.0f;
    float p = fminf(fmaxf(lo + g*sz, 0.0f), 15.0f);
    int p0 = (int)floorf(p);
    int p1 = min(p0 + 1, 15);
    float l = p - (float)p0;
    geoi[base] = p0; geoi[base+1] = p1;
    geow[base] = 0.5f * (1.0f - l); geow[base+1] = 0.5f * l;
}

// ---------------- ROI align v3: channel-group x roi-chunk blocks ----------------
__global__ void __launch_bounds__(256)
roi_align3_kernel(const float* __restrict__ feat,
                  const int* __restrict__ geoi, const float* __restrict__ geow,
                  u16* __restrict__ Ah) {
    __shared__ float ftile[16*256];   // 16 channels
    __shared__ int   si[64*56];
    __shared__ float sw[64*56];
    int cg = blockIdx.x;              // 0..31
    int chunk = blockIdx.y;           // 0..15 (64 rois each)
    int tid = threadIdx.x;
    // stage channels
    {
        const float4* src = (const float4*)(feat + (size_t)cg*16*256);
        float4* dst = (float4*)ftile;
        for (int i = tid; i < 1024; i += 256) dst[i] = src[i];
    }
    // stage geometry for 64 rois
    int gbase = chunk*64*56;
    for (int i = tid; i < 64*56; i += 256) {
        si[i] = geoi[gbase + i];
        sw[i] = geow[gbase + i];
    }
    __syncthreads();

    for (int rl = 0; rl < 64; rl++) {
        int rr = chunk*64 + rl;
        const int* gi = si + rl*56;
        const float* gw = sw + rl*56;
        for (int t = tid; t < 784; t += 256) {
            int cl = t / 49, p = t % 49;
            int py = p / 7, px = p % 7;
            const float* f = ftile + cl*256;
            float acc = 0.0f;
            #pragma unroll
            for (int a = 0; a < 4; a++) {
                const float* frow = f + gi[28 + py*4 + a]*16;
                float s = 0.0f;
                #pragma unroll
                for (int bb = 0; bb < 4; bb++)
                    s = fmaf(gw[px*4 + bb], frow[gi[px*4 + bb]], s);
                acc = fmaf(gw[28 + py*4 + a], s, acc);
            }
            __half h = __float2half_rn(acc);
            Ah[(size_t)rr*25088 + (size_t)(cg*16 + cl)*49 + p] = *(u16*)&h;
        }
    }
}

// ---------------- transpose + fp16 weights ----------------
__global__ void tsplit_kernel(const float* __restrict__ W,
                              u16* __restrict__ Th, int K, int N) {
    __shared__ float t[32][33];
    int n0 = blockIdx.x * 32, k0 = blockIdx.y * 32;
    int tx = threadIdx.x, ty = threadIdx.y;
    #pragma unroll
    for (int i = 0; i < 4; i++)
        t[ty + 8*i][tx] = W[(size_t)(k0 + ty + 8*i)*N + n0 + tx];
    __syncthreads();
    #pragma unroll
    for (int i = 0; i < 4; i++) {
        __half h = __float2half_rn(t[tx][ty + 8*i]);
        Th[(size_t)(n0 + ty + 8*i)*K + k0 + tx] = *(u16*)&h;
    }
}

// ---------------- single-pass fp16 tensor-core GEMM ----------------
__device__ __forceinline__ void mma16816_f32(float& d0, float& d1, float& d2, float& d3,
                                             uint32_t a0, uint32_t a1, uint32_t a2, uint32_t a3,
                                             uint32_t b0, uint32_t b1) {
    asm volatile("mma.sync.aligned.m16n8k16.row.col.f32.f16.f16.f32 "
                 "{%0,%1,%2,%3}, {%4,%5,%6,%7}, {%8,%9}, {%0,%1,%2,%3};\n"
                 : "+f"(d0), "+f"(d1), "+f"(d2), "+f"(d3)
                 : "r"(a0), "r"(a1), "r"(a2), "r"(a3), "r"(b0), "r"(b1));
}
__device__ __forceinline__ void cpasync16(uint32_t dst, const void* src) {
    asm volatile("cp.async.cg.shared.global [%0], [%1], 16;\n" :: "r"(dst), "l"(src));
}
__device__ __forceinline__ void ldsm_x4(uint32_t& r0, uint32_t& r1, uint32_t& r2, uint32_t& r3,
                                        uint32_t addr) {
    asm volatile("ldmatrix.sync.aligned.m8n8.x4.shared.b16 {%0,%1,%2,%3}, [%4];\n"
                 : "=r"(r0), "=r"(r1), "=r"(r2), "=r"(r3) : "r"(addr));
}

#define LDK 24

__global__ void __launch_bounds__(256)
gemm_fp16_kernel(const u16* __restrict__ A, const u16* __restrict__ B,
                 float* __restrict__ part, int K, int stages) {
    __shared__ __align__(16) u16 sm[2][2][128*LDK];
    int tid = threadIdx.x;
    int wid = tid >> 5, lane = tid & 31;
    int wm = (wid & 1) * 64;
    int wn = (wid >> 1) * 32;
    int g = lane >> 2, tig = lane & 3;
    int r8 = lane & 7, q = lane >> 3;
    int bm = blockIdx.y * 128, bn = blockIdx.x * 128;
    int kbase = blockIdx.z * stages * 16;

    float acc[16][4];
    #pragma unroll
    for (int i = 0; i < 16; i++)
        #pragma unroll
        for (int j = 0; j < 4; j++) acc[i][j] = 0.0f;

    uint32_t smb = (uint32_t)__cvta_generic_to_shared(&sm[0][0][0]);
    const uint32_t MAT = 128*LDK*2;
    const uint32_t BUF = 2*MAT;
    uint32_t offA = (uint32_t)(((wm + (q & 1)*8 + r8)*LDK + (q >> 1)*8) * 2);
    uint32_t offB = (uint32_t)(((wn + (q >> 1)*8 + r8)*LDK + (q & 1)*8) * 2);

    auto load_stage = [&](int buf, int s) {
        int kpos0 = kbase + s * 16;
        #pragma unroll
        for (int l = 0; l < 2; l++) {
            int idx = l * 256 + tid;
            int pl = idx >> 8;
            int rr = (idx & 255) >> 1;
            int half = idx & 1;
            const u16* src = (pl ? B + (size_t)(bn + rr)*K : A + (size_t)(bm + rr)*K)
                             + kpos0 + half*8;
            uint32_t dst = (uint32_t)__cvta_generic_to_shared(&sm[buf][pl][rr*LDK + half*8]);
            cpasync16(dst, src);
        }
        asm volatile("cp.async.commit_group;\n");
    };

    load_stage(0, 0);

    for (int s = 0; s < stages; s++) {
        if (s + 1 < stages) {
            load_stage((s + 1) & 1, s + 1);
            asm volatile("cp.async.wait_group 1;\n");
        } else {
            asm volatile("cp.async.wait_group 0;\n");
        }
        __syncthreads();
        uint32_t base = smb + (uint32_t)(s & 1)*BUF;
        uint32_t aA = base + offA;
        uint32_t aB = base + MAT + offB;

        uint32_t bh[4][2], ah[4][4];
        #pragma unroll
        for (int p = 0; p < 2; p++)
            ldsm_x4(bh[2*p][0], bh[2*p][1], bh[2*p+1][0], bh[2*p+1][1], aB + p*16*LDK*2);
        #pragma unroll
        for (int mi = 0; mi < 4; mi++)
            ldsm_x4(ah[mi][0], ah[mi][1], ah[mi][2], ah[mi][3], aA + mi*16*LDK*2);

        #pragma unroll
        for (int mi = 0; mi < 4; mi++)
            #pragma unroll
            for (int ni = 0; ni < 4; ni++) {
                float* d = acc[mi*4 + ni];
                mma16816_f32(d[0], d[1], d[2], d[3],
                             ah[mi][0], ah[mi][1], ah[mi][2], ah[mi][3], bh[ni][0], bh[ni][1]);
            }
        __syncthreads();
    }

    float* cbase = part + ((size_t)blockIdx.z << 20);
    #pragma unroll
    for (int mi = 0; mi < 4; mi++) {
        #pragma unroll
        for (int ni = 0; ni < 4; ni++) {
            int row = bm + wm + mi*16 + g;
            int col = bn + wn + ni*8 + 2*tig;
            float* d = acc[mi*4 + ni];
            *(float2*)&cbase[(size_t)row*1024 + col]     = make_float2(d[0], d[1]);
            *(float2*)&cbase[(size_t)(row+8)*1024 + col] = make_float2(d[2], d[3]);
        }
    }
}

// reduce fc1 partials -> relu -> fp16 h1
__global__ void reduce1_kernel(const float* __restrict__ part,
                               const float* __restrict__ bias,
                               u16* __restrict__ Hh) {
    size_t idx = (size_t)blockIdx.x * 256 + threadIdx.x;
    int n = (int)(idx & 1023);
    float s = bias[n];
    #pragma unroll
    for (int i = 0; i < 16; i++) s += part[((size_t)i << 20) + idx];
    s = fmaxf(s, 0.0f);
    __half h = __float2half_rn(s);
    Hh[idx] = *(u16*)&h;
}

// reduce fc2 partials -> relu -> f32 h2
__global__ void reduce2_kernel(const float* __restrict__ part,
                               const float* __restrict__ bias,
                               float* __restrict__ H) {
    size_t idx = (size_t)blockIdx.x * 256 + threadIdx.x;
    int n = (int)(idx & 1023);
    float s = bias[n];
    #pragma unroll
    for (int i = 0; i < 4; i++) s += part[((size_t)i << 20) + idx];
    H[idx] = fmaxf(s, 0.0f);
}

// ---------------- cls + bbox heads: block per roi ----------------
__global__ void __launch_bounds__(256)
fc_small2_kernel(const float* __restrict__ h,
                 const float* __restrict__ clsw, const float* __restrict__ clsb,
                 const float* __restrict__ bbw, const float* __restrict__ bbb,
                 float* __restrict__ logits, float* __restrict__ breg) {
    __shared__ float hs[1024];
    int r = blockIdx.x;
    int tid = threadIdx.x;
    const float* hp = h + (size_t)r*1024;
    for (int i = tid; i < 1024; i += 256) hs[i] = hp[i];
    __syncthreads();
    if (tid < 240) {
        int j = tid >> 3, part = tid & 7;
        float acc = 0.0f;
        if (j < 6) {
            for (int k = part; k < 1024; k += 8)
                acc = fmaf(hs[k], clsw[k*6 + j], acc);
        } else {
            int q = j - 6;
            for (int k = part; k < 1024; k += 8)
                acc = fmaf(hs[k], bbw[k*24 + q], acc);
        }
        #pragma unroll
        for (int off = 4; off; off >>= 1)
            acc += __shfl_down_sync(0xffffffff, acc, off);
        if (part == 0) {
            if (j < 6) logits[r*6 + j] = acc + clsb[j];
            else       breg[r*24 + (j-6)] = acc + bbb[j-6];
        }
    }
}

// ---------------- final ----------------
__global__ void final_kernel(const float* __restrict__ rois,
                             const float* __restrict__ logits,
                             const float* __restrict__ breg,
                             float* __restrict__ out) {
    int r = blockIdx.x * 128 + threadIdx.x;
    if (r >= TOPN) return;
    float l[6];
    float m = -INFINITY;
    #pragma unroll
    for (int i = 0; i < 6; i++) { l[i] = logits[r*6 + i]; m = fmaxf(m, l[i]); }
    float ssum = 0.0f;
    #pragma unroll
    for (int i = 0; i < 6; i++) { l[i] = expf(l[i] - m); ssum += l[i]; }
    float inv = 1.0f / ssum;

    float x1 = rois[r*4+0], y1 = rois[r*4+1], x2 = rois[r*4+2], y2 = rois[r*4+3];
    float W = x2 - x1, H = y2 - y1;
    float cx = x1 + 0.5f*W, cy = y1 + 0.5f*H;
    #pragma unroll
    for (int c = 1; c < 6; c++) {
        float dx = breg[r*24 + c*4+0] / 10.0f;
        float dy = breg[r*24 + c*4+1] / 10.0f;
        float dw = fminf(breg[r*24 + c*4+2] / 5.0f, BBOX_CLAMP);
        float dh = fminf(breg[r*24 + c*4+3] / 5.0f, BBOX_CLAMP);
        float pcx = dx*W + cx, pcy = dy*H + cy;
        float pw = expf(dw)*W, ph = expf(dh)*H;
        float bx1 = fminf(fmaxf(pcx - 0.5f*pw, 0.0f), 512.0f);
        float by1 = fminf(fmaxf(pcy - 0.5f*ph, 0.0f), 512.0f);
        float bx2 = fminf(fmaxf(pcx + 0.5f*pw, 0.0f), 512.0f);
        float by2 = fminf(fmaxf(pcy + 0.5f*ph, 0.0f), 512.0f);
        int o = r*25 + (c-1)*5;
        out[o+0] = bx1; out[o+1] = by1; out[o+2] = bx2; out[o+3] = by2;
        out[o+4] = l[c] * inv;
    }
}

// ---------------- launcher ----------------
extern "C" void kernel_launch(void* const* d_in, const int* in_sizes, int n_in,
                              void* d_out, int out_size) {
    const float* images     = (const float*)d_in[0];
    const float* c0_w       = (const float*)d_in[1];
    const float* c0_b       = (const float*)d_in[2];
    const float* c1_w       = (const float*)d_in[3];
    const float* c1_b       = (const float*)d_in[4];
    const float* c2_w       = (const float*)d_in[5];
    const float* c2_b       = (const float*)d_in[6];
    const float* c3_w       = (const float*)d_in[7];
    const float* c3_b       = (const float*)d_in[8];
    const float* rpn_conv_w = (const float*)d_in[9];
    const float* rpn_conv_b = (const float*)d_in[10];
    const float* rpn_cls_w  = (const float*)d_in[11];
    const float* rpn_cls_b  = (const float*)d_in[12];
    const float* rpn_bbox_w = (const float*)d_in[13];
    const float* rpn_bbox_b = (const float*)d_in[14];
    const float* fc1_w      = (const float*)d_in[15];
    const float* fc1_b      = (const float*)d_in[16];
    const float* fc2_w      = (const float*)d_in[17];
    const float* fc2_b      = (const float*)d_in[18];
    const float* cls_w      = (const float*)d_in[19];
    const float* cls_b      = (const float*)d_in[20];
    const float* bbox_w     = (const float*)d_in[21];
    const float* bbox_b     = (const float*)d_in[22];
    float* out = (float*)d_out;

    float *p_c0, *p_pool, *p_c1, *p_c2, *p_feat, *p_rpn, *p_cpart, *p_obj, *p_bd;
    float *p_props, *p_scores, *p_rois, *p_part, *p_h2, *p_logits, *p_breg, *p_geow;
    int *p_topidx, *p_geoi;
    u16 *p_Ah, *p_B1h, *p_B2h, *p_h1h;
    cudaGetSymbolAddress((void**)&p_c0, g_c0);
    cudaGetSymbolAddress((void**)&p_pool, g_pool);
    cudaGetSymbolAddress((void**)&p_c1, g_c1);
    cudaGetSymbolAddress((void**)&p_c2, g_c2);
    cudaGetSymbolAddress((void**)&p_feat, g_feat);
    cudaGetSymbolAddress((void**)&p_rpn, g_rpn);
    cudaGetSymbolAddress((void**)&p_cpart, g_cpart);
    cudaGetSymbolAddress((void**)&p_obj, g_obj);
    cudaGetSymbolAddress((void**)&p_bd, g_bd);
    cudaGetSymbolAddress((void**)&p_props, g_props);
    cudaGetSymbolAddress((void**)&p_scores, g_scores);
    cudaGetSymbolAddress((void**)&p_topidx, g_topidx);
    cudaGetSymbolAddress((void**)&p_rois, g_rois);
    cudaGetSymbolAddress((void**)&p_geoi, g_geoi);
    cudaGetSymbolAddress((void**)&p_geow, g_geow);
    cudaGetSymbolAddress((void**)&p_Ah, g_Ah);
    cudaGetSymbolAddress((void**)&p_B1h, g_B1h);
    cudaGetSymbolAddress((void**)&p_B2h, g_B2h);
    cudaGetSymbolAddress((void**)&p_h1h, g_h1h);
    cudaGetSymbolAddress((void**)&p_part, g_part);
    cudaGetSymbolAddress((void**)&p_h2, g_h2);
    cudaGetSymbolAddress((void**)&p_logits, g_logits);
    cudaGetSymbolAddress((void**)&p_breg, g_breg);

    // backbone
    conv0v2_kernel<<<dim3(8,16,16), dim3(8,16)>>>(images, c0_w, c0_b, p_c0);
    maxpool_kernel<<<(64*128*128 + 255)/256, 256>>>(p_c0, p_pool);
    conv3x3t_kernel<2><<<dim3(4,4,32), 256>>>(p_pool, c1_w, c1_b, p_c1, p_cpart,
                                              64, 128, 64, 128, 2);
    creduce_kernel<<<(128*4096+255)/256, 256>>>(p_cpart, c1_b, p_c1, 4096, 2, 128*4096);
    conv3x3t_kernel<2><<<dim3(2,2,128), 256>>>(p_c1, c2_w, c2_b, p_c2, p_cpart,
                                               128, 64, 32, 256, 4);
    creduce_kernel<<<(256*1024+255)/256, 256>>>(p_cpart, c2_b, p_c2, 1024, 4, 256*1024);
    conv3x3t_kernel<2><<<dim3(1,1,512), 256>>>(p_c2, c3_w, c3_b, p_feat, p_cpart,
                                               256, 32, 16, 512, 8);
    creduce_kernel<<<(512*256+255)/256, 256>>>(p_cpart, c3_b, p_feat, 256, 8, 512*256);
    conv3x3t_kernel<1><<<dim3(1,1,512), 256>>>(p_feat, rpn_conv_w, rpn_conv_b, p_rpn, p_cpart,
                                               512, 16, 16, 512, 8);
    creduce_kernel<<<(512*256+255)/256, 256>>>(p_cpart, rpn_conv_b, p_rpn, 256, 8, 512*256);

    // RPN heads (merged)
    rpnheads_kernel<<<45, 256>>>(p_rpn, rpn_cls_w, rpn_cls_b, rpn_bbox_w, rpn_bbox_b, p_obj, p_bd);

    // proposals
    rpn_decode_kernel<<<9, 256>>>(p_obj, p_bd, p_props, p_scores);
    topk_kernel<<<1, 1024>>>(p_scores, p_topidx);
    gather_rois_kernel<<<4, 256>>>(p_props, p_topidx, p_rois);

    // roi align v3 -> fp16 A (rows 1000..1023 written as zeros via zero weights)
    roigeo_kernel<<<(1024*28 + 255)/256, 256>>>(p_rois, p_geoi, p_geow);
    roi_align3_kernel<<<dim3(32,16), 256>>>(p_feat, p_geoi, p_geow, p_Ah);

    // weight transpose -> fp16
    tsplit_kernel<<<dim3(1024/32, 25088/32), dim3(32,8)>>>(fc1_w, p_B1h, 25088, 1024);
    tsplit_kernel<<<dim3(1024/32, 1024/32),  dim3(32,8)>>>(fc2_w, p_B2h, 1024, 1024);

    // fc1: K=25088, z=16 -> stages 98
    gemm_fp16_kernel<<<dim3(8,8,16), 256>>>(p_Ah, p_B1h, p_part, 25088, 98);
    reduce1_kernel<<<(1024*1024)/256, 256>>>(p_part, fc1_b, p_h1h);

    // fc2: K=1024, z=4 -> stages 16
    gemm_fp16_kernel<<<dim3(8,8,4), 256>>>(p_h1h, p_B2h, p_part, 1024, 16);
    reduce2_kernel<<<(1024*1024)/256, 256>>>(p_part, fc2_b, p_h2);

    fc_small2_kernel<<<TOPN, 256>>>(p_h2, cls_w, cls_b, bbox_w, bbox_b, p_logits, p_breg);
    final_kernel<<<(TOPN + 127)/128, 128>>>(p_rois, p_logits, p_breg, out);
}

// round 12
// speedup vs baseline: 1.9260x; 1.0015x over previous
#include <cuda_runtime.h>
#include <cuda_fp16.h>
#include <math.h>
#include <stdint.h>

#define TOPN 1000
#define BBOX_CLAMP 4.135166556742356f
typedef unsigned short u16;

// ---------------- scratch (device globals) ----------------
__device__ float g_c0[64*256*256];
__device__ float g_pool[64*128*128];
__device__ float g_c1[128*64*64];
__device__ float g_c2[256*32*32];
__device__ float g_feat[512*16*16];
__device__ float g_rpn[512*16*16];
__device__ float g_cpart[1048576];
__device__ float g_obj[9*16*16];
__device__ float g_bd[36*16*16];
__device__ float g_props[2304*4];
__device__ float g_scores[2304];
__device__ int   g_topidx[TOPN];
__device__ float g_rois[TOPN*4];
__device__ int   g_geoi[1024*56];
__device__ float g_geow[1024*56];
__device__ u16 g_Ah[1024u*25088u];
__device__ u16 g_B1h[1024u*25088u];
__device__ u16 g_B2h[1024u*1024u];
__device__ u16 g_h1h[1024u*1024u];
__device__ float g_part[16u*1024u*1024u];
__device__ float g_h2[1024u*1024u];
__device__ float g_logits[TOPN*6];
__device__ float g_breg[TOPN*24];

// ---------------- conv0: smem-tiled 7x7 s2 ----------------
__global__ void conv0v2_kernel(const float* __restrict__ img,
                               const float* __restrict__ w,
                               const float* __restrict__ b,
                               float* __restrict__ out) {
    __shared__ float tile[3][37][72];
    __shared__ float ws[4][147];
    int tx = threadIdx.x, ty = threadIdx.y;
    int tid = ty*8 + tx;
    int oc0 = blockIdx.z * 4;
    int x0 = blockIdx.x * 32;
    int y0 = blockIdx.y * 16;
    int ixs = 2*x0 - 3, iys = 2*y0 - 3;
    const float mean[3] = {0.485f, 0.456f, 0.406f};
    const float istd[3] = {1.0f/0.229f, 1.0f/0.224f, 1.0f/0.225f};

    for (int i = tid; i < 3*37*72; i += 128) {
        int c = i / (37*72); int rem = i % (37*72);
        int iy = rem / 72, ix = rem % 72;
        int gy = iys + iy, gx = ixs + ix;
        float v = 0.0f;
        if (gy >= 0 && gy < 512 && gx >= 0 && gx < 512 && ix < 69)
            v = (img[(c*512 + gy)*512 + gx] - mean[c]) * istd[c];
        tile[c][iy][ix] = v;
    }
    for (int i = tid; i < 4*147; i += 128)
        ws[i/147][i%147] = w[(size_t)(oc0 + i/147)*147 + i%147];
    __syncthreads();

    float acc[4][4];
    #pragma unroll
    for (int oc = 0; oc < 4; oc++) {
        float bb = b[oc0+oc];
        #pragma unroll
        for (int xo = 0; xo < 4; xo++) acc[oc][xo] = bb;
    }
    for (int c = 0; c < 3; c++) {
        #pragma unroll
        for (int ky = 0; ky < 7; ky++) {
            const float* row = tile[c][2*ty + ky];
            float v[13];
            #pragma unroll
            for (int j = 0; j < 13; j++) v[j] = row[8*tx + j];
            #pragma unroll
            for (int kx = 0; kx < 7; kx++) {
                float w0 = ws[0][c*49 + ky*7 + kx];
                float w1 = ws[1][c*49 + ky*7 + kx];
                float w2 = ws[2][c*49 + ky*7 + kx];
                float w3 = ws[3][c*49 + ky*7 + kx];
                #pragma unroll
                for (int xo = 0; xo < 4; xo++) {
                    float vv = v[2*xo + kx];
                    acc[0][xo] = fmaf(vv, w0, acc[0][xo]);
                    acc[1][xo] = fmaf(vv, w1, acc[1][xo]);
                    acc[2][xo] = fmaf(vv, w2, acc[2][xo]);
                    acc[3][xo] = fmaf(vv, w3, acc[3][xo]);
                }
            }
        }
    }
    int y = y0 + ty;
    #pragma unroll
    for (int oc = 0; oc < 4; oc++)
        #pragma unroll
        for (int xo = 0; xo < 4; xo++)
            out[(size_t)(oc0+oc)*65536 + y*256 + x0 + tx*4 + xo] = fmaxf(acc[oc][xo], 0.0f);
}

// ---------------- maxpool 3x3 s2 p1 ----------------
__global__ void maxpool_kernel(const float* __restrict__ in, float* __restrict__ out) {
    int idx = blockIdx.x * 256 + threadIdx.x;
    if (idx >= 64*128*128) return;
    int x = idx & 127;
    int y = (idx >> 7) & 127;
    int c = idx >> 14;
    float m = -INFINITY;
    #pragma unroll
    for (int dy = 0; dy < 3; dy++) {
        int iy = 2*y - 1 + dy;
        if (iy < 0 || iy >= 256) continue;
        #pragma unroll
        for (int dx = 0; dx < 3; dx++) {
            int ix = 2*x - 1 + dx;
            if (ix < 0 || ix >= 256) continue;
            m = fmaxf(m, in[(c*256 + iy)*256 + ix]);
        }
    }
    out[idx] = m;
}

// ---------------- 3x3 conv: templated stride, CCH=8 ----------------
#define CCH 8
template<int STRIDE>
__global__ void __launch_bounds__(256)
conv3x3t_kernel(const float* __restrict__ in, const float* __restrict__ w,
                const float* __restrict__ bias,
                float* __restrict__ out, float* __restrict__ partial,
                int Cin, int Hin, int Hout, int Cout, int cs) {
    constexpr int TH  = STRIDE*15 + 3;
    constexpr int TWP = (STRIDE == 2) ? 36 : 20;
    constexpr int TSZ = TH * TWP;
    __shared__ float tile[CCH*TSZ];
    __shared__ float ws[8*CCH*9];
    int nocg = Cout >> 3;
    int ocg = blockIdx.z % nocg, slice = blockIdx.z / nocg;
    int oc0 = ocg * 8;
    int tid = threadIdx.x;
    int tx = tid & 15, ty = tid >> 4;
    int x0 = blockIdx.x * 16, y0 = blockIdx.y * 16;
    int iys = y0*STRIDE - 1, ixs = x0*STRIDE - 1;
    int cps = Cin / cs;
    int cbeg = slice * cps;

    float acc[8];
    #pragma unroll
    for (int oc = 0; oc < 8; oc++) acc[oc] = 0.0f;

    for (int c0 = 0; c0 < cps; c0 += CCH) {
        __syncthreads();
        #pragma unroll 4
        for (int i = tid; i < CCH*TSZ; i += 256) {
            int c = i / TSZ;
            int rem = i - c*TSZ;
            int r = rem / TWP, col = rem - r*TWP;
            int gy = iys + r, gx = ixs + col;
            float v = 0.0f;
            if (col < TH && gy >= 0 && gy < Hin && gx >= 0 && gx < Hin)
                v = in[(size_t)(cbeg + c0 + c)*Hin*Hin + gy*Hin + gx];
            tile[i] = v;
        }
        for (int i = tid; i < 8*CCH*9; i += 256) {
            int oc = i / (CCH*9);
            int rem = i - oc*CCH*9;
            int c = rem / 9, k = rem - c*9;
            ws[i] = w[(size_t)(oc0 + oc)*Cin*9 + (size_t)(cbeg + c0 + c)*9 + k];
        }
        __syncthreads();
        #pragma unroll
        for (int cl = 0; cl < CCH; cl++) {
            const float* tb = tile + cl*TSZ;
            float v[9];
            #pragma unroll
            for (int ky = 0; ky < 3; ky++)
                #pragma unroll
                for (int kx = 0; kx < 3; kx++)
                    v[ky*3+kx] = tb[(STRIDE*ty + ky)*TWP + STRIDE*tx + kx];
            const float* wp = ws + cl*9;
            #pragma unroll
            for (int oc = 0; oc < 8; oc++)
                #pragma unroll
                for (int k = 0; k < 9; k++)
                    acc[oc] = fmaf(v[k], wp[oc*CCH*9 + k], acc[oc]);
        }
    }

    size_t HW = (size_t)Hout*Hout;
    size_t pix = (size_t)(y0 + ty)*Hout + x0 + tx;
    if (cs == 1) {
        #pragma unroll
        for (int oc = 0; oc < 8; oc++)
            out[(size_t)(oc0+oc)*HW + pix] = fmaxf(acc[oc] + bias[oc0+oc], 0.0f);
    } else {
        #pragma unroll
        for (int oc = 0; oc < 8; oc++)
            partial[(size_t)slice*Cout*HW + (size_t)(oc0+oc)*HW + pix] = acc[oc];
    }
}

// reduce conv partials -> bias + relu
__global__ void creduce_kernel(const float* __restrict__ partial,
                               const float* __restrict__ bias,
                               float* __restrict__ out, int HW, int ns, int total) {
    int idx = blockIdx.x * 256 + threadIdx.x;
    if (idx >= total) return;
    int oc = idx / HW;
    float s = bias[oc];
    for (int i = 0; i < ns; i++) s += partial[(size_t)i*total + idx];
    out[idx] = fmaxf(s, 0.0f);
}

// ---------------- merged RPN 1x1 heads ----------------
__global__ void rpnheads_kernel(const float* __restrict__ in,
                                const float* __restrict__ clsw, const float* __restrict__ clsb,
                                const float* __restrict__ bbw, const float* __restrict__ bbb,
                                float* __restrict__ obj, float* __restrict__ bd) {
    int o = blockIdx.x;
    int p = threadIdx.x;
    const float* w;
    float acc;
    if (o < 9) { w = clsw + o*512; acc = clsb[o]; }
    else       { w = bbw + (o-9)*512; acc = bbb[o-9]; }
    for (int c = 0; c < 512; c++)
        acc = fmaf(in[c*256 + p], w[c], acc);
    if (o < 9) obj[o*256 + p] = acc;
    else       bd[(o-9)*256 + p] = acc;
}

// ---------------- RPN decode ----------------
__global__ void rpn_decode_kernel(const float* __restrict__ obj,
                                  const float* __restrict__ bd,
                                  float* __restrict__ props,
                                  float* __restrict__ scores) {
    int i = blockIdx.x * 256 + threadIdx.x;
    if (i >= 2304) return;
    int a = i % 9;
    int cell = i / 9;
    int wq = cell % 16;
    int hq = cell / 16;
    int pix = hq*16 + wq;
    scores[i] = obj[a*256 + pix];

    const float ratios[3] = {0.5f, 1.0f, 2.0f};
    int r = a / 3, s = a % 3;
    float scale = 128.0f * (float)(1 << s);
    float hr = sqrtf(ratios[r]);
    float wr = 1.0f / hr;
    float hw = rintf(wr * scale * 0.5f);
    float hh = rintf(hr * scale * 0.5f);
    float sx = (float)(wq * 32), sy = (float)(hq * 32);
    float W = 2.0f*hw, H = 2.0f*hh;
    float cx = sx, cy = sy;

    float dx = bd[(a*4+0)*256 + pix];
    float dy = bd[(a*4+1)*256 + pix];
    float dw = fminf(bd[(a*4+2)*256 + pix], BBOX_CLAMP);
    float dh = fminf(bd[(a*4+3)*256 + pix], BBOX_CLAMP);
    float pcx = dx*W + cx, pcy = dy*H + cy;
    float pw = expf(dw)*W, ph = expf(dh)*H;
    props[i*4+0] = pcx - 0.5f*pw;
    props[i*4+1] = pcy - 0.5f*ph;
    props[i*4+2] = pcx + 0.5f*pw;
    props[i*4+3] = pcy + 0.5f*ph;
}

// ---------------- top-k bitonic ----------------
__device__ __forceinline__ bool tk_lt(float sa, int ia, float sb, int ib) {
    return (sa > sb) || (sa == sb && ia < ib);
}
__global__ void topk_kernel(const float* __restrict__ scores, int* __restrict__ topidx) {
    __shared__ float s[4096];
    __shared__ int   ind[4096];
    int tid = threadIdx.x;
    for (int i = tid; i < 4096; i += 1024) {
        s[i] = (i < 2304) ? scores[i] : -INFINITY;
        ind[i] = i;
    }
    __syncthreads();
    for (int k = 2; k <= 4096; k <<= 1) {
        for (int j = k >> 1; j > 0; j >>= 1) {
            for (int base = 0; base < 4096; base += 1024) {
                int i = base + tid;
                int ixj = i ^ j;
                if (ixj > i) {
                    bool up = ((i & k) == 0);
                    float si = s[i], sj = s[ixj];
                    int ii = ind[i], ij = ind[ixj];
                    bool swp = up ? tk_lt(sj, ij, si, ii) : tk_lt(si, ii, sj, ij);
                    if (swp) { s[i] = sj; s[ixj] = si; ind[i] = ij; ind[ixj] = ii; }
                }
            }
            __syncthreads();
        }
    }
    for (int i = tid; i < TOPN; i += 1024) topidx[i] = ind[i];
}

__global__ void gather_rois_kernel(const float* __restrict__ props,
                                   const int* __restrict__ topidx,
                                   float* __restrict__ rois) {
    int i = blockIdx.x * 256 + threadIdx.x;
    if (i >= TOPN) return;
    int idx = topidx[i];
    #pragma unroll
    for (int k = 0; k < 4; k++)
        rois[i*4+k] = fminf(fmaxf(props[idx*4+k], 0.0f), 512.0f);
}

// ---------------- roi geometry precompute ----------------
__global__ void roigeo_kernel(const float* __restrict__ rois,
                              int* __restrict__ geoi, float* __restrict__ geow) {
    int t = blockIdx.x * 256 + threadIdx.x;
    if (t >= 1024*28) return;
    int rr = t / 28, i = t % 28;
    int ii = i % 14;
    bool isY = i >= 14;
    int pp = ii >> 1, sl = (ii & 1) * 2;
    int base = rr*56 + (isY ? 28 : 0) + pp*4 + sl;
    if (rr >= TOPN) {
        geoi[base] = 0; geoi[base+1] = 0;
        geow[base] = 0.0f; geow[base+1] = 0.0f;
        return;
    }
    float c1 = rois[rr*4 + (isY ? 1 : 0)];
    float c2 = rois[rr*4 + (isY ? 3 : 2)];
    float lo = c1 * (1.0f/32.0f);
    float hi = c2 * (1.0f/32.0f);
    float sz = fmaxf(hi - lo, 1.0f);
    float g = ((float)ii + 0.5f) / 14.0f;
    float p = fminf(fmaxf(lo + g*sz, 0.0f), 15.0f);
    int p0 = (int)floorf(p);
    int p1 = min(p0 + 1, 15);
    float l = p - (float)p0;
    geoi[base] = p0; geoi[base+1] = p1;
    geow[base] = 0.5f * (1.0f - l); geow[base+1] = 0.5f * l;
}

// ---------------- ROI align v3 ----------------
__global__ void __launch_bounds__(256)
roi_align3_kernel(const float* __restrict__ feat,
                  const int* __restrict__ geoi, const float* __restrict__ geow,
                  u16* __restrict__ Ah) {
    __shared__ float ftile[16*256];
    __shared__ int   si[64*56];
    __shared__ float sw[64*56];
    int cg = blockIdx.x;
    int chunk = blockIdx.y;
    int tid = threadIdx.x;
    {
        const float4* src = (const float4*)(feat + (size_t)cg*16*256);
        float4* dst = (float4*)ftile;
        for (int i = tid; i < 1024; i += 256) dst[i] = src[i];
    }
    int gbase = chunk*64*56;
    for (int i = tid; i < 64*56; i += 256) {
        si[i] = geoi[gbase + i];
        sw[i] = geow[gbase + i];
    }
    __syncthreads();

    for (int rl = 0; rl < 64; rl++) {
        int rr = chunk*64 + rl;
        const int* gi = si + rl*56;
        const float* gw = sw + rl*56;
        for (int t = tid; t < 784; t += 256) {
            int cl = t / 49, p = t % 49;
            int py = p / 7, px = p % 7;
            const float* f = ftile + cl*256;
            float acc = 0.0f;
            #pragma unroll
            for (int a = 0; a < 4; a++) {
                const float* frow = f + gi[28 + py*4 + a]*16;
                float s = 0.0f;
                #pragma unroll
                for (int bb = 0; bb < 4; bb++)
                    s = fmaf(gw[px*4 + bb], frow[gi[px*4 + bb]], s);
                acc = fmaf(gw[28 + py*4 + a], s, acc);
            }
            __half h = __float2half_rn(acc);
            Ah[(size_t)rr*25088 + (size_t)(cg*16 + cl)*49 + p] = *(u16*)&h;
        }
    }
}

// ---------------- transpose + fp16 weights ----------------
__global__ void tsplit_kernel(const float* __restrict__ W,
                              u16* __restrict__ Th, int K, int N) {
    __shared__ float t[32][33];
    int n0 = blockIdx.x * 32, k0 = blockIdx.y * 32;
    int tx = threadIdx.x, ty = threadIdx.y;
    #pragma unroll
    for (int i = 0; i < 4; i++)
        t[ty + 8*i][tx] = W[(size_t)(k0 + ty + 8*i)*N + n0 + tx];
    __syncthreads();
    #pragma unroll
    for (int i = 0; i < 4; i++) {
        __half h = __float2half_rn(t[tx][ty + 8*i]);
        Th[(size_t)(n0 + ty + 8*i)*K + k0 + tx] = *(u16*)&h;
    }
}

// ---------------- single-pass fp16 tensor-core GEMM ----------------
__device__ __forceinline__ void mma16816_f32(float& d0, float& d1, float& d2, float& d3,
                                             uint32_t a0, uint32_t a1, uint32_t a2, uint32_t a3,
                                             uint32_t b0, uint32_t b1) {
    asm volatile("mma.sync.aligned.m16n8k16.row.col.f32.f16.f16.f32 "
                 "{%0,%1,%2,%3}, {%4,%5,%6,%7}, {%8,%9}, {%0,%1,%2,%3};\n"
                 : "+f"(d0), "+f"(d1), "+f"(d2), "+f"(d3)
                 : "r"(a0), "r"(a1), "r"(a2), "r"(a3), "r"(b0), "r"(b1));
}
__device__ __forceinline__ void cpasync16(uint32_t dst, const void* src) {
    asm volatile("cp.async.cg.shared.global [%0], [%1], 16;\n" :: "r"(dst), "l"(src));
}
__device__ __forceinline__ void ldsm_x4(uint32_t& r0, uint32_t& r1, uint32_t& r2, uint32_t& r3,
                                        uint32_t addr) {
    asm volatile("ldmatrix.sync.aligned.m8n8.x4.shared.b16 {%0,%1,%2,%3}, [%4];\n"
                 : "=r"(r0), "=r"(r1), "=r"(r2), "=r"(r3) : "r"(addr));
}

#define LDK 24

__global__ void __launch_bounds__(256)
gemm_fp16_kernel(const u16* __restrict__ A, const u16* __restrict__ B,
                 float* __restrict__ part, int K, int stages) {
    __shared__ __align__(16) u16 sm[2][2][128*LDK];
    int tid = threadIdx.x;
    int wid = tid >> 5, lane = tid & 31;
    int wm = (wid & 1) * 64;
    int wn = (wid >> 1) * 32;
    int g = lane >> 2, tig = lane & 3;
    int r8 = lane & 7, q = lane >> 3;
    int bm = blockIdx.y * 128, bn = blockIdx.x * 128;
    int kbase = blockIdx.z * stages * 16;

    float acc[16][4];
    #pragma unroll
    for (int i = 0; i < 16; i++)
        #pragma unroll
        for (int j = 0; j < 4; j++) acc[i][j] = 0.0f;

    uint32_t smb = (uint32_t)__cvta_generic_to_shared(&sm[0][0][0]);
    const uint32_t MAT = 128*LDK*2;
    const uint32_t BUF = 2*MAT;
    uint32_t offA = (uint32_t)(((wm + (q & 1)*8 + r8)*LDK + (q >> 1)*8) * 2);
    uint32_t offB = (uint32_t)(((wn + (q >> 1)*8 + r8)*LDK + (q & 1)*8) * 2);

    auto load_stage = [&](int buf, int s) {
        int kpos0 = kbase + s * 16;
        #pragma unroll
        for (int l = 0; l < 2; l++) {
            int idx = l * 256 + tid;
            int pl = idx >> 8;
            int rr = (idx & 255) >> 1;
            int half = idx & 1;
            const u16* src = (pl ? B + (size_t)(bn + rr)*K : A + (size_t)(bm + rr)*K)
                             + kpos0 + half*8;
            uint32_t dst = (uint32_t)__cvta_generic_to_shared(&sm[buf][pl][rr*LDK + half*8]);
            cpasync16(dst, src);
        }
        asm volatile("cp.async.commit_group;\n");
    };

    load_stage(0, 0);

    for (int s = 0; s < stages; s++) {
        if (s + 1 < stages) {
            load_stage((s + 1) & 1, s + 1);
            asm volatile("cp.async.wait_group 1;\n");
        } else {
            asm volatile("cp.async.wait_group 0;\n");
        }
        __syncthreads();
        uint32_t base = smb + (uint32_t)(s & 1)*BUF;
        uint32_t aA = base + offA;
        uint32_t aB = base + MAT + offB;

        uint32_t bh[4][2], ah[4][4];
        #pragma unroll
        for (int p = 0; p < 2; p++)
            ldsm_x4(bh[2*p][0], bh[2*p][1], bh[2*p+1][0], bh[2*p+1][1], aB + p*16*LDK*2);
        #pragma unroll
        for (int mi = 0; mi < 4; mi++)
            ldsm_x4(ah[mi][0], ah[mi][1], ah[mi][2], ah[mi][3], aA + mi*16*LDK*2);

        #pragma unroll
        for (int mi = 0; mi < 4; mi++)
            #pragma unroll
            for (int ni = 0; ni < 4; ni++) {
                float* d = acc[mi*4 + ni];
                mma16816_f32(d[0], d[1], d[2], d[3],
                             ah[mi][0], ah[mi][1], ah[mi][2], ah[mi][3], bh[ni][0], bh[ni][1]);
            }
        __syncthreads();
    }

    float* cbase = part + ((size_t)blockIdx.z << 20);
    #pragma unroll
    for (int mi = 0; mi < 4; mi++) {
        #pragma unroll
        for (int ni = 0; ni < 4; ni++) {
            int row = bm + wm + mi*16 + g;
            int col = bn + wn + ni*8 + 2*tig;
            float* d = acc[mi*4 + ni];
            *(float2*)&cbase[(size_t)row*1024 + col]     = make_float2(d[0], d[1]);
            *(float2*)&cbase[(size_t)(row+8)*1024 + col] = make_float2(d[2], d[3]);
        }
    }
}

// reduce fc1 partials -> relu -> fp16 h1
__global__ void reduce1_kernel(const float* __restrict__ part,
                               const float* __restrict__ bias,
                               u16* __restrict__ Hh) {
    size_t idx = (size_t)blockIdx.x * 256 + threadIdx.x;
    int n = (int)(idx & 1023);
    float s = bias[n];
    #pragma unroll
    for (int i = 0; i < 16; i++) s += part[((size_t)i << 20) + idx];
    s = fmaxf(s, 0.0f);
    __half h = __float2half_rn(s);
    Hh[idx] = *(u16*)&h;
}

// reduce fc2 partials -> relu -> f32 h2
__global__ void reduce2_kernel(const float* __restrict__ part,
                               const float* __restrict__ bias,
                               float* __restrict__ H) {
    size_t idx = (size_t)blockIdx.x * 256 + threadIdx.x;
    int n = (int)(idx & 1023);
    float s = bias[n];
    #pragma unroll
    for (int i = 0; i < 4; i++) s += part[((size_t)i << 20) + idx];
    H[idx] = fmaxf(s, 0.0f);
}

// ---------------- cls + bbox heads: block per roi ----------------
__global__ void __launch_bounds__(256)
fc_small2_kernel(const float* __restrict__ h,
                 const float* __restrict__ clsw, const float* __restrict__ clsb,
                 const float* __restrict__ bbw, const float* __restrict__ bbb,
                 float* __restrict__ logits, float* __restrict__ breg) {
    __shared__ float hs[1024];
    int r = blockIdx.x;
    int tid = threadIdx.x;
    const float* hp = h + (size_t)r*1024;
    for (int i = tid; i < 1024; i += 256) hs[i] = hp[i];
    __syncthreads();
    if (tid < 240) {
        int j = tid >> 3, part = tid & 7;
        float acc = 0.0f;
        if (j < 6) {
            for (int k = part; k < 1024; k += 8)
                acc = fmaf(hs[k], clsw[k*6 + j], acc);
        } else {
            int q = j - 6;
            for (int k = part; k < 1024; k += 8)
                acc = fmaf(hs[k], bbw[k*24 + q], acc);
        }
        #pragma unroll
        for (int off = 4; off; off >>= 1)
            acc += __shfl_down_sync(0xffffffff, acc, off);
        if (part == 0) {
            if (j < 6) logits[r*6 + j] = acc + clsb[j];
            else       breg[r*24 + (j-6)] = acc + bbb[j-6];
        }
    }
}

// ---------------- final ----------------
__global__ void final_kernel(const float* __restrict__ rois,
                             const float* __restrict__ logits,
                             const float* __restrict__ breg,
                             float* __restrict__ out) {
    int r = blockIdx.x * 128 + threadIdx.x;
    if (r >= TOPN) return;
    float l[6];
    float m = -INFINITY;
    #pragma unroll
    for (int i = 0; i < 6; i++) { l[i] = logits[r*6 + i]; m = fmaxf(m, l[i]); }
    float ssum = 0.0f;
    #pragma unroll
    for (int i = 0; i < 6; i++) { l[i] = expf(l[i] - m); ssum += l[i]; }
    float inv = 1.0f / ssum;

    float x1 = rois[r*4+0], y1 = rois[r*4+1], x2 = rois[r*4+2], y2 = rois[r*4+3];
    float W = x2 - x1, H = y2 - y1;
    float cx = x1 + 0.5f*W, cy = y1 + 0.5f*H;
    #pragma unroll
    for (int c = 1; c < 6; c++) {
        float dx = breg[r*24 + c*4+0] / 10.0f;
        float dy = breg[r*24 + c*4+1] / 10.0f;
        float dw = fminf(breg[r*24 + c*4+2] / 5.0f, BBOX_CLAMP);
        float dh = fminf(breg[r*24 + c*4+3] / 5.0f, BBOX_CLAMP);
        float pcx = dx*W + cx, pcy = dy*H + cy;
        float pw = expf(dw)*W, ph = expf(dh)*H;
        float bx1 = fminf(fmaxf(pcx - 0.5f*pw, 0.0f), 512.0f);
        float by1 = fminf(fmaxf(pcy - 0.5f*ph, 0.0f), 512.0f);
        float bx2 = fminf(fmaxf(pcx + 0.5f*pw, 0.0f), 512.0f);
        float by2 = fminf(fmaxf(pcy + 0.5f*ph, 0.0f), 512.0f);
        int o = r*25 + (c-1)*5;
        out[o+0] = bx1; out[o+1] = by1; out[o+2] = bx2; out[o+3] = by2;
        out[o+4] = l[c] * inv;
    }
}

// ---------------- launcher ----------------
extern "C" void kernel_launch(void* const* d_in, const int* in_sizes, int n_in,
                              void* d_out, int out_size) {
    const float* images     = (const float*)d_in[0];
    const float* c0_w       = (const float*)d_in[1];
    const float* c0_b       = (const float*)d_in[2];
    const float* c1_w       = (const float*)d_in[3];
    const float* c1_b       = (const float*)d_in[4];
    const float* c2_w       = (const float*)d_in[5];
    const float* c2_b       = (const float*)d_in[6];
    const float* c3_w       = (const float*)d_in[7];
    const float* c3_b       = (const float*)d_in[8];
    const float* rpn_conv_w = (const float*)d_in[9];
    const float* rpn_conv_b = (const float*)d_in[10];
    const float* rpn_cls_w  = (const float*)d_in[11];
    const float* rpn_cls_b  = (const float*)d_in[12];
    const float* rpn_bbox_w = (const float*)d_in[13];
    const float* rpn_bbox_b = (const float*)d_in[14];
    const float* fc1_w      = (const float*)d_in[15];
    const float* fc1_b      = (const float*)d_in[16];
    const float* fc2_w      = (const float*)d_in[17];
    const float* fc2_b      = (const float*)d_in[18];
    const float* cls_w      = (const float*)d_in[19];
    const float* cls_b      = (const float*)d_in[20];
    const float* bbox_w     = (const float*)d_in[21];
    const float* bbox_b     = (const float*)d_in[22];
    float* out = (float*)d_out;

    float *p_c0, *p_pool, *p_c1, *p_c2, *p_feat, *p_rpn, *p_cpart, *p_obj, *p_bd;
    float *p_props, *p_scores, *p_rois, *p_part, *p_h2, *p_logits, *p_breg, *p_geow;
    int *p_topidx, *p_geoi;
    u16 *p_Ah, *p_B1h, *p_B2h, *p_h1h;
    cudaGetSymbolAddress((void**)&p_c0, g_c0);
    cudaGetSymbolAddress((void**)&p_pool, g_pool);
    cudaGetSymbolAddress((void**)&p_c1, g_c1);
    cudaGetSymbolAddress((void**)&p_c2, g_c2);
    cudaGetSymbolAddress((void**)&p_feat, g_feat);
    cudaGetSymbolAddress((void**)&p_rpn, g_rpn);
    cudaGetSymbolAddress((void**)&p_cpart, g_cpart);
    cudaGetSymbolAddress((void**)&p_obj, g_obj);
    cudaGetSymbolAddress((void**)&p_bd, g_bd);
    cudaGetSymbolAddress((void**)&p_props, g_props);
    cudaGetSymbolAddress((void**)&p_scores, g_scores);
    cudaGetSymbolAddress((void**)&p_topidx, g_topidx);
    cudaGetSymbolAddress((void**)&p_rois, g_rois);
    cudaGetSymbolAddress((void**)&p_geoi, g_geoi);
    cudaGetSymbolAddress((void**)&p_geow, g_geow);
    cudaGetSymbolAddress((void**)&p_Ah, g_Ah);
    cudaGetSymbolAddress((void**)&p_B1h, g_B1h);
    cudaGetSymbolAddress((void**)&p_B2h, g_B2h);
    cudaGetSymbolAddress((void**)&p_h1h, g_h1h);
    cudaGetSymbolAddress((void**)&p_part, g_part);
    cudaGetSymbolAddress((void**)&p_h2, g_h2);
    cudaGetSymbolAddress((void**)&p_logits, g_logits);
    cudaGetSymbolAddress((void**)&p_breg, g_breg);

    // second stream for independent weight transpose (created once, outside capture:
    // first call is the uncaptured correctness run)
    static cudaStream_t s2 = 0;
    static cudaEvent_t evF = 0, evJ = 0;
    if (!s2) {
        cudaStreamCreateWithFlags(&s2, cudaStreamNonBlocking);
        cudaEventCreateWithFlags(&evF, cudaEventDisableTiming);
        cudaEventCreateWithFlags(&evJ, cudaEventDisableTiming);
    }

    // fork: tsplits run concurrently with the backbone
    cudaEventRecord(evF, 0);
    cudaStreamWaitEvent(s2, evF, 0);
    tsplit_kernel<<<dim3(1024/32, 25088/32), dim3(32,8), 0, s2>>>(fc1_w, p_B1h, 25088, 1024);
    tsplit_kernel<<<dim3(1024/32, 1024/32),  dim3(32,8), 0, s2>>>(fc2_w, p_B2h, 1024, 1024);
    cudaEventRecord(evJ, s2);

    // backbone
    conv0v2_kernel<<<dim3(8,16,16), dim3(8,16)>>>(images, c0_w, c0_b, p_c0);
    maxpool_kernel<<<(64*128*128 + 255)/256, 256>>>(p_c0, p_pool);
    conv3x3t_kernel<2><<<dim3(4,4,32), 256>>>(p_pool, c1_w, c1_b, p_c1, p_cpart,
                                              64, 128, 64, 128, 2);
    creduce_kernel<<<(128*4096+255)/256, 256>>>(p_cpart, c1_b, p_c1, 4096, 2, 128*4096);
    conv3x3t_kernel<2><<<dim3(2,2,128), 256>>>(p_c1, c2_w, c2_b, p_c2, p_cpart,
                                               128, 64, 32, 256, 4);
    creduce_kernel<<<(256*1024+255)/256, 256>>>(p_cpart, c2_b, p_c2, 1024, 4, 256*1024);
    conv3x3t_kernel<2><<<dim3(1,1,512), 256>>>(p_c2, c3_w, c3_b, p_feat, p_cpart,
                                               256, 32, 16, 512, 8);
    creduce_kernel<<<(512*256+255)/256, 256>>>(p_cpart, c3_b, p_feat, 256, 8, 512*256);
    conv3x3t_kernel<1><<<dim3(1,1,512), 256>>>(p_feat, rpn_conv_w, rpn_conv_b, p_rpn, p_cpart,
                                               512, 16, 16, 512, 8);
    creduce_kernel<<<(512*256+255)/256, 256>>>(p_cpart, rpn_conv_b, p_rpn, 256, 8, 512*256);

    // RPN heads (merged)
    rpnheads_kernel<<<45, 256>>>(p_rpn, rpn_cls_w, rpn_cls_b, rpn_bbox_w, rpn_bbox_b, p_obj, p_bd);

    // proposals
    rpn_decode_kernel<<<9, 256>>>(p_obj, p_bd, p_props, p_scores);
    topk_kernel<<<1, 1024>>>(p_scores, p_topidx);
    gather_rois_kernel<<<4, 256>>>(p_props, p_topidx, p_rois);

    // roi align v3 -> fp16 A
    roigeo_kernel<<<(1024*28 + 255)/256, 256>>>(p_rois, p_geoi, p_geow);
    roi_align3_kernel<<<dim3(32,16), 256>>>(p_feat, p_geoi, p_geow, p_Ah);

    // join: weights ready before fc1
    cudaStreamWaitEvent(0, evJ, 0);

    // fc1: K=25088, z=16 -> stages 98
    gemm_fp16_kernel<<<dim3(8,8,16), 256>>>(p_Ah, p_B1h, p_part, 25088, 98);
    reduce1_kernel<<<(1024*1024)/256, 256>>>(p_part, fc1_b, p_h1h);

    // fc2: K=1024, z=4 -> stages 16
    gemm_fp16_kernel<<<dim3(8,8,4), 256>>>(p_h1h, p_B2h, p_part, 1024, 16);
    reduce2_kernel<<<(1024*1024)/256, 256>>>(p_part, fc2_b, p_h2);

    fc_small2_kernel<<<TOPN, 256>>>(p_h2, cls_w, cls_b, bbox_w, bbox_b, p_logits, p_breg);
    final_kernel<<<(TOPN + 127)/128, 128>>>(p_rois, p_logits, p_breg, out);
}

// round 13
// speedup vs baseline: 2.2391x; 1.1626x over previous
#include <cuda_runtime.h>
#include <cuda_fp16.h>
#include <math.h>
#include <stdint.h>

#define TOPN 1000
#define BBOX_CLAMP 4.135166556742356f
#define LOSCALE 2048.0f
#define INVLOSCALE (1.0f/2048.0f)
typedef unsigned short u16;

// ---------------- scratch (device globals) ----------------
__device__ float g_c0[64*256*256];
__device__ float g_pool[64*128*128];
__device__ float g_c1[128*64*64];
__device__ float g_c2[256*32*32];
__device__ float g_feat[512*16*16];
__device__ float g_rpn[512*16*16];
__device__ float g_obj[9*16*16];
__device__ float g_bd[36*16*16];
__device__ float g_props[2304*4];
__device__ float g_scores[2304];
__device__ int   g_topidx[TOPN];
__device__ float g_rois[TOPN*4];
__device__ int   g_geoi[1024*56];
__device__ float g_geow[1024*56];
__device__ u16 g_cAh[4096*576];    // conv im2col hi (max M*K = 2.36M)
__device__ u16 g_cAl[4096*576];
__device__ u16 g_cBh[512*4608];    // conv weight hi (max N*K = 2.36M)
__device__ u16 g_cBl[512*4608];
__device__ u16 g_Ah[1024u*25088u];
__device__ u16 g_B1h[1024u*25088u];
__device__ u16 g_B2h[1024u*1024u];
__device__ u16 g_h1h[1024u*1024u];
__device__ float g_part[16u*1024u*1024u];
__device__ float g_h2[1024u*1024u];
__device__ float g_logits[TOPN*6];
__device__ float g_breg[TOPN*24];

__device__ __forceinline__ void split16(float v, u16& hi, u16& lo) {
    __half h = __float2half_rn(v);
    float res = (v - __half2float(h)) * LOSCALE;
    __half l = __float2half_rn(res);
    hi = *(u16*)&h;
    lo = *(u16*)&l;
}

// ---------------- conv0: smem-tiled 7x7 s2 ----------------
__global__ void conv0v2_kernel(const float* __restrict__ img,
                               const float* __restrict__ w,
                               const float* __restrict__ b,
                               float* __restrict__ out) {
    __shared__ float tile[3][37][72];
    __shared__ float ws[4][147];
    int tx = threadIdx.x, ty = threadIdx.y;
    int tid = ty*8 + tx;
    int oc0 = blockIdx.z * 4;
    int x0 = blockIdx.x * 32;
    int y0 = blockIdx.y * 16;
    int ixs = 2*x0 - 3, iys = 2*y0 - 3;
    const float mean[3] = {0.485f, 0.456f, 0.406f};
    const float istd[3] = {1.0f/0.229f, 1.0f/0.224f, 1.0f/0.225f};

    for (int i = tid; i < 3*37*72; i += 128) {
        int c = i / (37*72); int rem = i % (37*72);
        int iy = rem / 72, ix = rem % 72;
        int gy = iys + iy, gx = ixs + ix;
        float v = 0.0f;
        if (gy >= 0 && gy < 512 && gx >= 0 && gx < 512 && ix < 69)
            v = (img[(c*512 + gy)*512 + gx] - mean[c]) * istd[c];
        tile[c][iy][ix] = v;
    }
    for (int i = tid; i < 4*147; i += 128)
        ws[i/147][i%147] = w[(size_t)(oc0 + i/147)*147 + i%147];
    __syncthreads();

    float acc[4][4];
    #pragma unroll
    for (int oc = 0; oc < 4; oc++) {
        float bb = b[oc0+oc];
        #pragma unroll
        for (int xo = 0; xo < 4; xo++) acc[oc][xo] = bb;
    }
    for (int c = 0; c < 3; c++) {
        #pragma unroll
        for (int ky = 0; ky < 7; ky++) {
            const float* row = tile[c][2*ty + ky];
            float v[13];
            #pragma unroll
            for (int j = 0; j < 13; j++) v[j] = row[8*tx + j];
            #pragma unroll
            for (int kx = 0; kx < 7; kx++) {
                float w0 = ws[0][c*49 + ky*7 + kx];
                float w1 = ws[1][c*49 + ky*7 + kx];
                float w2 = ws[2][c*49 + ky*7 + kx];
                float w3 = ws[3][c*49 + ky*7 + kx];
                #pragma unroll
                for (int xo = 0; xo < 4; xo++) {
                    float vv = v[2*xo + kx];
                    acc[0][xo] = fmaf(vv, w0, acc[0][xo]);
                    acc[1][xo] = fmaf(vv, w1, acc[1][xo]);
                    acc[2][xo] = fmaf(vv, w2, acc[2][xo]);
                    acc[3][xo] = fmaf(vv, w3, acc[3][xo]);
                }
            }
        }
    }
    int y = y0 + ty;
    #pragma unroll
    for (int oc = 0; oc < 4; oc++)
        #pragma unroll
        for (int xo = 0; xo < 4; xo++)
            out[(size_t)(oc0+oc)*65536 + y*256 + x0 + tx*4 + xo] = fmaxf(acc[oc][xo], 0.0f);
}

// ---------------- maxpool 3x3 s2 p1 ----------------
__global__ void maxpool_kernel(const float* __restrict__ in, float* __restrict__ out) {
    int idx = blockIdx.x * 256 + threadIdx.x;
    if (idx >= 64*128*128) return;
    int x = idx & 127;
    int y = (idx >> 7) & 127;
    int c = idx >> 14;
    float m = -INFINITY;
    #pragma unroll
    for (int dy = 0; dy < 3; dy++) {
        int iy = 2*y - 1 + dy;
        if (iy < 0 || iy >= 256) continue;
        #pragma unroll
        for (int dx = 0; dx < 3; dx++) {
            int ix = 2*x - 1 + dx;
            if (ix < 0 || ix >= 256) continue;
            m = fmaxf(m, in[(c*256 + iy)*256 + ix]);
        }
    }
    out[idx] = m;
}

// ---------------- im2col + split (fp32 CHW -> fp16 hi/lo patch matrix [M][K]) ----------------
__global__ void im2col_kernel(const float* __restrict__ in,
                              u16* __restrict__ Ah, u16* __restrict__ Al,
                              int Cin, int Hin, int Hout, int stride, int total) {
    int t = blockIdx.x * 256 + threadIdx.x;
    if (t >= total) return;
    int K = Cin * 9;
    int pix = t / K, col = t - pix * K;
    int c = col / 9, k = col - c * 9;
    int ky = k / 3, kx = k - ky * 3;
    int y = pix / Hout, x = pix - y * Hout;
    int gy = y*stride - 1 + ky, gx = x*stride - 1 + kx;
    float v = 0.0f;
    if (gy >= 0 && gy < Hin && gx >= 0 && gx < Hin)
        v = in[(size_t)c*Hin*Hin + gy*Hin + gx];
    split16(v, Ah[t], Al[t]);
}

// ---------------- weight split (already [N][K] row-major) ----------------
__global__ void wsplit_kernel(const float* __restrict__ W,
                              u16* __restrict__ Bh, u16* __restrict__ Bl, int total) {
    int t = blockIdx.x * 256 + threadIdx.x;
    if (t >= total) return;
    split16(W[t], Bh[t], Bl[t]);
}

// ---------------- mma helpers ----------------
__device__ __forceinline__ void mma16816_f32(float& d0, float& d1, float& d2, float& d3,
                                             uint32_t a0, uint32_t a1, uint32_t a2, uint32_t a3,
                                             uint32_t b0, uint32_t b1) {
    asm volatile("mma.sync.aligned.m16n8k16.row.col.f32.f16.f16.f32 "
                 "{%0,%1,%2,%3}, {%4,%5,%6,%7}, {%8,%9}, {%0,%1,%2,%3};\n"
                 : "+f"(d0), "+f"(d1), "+f"(d2), "+f"(d3)
                 : "r"(a0), "r"(a1), "r"(a2), "r"(a3), "r"(b0), "r"(b1));
}
__device__ __forceinline__ void cpasync16(uint32_t dst, const void* src) {
    asm volatile("cp.async.cg.shared.global [%0], [%1], 16;\n" :: "r"(dst), "l"(src));
}
__device__ __forceinline__ void ldsm_x4(uint32_t& r0, uint32_t& r1, uint32_t& r2, uint32_t& r3,
                                        uint32_t addr) {
    asm volatile("ldmatrix.sync.aligned.m8n8.x4.shared.b16 {%0,%1,%2,%3}, [%4];\n"
                 : "=r"(r0), "=r"(r1), "=r"(r2), "=r"(r3) : "r"(addr));
}

#define LDK 24

// ---------------- 3-pass split-fp16 GEMM (conv path): part[z][M][N] ----------------
__global__ void __launch_bounds__(256)
gemm_split3_kernel(const u16* __restrict__ Ah, const u16* __restrict__ Al,
                   const u16* __restrict__ Bh, const u16* __restrict__ Bl,
                   float* __restrict__ part, int K, int stages, int N) {
    __shared__ __align__(16) u16 sm[2][4][128*LDK];
    int tid = threadIdx.x;
    int wid = tid >> 5, lane = tid & 31;
    int wm = (wid & 1) * 64;
    int wn = (wid >> 1) * 32;
    int g = lane >> 2, tig = lane & 3;
    int r8 = lane & 7, q = lane >> 3;
    int bm = blockIdx.y * 128, bn = blockIdx.x * 128;
    int kbase = blockIdx.z * stages * 16;

    float acc[16][4], accx[16][4];
    #pragma unroll
    for (int i = 0; i < 16; i++)
        #pragma unroll
        for (int j = 0; j < 4; j++) { acc[i][j] = 0.0f; accx[i][j] = 0.0f; }

    uint32_t smb = (uint32_t)__cvta_generic_to_shared(&sm[0][0][0]);
    const uint32_t MAT = 128*LDK*2;
    const uint32_t BUF = 4*MAT;
    uint32_t offA = (uint32_t)(((wm + (q & 1)*8 + r8)*LDK + (q >> 1)*8) * 2);
    uint32_t offB = (uint32_t)(((wn + (q >> 1)*8 + r8)*LDK + (q & 1)*8) * 2);

    auto load_stage = [&](int buf, int s) {
        int kpos0 = kbase + s * 16;
        #pragma unroll
        for (int l = 0; l < 4; l++) {
            int idx = l * 256 + tid;
            int pl = idx >> 8;
            int rr = (idx & 255) >> 1;
            int half = idx & 1;
            int kpos = kpos0 + half * 8;
            const u16* src;
            if (pl == 0)      src = Ah + (size_t)(bm + rr)*K + kpos;
            else if (pl == 1) src = Al + (size_t)(bm + rr)*K + kpos;
            else if (pl == 2) src = Bh + (size_t)(bn + rr)*K + kpos;
            else              src = Bl + (size_t)(bn + rr)*K + kpos;
            uint32_t dst = (uint32_t)__cvta_generic_to_shared(&sm[buf][pl][rr*LDK + half*8]);
            cpasync16(dst, src);
        }
        asm volatile("cp.async.commit_group;\n");
    };

    load_stage(0, 0);

    for (int s = 0; s < stages; s++) {
        if (s + 1 < stages) {
            load_stage((s + 1) & 1, s + 1);
            asm volatile("cp.async.wait_group 1;\n");
        } else {
            asm volatile("cp.async.wait_group 0;\n");
        }
        __syncthreads();
        uint32_t base = smb + (uint32_t)(s & 1)*BUF;
        uint32_t aAh = base + offA;
        uint32_t aAl = base + MAT + offA;
        uint32_t aBh = base + 2*MAT + offB;
        uint32_t aBl = base + 3*MAT + offB;

        uint32_t bh[4][2], bl[4][2], ah[4][4], al[4][4];
        #pragma unroll
        for (int p = 0; p < 2; p++) {
            ldsm_x4(bh[2*p][0], bh[2*p][1], bh[2*p+1][0], bh[2*p+1][1], aBh + p*16*LDK*2);
            ldsm_x4(bl[2*p][0], bl[2*p][1], bl[2*p+1][0], bl[2*p+1][1], aBl + p*16*LDK*2);
        }
        #pragma unroll
        for (int mi = 0; mi < 4; mi++) {
            ldsm_x4(ah[mi][0], ah[mi][1], ah[mi][2], ah[mi][3], aAh + mi*16*LDK*2);
            ldsm_x4(al[mi][0], al[mi][1], al[mi][2], al[mi][3], aAl + mi*16*LDK*2);
        }

        #pragma unroll
        for (int mi = 0; mi < 4; mi++)
            #pragma unroll
            for (int ni = 0; ni < 4; ni++) {
                float* d = acc[mi*4 + ni];
                mma16816_f32(d[0], d[1], d[2], d[3],
                             ah[mi][0], ah[mi][1], ah[mi][2], ah[mi][3], bh[ni][0], bh[ni][1]);
            }
        #pragma unroll
        for (int mi = 0; mi < 4; mi++)
            #pragma unroll
            for (int ni = 0; ni < 4; ni++) {
                float* d = accx[mi*4 + ni];
                mma16816_f32(d[0], d[1], d[2], d[3],
                             ah[mi][0], ah[mi][1], ah[mi][2], ah[mi][3], bl[ni][0], bl[ni][1]);
            }
        #pragma unroll
        for (int mi = 0; mi < 4; mi++)
            #pragma unroll
            for (int ni = 0; ni < 4; ni++) {
                float* d = accx[mi*4 + ni];
                mma16816_f32(d[0], d[1], d[2], d[3],
                             al[mi][0], al[mi][1], al[mi][2], al[mi][3], bh[ni][0], bh[ni][1]);
            }
        __syncthreads();
    }

    size_t MN = (size_t)gridDim.y * 128 * N;
    float* cbase = part + (size_t)blockIdx.z * MN;
    #pragma unroll
    for (int mi = 0; mi < 4; mi++) {
        #pragma unroll
        for (int ni = 0; ni < 4; ni++) {
            int row = bm + wm + mi*16 + g;
            int col = bn + wn + ni*8 + 2*tig;
            float* d = acc[mi*4 + ni];
            float* x = accx[mi*4 + ni];
            *(float2*)&cbase[(size_t)row*N + col] =
                make_float2(fmaf(x[0], INVLOSCALE, d[0]), fmaf(x[1], INVLOSCALE, d[1]));
            *(float2*)&cbase[(size_t)(row+8)*N + col] =
                make_float2(fmaf(x[2], INVLOSCALE, d[2]), fmaf(x[3], INVLOSCALE, d[3]));
        }
    }
}

// reduce conv partials [z][pix][oc] -> CHW + bias + relu
__global__ void creduceT_kernel(const float* __restrict__ part,
                                const float* __restrict__ bias,
                                float* __restrict__ out, int M, int N, int z) {
    int idx = blockIdx.x * 256 + threadIdx.x;
    if (idx >= M*N) return;
    int pix = idx / N, oc = idx - pix*N;
    float s = bias[oc];
    size_t MN = (size_t)M*N;
    for (int i = 0; i < z; i++) s += part[i*MN + idx];
    out[(size_t)oc*M + pix] = fmaxf(s, 0.0f);
}

// ---------------- merged RPN 1x1 heads ----------------
__global__ void rpnheads_kernel(const float* __restrict__ in,
                                const float* __restrict__ clsw, const float* __restrict__ clsb,
                                const float* __restrict__ bbw, const float* __restrict__ bbb,
                                float* __restrict__ obj, float* __restrict__ bd) {
    int o = blockIdx.x;
    int p = threadIdx.x;
    const float* w;
    float acc;
    if (o < 9) { w = clsw + o*512; acc = clsb[o]; }
    else       { w = bbw + (o-9)*512; acc = bbb[o-9]; }
    for (int c = 0; c < 512; c++)
        acc = fmaf(in[c*256 + p], w[c], acc);
    if (o < 9) obj[o*256 + p] = acc;
    else       bd[(o-9)*256 + p] = acc;
}

// ---------------- RPN decode ----------------
__global__ void rpn_decode_kernel(const float* __restrict__ obj,
                                  const float* __restrict__ bd,
                                  float* __restrict__ props,
                                  float* __restrict__ scores) {
    int i = blockIdx.x * 256 + threadIdx.x;
    if (i >= 2304) return;
    int a = i % 9;
    int cell = i / 9;
    int wq = cell % 16;
    int hq = cell / 16;
    int pix = hq*16 + wq;
    scores[i] = obj[a*256 + pix];

    const float ratios[3] = {0.5f, 1.0f, 2.0f};
    int r = a / 3, s = a % 3;
    float scale = 128.0f * (float)(1 << s);
    float hr = sqrtf(ratios[r]);
    float wr = 1.0f / hr;
    float hw = rintf(wr * scale * 0.5f);
    float hh = rintf(hr * scale * 0.5f);
    float sx = (float)(wq * 32), sy = (float)(hq * 32);
    float W = 2.0f*hw, H = 2.0f*hh;
    float cx = sx, cy = sy;

    float dx = bd[(a*4+0)*256 + pix];
    float dy = bd[(a*4+1)*256 + pix];
    float dw = fminf(bd[(a*4+2)*256 + pix], BBOX_CLAMP);
    float dh = fminf(bd[(a*4+3)*256 + pix], BBOX_CLAMP);
    float pcx = dx*W + cx, pcy = dy*H + cy;
    float pw = expf(dw)*W, ph = expf(dh)*H;
    props[i*4+0] = pcx - 0.5f*pw;
    props[i*4+1] = pcy - 0.5f*ph;
    props[i*4+2] = pcx + 0.5f*pw;
    props[i*4+3] = pcy + 0.5f*ph;
}

// ---------------- top-k bitonic ----------------
__device__ __forceinline__ bool tk_lt(float sa, int ia, float sb, int ib) {
    return (sa > sb) || (sa == sb && ia < ib);
}
__global__ void topk_kernel(const float* __restrict__ scores, int* __restrict__ topidx) {
    __shared__ float s[4096];
    __shared__ int   ind[4096];
    int tid = threadIdx.x;
    for (int i = tid; i < 4096; i += 1024) {
        s[i] = (i < 2304) ? scores[i] : -INFINITY;
        ind[i] = i;
    }
    __syncthreads();
    for (int k = 2; k <= 4096; k <<= 1) {
        for (int j = k >> 1; j > 0; j >>= 1) {
            for (int base = 0; base < 4096; base += 1024) {
                int i = base + tid;
                int ixj = i ^ j;
                if (ixj > i) {
                    bool up = ((i & k) == 0);
                    float si = s[i], sj = s[ixj];
                    int ii = ind[i], ij = ind[ixj];
                    bool swp = up ? tk_lt(sj, ij, si, ii) : tk_lt(si, ii, sj, ij);
                    if (swp) { s[i] = sj; s[ixj] = si; ind[i] = ij; ind[ixj] = ii; }
                }
            }
            __syncthreads();
        }
    }
    for (int i = tid; i < TOPN; i += 1024) topidx[i] = ind[i];
}

__global__ void gather_rois_kernel(const float* __restrict__ props,
                                   const int* __restrict__ topidx,
                                   float* __restrict__ rois) {
    int i = blockIdx.x * 256 + threadIdx.x;
    if (i >= TOPN) return;
    int idx = topidx[i];
    #pragma unroll
    for (int k = 0; k < 4; k++)
        rois[i*4+k] = fminf(fmaxf(props[idx*4+k], 0.0f), 512.0f);
}

// ---------------- roi geometry precompute ----------------
__global__ void roigeo_kernel(const float* __restrict__ rois,
                              int* __restrict__ geoi, float* __restrict__ geow) {
    int t = blockIdx.x * 256 + threadIdx.x;
    if (t >= 1024*28) return;
    int rr = t / 28, i = t % 28;
    int ii = i % 14;
    bool isY = i >= 14;
    int pp = ii >> 1, sl = (ii & 1) * 2;
    int base = rr*56 + (isY ? 28 : 0) + pp*4 + sl;
    if (rr >= TOPN) {
        geoi[base] = 0; geoi[base+1] = 0;
        geow[base] = 0.0f; geow[base+1] = 0.0f;
        return;
    }
    float c1 = rois[rr*4 + (isY ? 1 : 0)];
    float c2 = rois[rr*4 + (isY ? 3 : 2)];
    float lo = c1 * (1.0f/32.0f);
    float hi = c2 * (1.0f/32.0f);
    float sz = fmaxf(hi - lo, 1.0f);
    float g = ((float)ii + 0.5f) / 14.0f;
    float p = fminf(fmaxf(lo + g*sz, 0.0f), 15.0f);
    int p0 = (int)floorf(p);
    int p1 = min(p0 + 1, 15);
    float l = p - (float)p0;
    geoi[base] = p0; geoi[base+1] = p1;
    geow[base] = 0.5f * (1.0f - l); geow[base+1] = 0.5f * l;
}

// ---------------- ROI align v3 ----------------
__global__ void __launch_bounds__(256)
roi_align3_kernel(const float* __restrict__ feat,
                  const int* __restrict__ geoi, const float* __restrict__ geow,
                  u16* __restrict__ Ah) {
    __shared__ float ftile[16*256];
    __shared__ int   si[64*56];
    __shared__ float sw[64*56];
    int cg = blockIdx.x;
    int chunk = blockIdx.y;
    int tid = threadIdx.x;
    {
        const float4* src = (const float4*)(feat + (size_t)cg*16*256);
        float4* dst = (float4*)ftile;
        for (int i = tid; i < 1024; i += 256) dst[i] = src[i];
    }
    int gbase = chunk*64*56;
    for (int i = tid; i < 64*56; i += 256) {
        si[i] = geoi[gbase + i];
        sw[i] = geow[gbase + i];
    }
    __syncthreads();

    for (int rl = 0; rl < 64; rl++) {
        int rr = chunk*64 + rl;
        const int* gi = si + rl*56;
        const float* gw = sw + rl*56;
        for (int t = tid; t < 784; t += 256) {
            int cl = t / 49, p = t % 49;
            int py = p / 7, px = p % 7;
            const float* f = ftile + cl*256;
            float acc = 0.0f;
            #pragma unroll
            for (int a = 0; a < 4; a++) {
                const float* frow = f + gi[28 + py*4 + a]*16;
                float s = 0.0f;
                #pragma unroll
                for (int bb = 0; bb < 4; bb++)
                    s = fmaf(gw[px*4 + bb], frow[gi[px*4 + bb]], s);
                acc = fmaf(gw[28 + py*4 + a], s, acc);
            }
            __half h = __float2half_rn(acc);
            Ah[(size_t)rr*25088 + (size_t)(cg*16 + cl)*49 + p] = *(u16*)&h;
        }
    }
}

// ---------------- transpose + fp16 weights ----------------
__global__ void tsplit_kernel(const float* __restrict__ W,
                              u16* __restrict__ Th, int K, int N) {
    __shared__ float t[32][33];
    int n0 = blockIdx.x * 32, k0 = blockIdx.y * 32;
    int tx = threadIdx.x, ty = threadIdx.y;
    #pragma unroll
    for (int i = 0; i < 4; i++)
        t[ty + 8*i][tx] = W[(size_t)(k0 + ty + 8*i)*N + n0 + tx];
    __syncthreads();
    #pragma unroll
    for (int i = 0; i < 4; i++) {
        __half h = __float2half_rn(t[tx][ty + 8*i]);
        Th[(size_t)(n0 + ty + 8*i)*K + k0 + tx] = *(u16*)&h;
    }
}

// ---------------- single-pass fp16 tensor-core GEMM (fc path) ----------------
__global__ void __launch_bounds__(256)
gemm_fp16_kernel(const u16* __restrict__ A, const u16* __restrict__ B,
                 float* __restrict__ part, int K, int stages) {
    __shared__ __align__(16) u16 sm[2][2][128*LDK];
    int tid = threadIdx.x;
    int wid = tid >> 5, lane = tid & 31;
    int wm = (wid & 1) * 64;
    int wn = (wid >> 1) * 32;
    int g = lane >> 2, tig = lane & 3;
    int r8 = lane & 7, q = lane >> 3;
    int bm = blockIdx.y * 128, bn = blockIdx.x * 128;
    int kbase = blockIdx.z * stages * 16;

    float acc[16][4];
    #pragma unroll
    for (int i = 0; i < 16; i++)
        #pragma unroll
        for (int j = 0; j < 4; j++) acc[i][j] = 0.0f;

    uint32_t smb = (uint32_t)__cvta_generic_to_shared(&sm[0][0][0]);
    const uint32_t MAT = 128*LDK*2;
    const uint32_t BUF = 2*MAT;
    uint32_t offA = (uint32_t)(((wm + (q & 1)*8 + r8)*LDK + (q >> 1)*8) * 2);
    uint32_t offB = (uint32_t)(((wn + (q >> 1)*8 + r8)*LDK + (q & 1)*8) * 2);

    auto load_stage = [&](int buf, int s) {
        int kpos0 = kbase + s * 16;
        #pragma unroll
        for (int l = 0; l < 2; l++) {
            int idx = l * 256 + tid;
            int pl = idx >> 8;
            int rr = (idx & 255) >> 1;
            int half = idx & 1;
            const u16* src = (pl ? B + (size_t)(bn + rr)*K : A + (size_t)(bm + rr)*K)
                             + kpos0 + half*8;
            uint32_t dst = (uint32_t)__cvta_generic_to_shared(&sm[buf][pl][rr*LDK + half*8]);
            cpasync16(dst, src);
        }
        asm volatile("cp.async.commit_group;\n");
    };

    load_stage(0, 0);

    for (int s = 0; s < stages; s++) {
        if (s + 1 < stages) {
            load_stage((s + 1) & 1, s + 1);
            asm volatile("cp.async.wait_group 1;\n");
        } else {
            asm volatile("cp.async.wait_group 0;\n");
        }
        __syncthreads();
        uint32_t base = smb + (uint32_t)(s & 1)*BUF;
        uint32_t aA = base + offA;
        uint32_t aB = base + MAT + offB;

        uint32_t bh[4][2], ah[4][4];
        #pragma unroll
        for (int p = 0; p < 2; p++)
            ldsm_x4(bh[2*p][0], bh[2*p][1], bh[2*p+1][0], bh[2*p+1][1], aB + p*16*LDK*2);
        #pragma unroll
        for (int mi = 0; mi < 4; mi++)
            ldsm_x4(ah[mi][0], ah[mi][1], ah[mi][2], ah[mi][3], aA + mi*16*LDK*2);

        #pragma unroll
        for (int mi = 0; mi < 4; mi++)
            #pragma unroll
            for (int ni = 0; ni < 4; ni++) {
                float* d = acc[mi*4 + ni];
                mma16816_f32(d[0], d[1], d[2], d[3],
                             ah[mi][0], ah[mi][1], ah[mi][2], ah[mi][3], bh[ni][0], bh[ni][1]);
            }
        __syncthreads();
    }

    float* cbase = part + ((size_t)blockIdx.z << 20);
    #pragma unroll
    for (int mi = 0; mi < 4; mi++) {
        #pragma unroll
        for (int ni = 0; ni < 4; ni++) {
            int row = bm + wm + mi*16 + g;
            int col = bn + wn + ni*8 + 2*tig;
            float* d = acc[mi*4 + ni];
            *(float2*)&cbase[(size_t)row*1024 + col]     = make_float2(d[0], d[1]);
            *(float2*)&cbase[(size_t)(row+8)*1024 + col] = make_float2(d[2], d[3]);
        }
    }
}

// reduce fc1 partials -> relu -> fp16 h1
__global__ void reduce1_kernel(const float* __restrict__ part,
                               const float* __restrict__ bias,
                               u16* __restrict__ Hh) {
    size_t idx = (size_t)blockIdx.x * 256 + threadIdx.x;
    int n = (int)(idx & 1023);
    float s = bias[n];
    #pragma unroll
    for (int i = 0; i < 16; i++) s += part[((size_t)i << 20) + idx];
    s = fmaxf(s, 0.0f);
    __half h = __float2half_rn(s);
    Hh[idx] = *(u16*)&h;
}

// reduce fc2 partials -> relu -> f32 h2
__global__ void reduce2_kernel(const float* __restrict__ part,
                               const float* __restrict__ bias,
                               float* __restrict__ H) {
    size_t idx = (size_t)blockIdx.x * 256 + threadIdx.x;
    int n = (int)(idx & 1023);
    float s = bias[n];
    #pragma unroll
    for (int i = 0; i < 4; i++) s += part[((size_t)i << 20) + idx];
    H[idx] = fmaxf(s, 0.0f);
}

// ---------------- cls + bbox heads: block per roi ----------------
__global__ void __launch_bounds__(256)
fc_small2_kernel(const float* __restrict__ h,
                 const float* __restrict__ clsw, const float* __restrict__ clsb,
                 const float* __restrict__ bbw, const float* __restrict__ bbb,
                 float* __restrict__ logits, float* __restrict__ breg) {
    __shared__ float hs[1024];
    int r = blockIdx.x;
    int tid = threadIdx.x;
    const float* hp = h + (size_t)r*1024;
    for (int i = tid; i < 1024; i += 256) hs[i] = hp[i];
    __syncthreads();
    if (tid < 240) {
        int j = tid >> 3, part = tid & 7;
        float acc = 0.0f;
        if (j < 6) {
            for (int k = part; k < 1024; k += 8)
                acc = fmaf(hs[k], clsw[k*6 + j], acc);
        } else {
            int q = j - 6;
            for (int k = part; k < 1024; k += 8)
                acc = fmaf(hs[k], bbw[k*24 + q], acc);
        }
        #pragma unroll
        for (int off = 4; off; off >>= 1)
            acc += __shfl_down_sync(0xffffffff, acc, off);
        if (part == 0) {
            if (j < 6) logits[r*6 + j] = acc + clsb[j];
            else       breg[r*24 + (j-6)] = acc + bbb[j-6];
        }
    }
}

// ---------------- final ----------------
__global__ void final_kernel(const float* __restrict__ rois,
                             const float* __restrict__ logits,
                             const float* __restrict__ breg,
                             float* __restrict__ out) {
    int r = blockIdx.x * 128 + threadIdx.x;
    if (r >= TOPN) return;
    float l[6];
    float m = -INFINITY;
    #pragma unroll
    for (int i = 0; i < 6; i++) { l[i] = logits[r*6 + i]; m = fmaxf(m, l[i]); }
    float ssum = 0.0f;
    #pragma unroll
    for (int i = 0; i < 6; i++) { l[i] = expf(l[i] - m); ssum += l[i]; }
    float inv = 1.0f / ssum;

    float x1 = rois[r*4+0], y1 = rois[r*4+1], x2 = rois[r*4+2], y2 = rois[r*4+3];
    float W = x2 - x1, H = y2 - y1;
    float cx = x1 + 0.5f*W, cy = y1 + 0.5f*H;
    #pragma unroll
    for (int c = 1; c < 6; c++) {
        float dx = breg[r*24 + c*4+0] / 10.0f;
        float dy = breg[r*24 + c*4+1] / 10.0f;
        float dw = fminf(breg[r*24 + c*4+2] / 5.0f, BBOX_CLAMP);
        float dh = fminf(breg[r*24 + c*4+3] / 5.0f, BBOX_CLAMP);
        float pcx = dx*W + cx, pcy = dy*H + cy;
        float pw = expf(dw)*W, ph = expf(dh)*H;
        float bx1 = fminf(fmaxf(pcx - 0.5f*pw, 0.0f), 512.0f);
        float by1 = fminf(fmaxf(pcy - 0.5f*ph, 0.0f), 512.0f);
        float bx2 = fminf(fmaxf(pcx + 0.5f*pw, 0.0f), 512.0f);
        float by2 = fminf(fmaxf(pcy + 0.5f*ph, 0.0f), 512.0f);
        int o = r*25 + (c-1)*5;
        out[o+0] = bx1; out[o+1] = by1; out[o+2] = bx2; out[o+3] = by2;
        out[o+4] = l[c] * inv;
    }
}

// ---------------- launcher ----------------
extern "C" void kernel_launch(void* const* d_in, const int* in_sizes, int n_in,
                              void* d_out, int out_size) {
    const float* images     = (const float*)d_in[0];
    const float* c0_w       = (const float*)d_in[1];
    const float* c0_b       = (const float*)d_in[2];
    const float* c1_w       = (const float*)d_in[3];
    const float* c1_b       = (const float*)d_in[4];
    const float* c2_w       = (const float*)d_in[5];
    const float* c2_b       = (const float*)d_in[6];
    const float* c3_w       = (const float*)d_in[7];
    const float* c3_b       = (const float*)d_in[8];
    const float* rpn_conv_w = (const float*)d_in[9];
    const float* rpn_conv_b = (const float*)d_in[10];
    const float* rpn_cls_w  = (const float*)d_in[11];
    const float* rpn_cls_b  = (const float*)d_in[12];
    const float* rpn_bbox_w = (const float*)d_in[13];
    const float* rpn_bbox_b = (const float*)d_in[14];
    const float* fc1_w      = (const float*)d_in[15];
    const float* fc1_b      = (const float*)d_in[16];
    const float* fc2_w      = (const float*)d_in[17];
    const float* fc2_b      = (const float*)d_in[18];
    const float* cls_w      = (const float*)d_in[19];
    const float* cls_b      = (const float*)d_in[20];
    const float* bbox_w     = (const float*)d_in[21];
    const float* bbox_b     = (const float*)d_in[22];
    float* out = (float*)d_out;

    float *p_c0, *p_pool, *p_c1, *p_c2, *p_feat, *p_rpn, *p_obj, *p_bd;
    float *p_props, *p_scores, *p_rois, *p_part, *p_h2, *p_logits, *p_breg, *p_geow;
    int *p_topidx, *p_geoi;
    u16 *p_Ah, *p_B1h, *p_B2h, *p_h1h, *p_cAh, *p_cAl, *p_cBh, *p_cBl;
    cudaGetSymbolAddress((void**)&p_c0, g_c0);
    cudaGetSymbolAddress((void**)&p_pool, g_pool);
    cudaGetSymbolAddress((void**)&p_c1, g_c1);
    cudaGetSymbolAddress((void**)&p_c2, g_c2);
    cudaGetSymbolAddress((void**)&p_feat, g_feat);
    cudaGetSymbolAddress((void**)&p_rpn, g_rpn);
    cudaGetSymbolAddress((void**)&p_obj, g_obj);
    cudaGetSymbolAddress((void**)&p_bd, g_bd);
    cudaGetSymbolAddress((void**)&p_props, g_props);
    cudaGetSymbolAddress((void**)&p_scores, g_scores);
    cudaGetSymbolAddress((void**)&p_topidx, g_topidx);
    cudaGetSymbolAddress((void**)&p_rois, g_rois);
    cudaGetSymbolAddress((void**)&p_geoi, g_geoi);
    cudaGetSymbolAddress((void**)&p_geow, g_geow);
    cudaGetSymbolAddress((void**)&p_cAh, g_cAh);
    cudaGetSymbolAddress((void**)&p_cAl, g_cAl);
    cudaGetSymbolAddress((void**)&p_cBh, g_cBh);
    cudaGetSymbolAddress((void**)&p_cBl, g_cBl);
    cudaGetSymbolAddress((void**)&p_Ah, g_Ah);
    cudaGetSymbolAddress((void**)&p_B1h, g_B1h);
    cudaGetSymbolAddress((void**)&p_B2h, g_B2h);
    cudaGetSymbolAddress((void**)&p_h1h, g_h1h);
    cudaGetSymbolAddress((void**)&p_part, g_part);
    cudaGetSymbolAddress((void**)&p_h2, g_h2);
    cudaGetSymbolAddress((void**)&p_logits, g_logits);
    cudaGetSymbolAddress((void**)&p_breg, g_breg);

    // second stream for independent weight transpose
    static cudaStream_t s2 = 0;
    static cudaEvent_t evF = 0, evJ = 0;
    if (!s2) {
        cudaStreamCreateWithFlags(&s2, cudaStreamNonBlocking);
        cudaEventCreateWithFlags(&evF, cudaEventDisableTiming);
        cudaEventCreateWithFlags(&evJ, cudaEventDisableTiming);
    }
    cudaEventRecord(evF, 0);
    cudaStreamWaitEvent(s2, evF, 0);
    tsplit_kernel<<<dim3(1024/32, 25088/32), dim3(32,8), 0, s2>>>(fc1_w, p_B1h, 25088, 1024);
    tsplit_kernel<<<dim3(1024/32, 1024/32),  dim3(32,8), 0, s2>>>(fc2_w, p_B2h, 1024, 1024);
    cudaEventRecord(evJ, s2);

    // backbone: conv0 + pool (fp32), then implicit-GEMM convs
    conv0v2_kernel<<<dim3(8,16,16), dim3(8,16)>>>(images, c0_w, c0_b, p_c0);
    maxpool_kernel<<<(64*128*128 + 255)/256, 256>>>(p_c0, p_pool);

    // c1: Cin64 Hin128 -> 64x64, N=128, K=576, z=9 (4 stages)
    im2col_kernel<<<(4096*576 + 255)/256, 256>>>(p_pool, p_cAh, p_cAl, 64, 128, 64, 2, 4096*576);
    wsplit_kernel<<<(128*576 + 255)/256, 256>>>(c1_w, p_cBh, p_cBl, 128*576);
    gemm_split3_kernel<<<dim3(1,32,9), 256>>>(p_cAh, p_cAl, p_cBh, p_cBl, p_part, 576, 4, 128);
    creduceT_kernel<<<(4096*128 + 255)/256, 256>>>(p_part, c1_b, p_c1, 4096, 128, 9);

    // c2: Cin128 Hin64 -> 32x32, N=256, K=1152, z=12 (6 stages)
    im2col_kernel<<<(1024*1152 + 255)/256, 256>>>(p_c1, p_cAh, p_cAl, 128, 64, 32, 2, 1024*1152);
    wsplit_kernel<<<(256*1152 + 255)/256, 256>>>(c2_w, p_cBh, p_cBl, 256*1152);
    gemm_split3_kernel<<<dim3(2,8,12), 256>>>(p_cAh, p_cAl, p_cBh, p_cBl, p_part, 1152, 6, 256);
    creduceT_kernel<<<(1024*256 + 255)/256, 256>>>(p_part, c2_b, p_c2, 1024, 256, 12);

    // c3: Cin256 Hin32 -> 16x16, N=512, K=2304, z=18 (8 stages)
    im2col_kernel<<<(256*2304 + 255)/256, 256>>>(p_c2, p_cAh, p_cAl, 256, 32, 16, 2, 256*2304);
    wsplit_kernel<<<(512*2304 + 255)/256, 256>>>(c3_w, p_cBh, p_cBl, 512*2304);
    gemm_split3_kernel<<<dim3(4,2,18), 256>>>(p_cAh, p_cAl, p_cBh, p_cBl, p_part, 2304, 8, 512);
    creduceT_kernel<<<(256*512 + 255)/256, 256>>>(p_part, c3_b, p_feat, 256, 512, 18);

    // rpn: Cin512 Hin16 -> 16x16 s1, N=512, K=4608, z=24 (12 stages)
    im2col_kernel<<<(256*4608 + 255)/256, 256>>>(p_feat, p_cAh, p_cAl, 512, 16, 16, 1, 256*4608);
    wsplit_kernel<<<(512*4608 + 255)/256, 256>>>(rpn_conv_w, p_cBh, p_cBl, 512*4608);
    gemm_split3_kernel<<<dim3(4,2,24), 256>>>(p_cAh, p_cAl, p_cBh, p_cBl, p_part, 4608, 12, 512);
    creduceT_kernel<<<(256*512 + 255)/256, 256>>>(p_part, rpn_conv_b, p_rpn, 256, 512, 24);

    // RPN heads
    rpnheads_kernel<<<45, 256>>>(p_rpn, rpn_cls_w, rpn_cls_b, rpn_bbox_w, rpn_bbox_b, p_obj, p_bd);

    // proposals
    rpn_decode_kernel<<<9, 256>>>(p_obj, p_bd, p_props, p_scores);
    topk_kernel<<<1, 1024>>>(p_scores, p_topidx);
    gather_rois_kernel<<<4, 256>>>(p_props, p_topidx, p_rois);

    // roi align v3 -> fp16 A
    roigeo_kernel<<<(1024*28 + 255)/256, 256>>>(p_rois, p_geoi, p_geow);
    roi_align3_kernel<<<dim3(32,16), 256>>>(p_feat, p_geoi, p_geow, p_Ah);

    // join: fc weights ready
    cudaStreamWaitEvent(0, evJ, 0);

    // fc1: K=25088, z=16 -> stages 98
    gemm_fp16_kernel<<<dim3(8,8,16), 256>>>(p_Ah, p_B1h, p_part, 25088, 98);
    reduce1_kernel<<<(1024*1024)/256, 256>>>(p_part, fc1_b, p_h1h);

    // fc2: K=1024, z=4 -> stages 16
    gemm_fp16_kernel<<<dim3(8,8,4), 256>>>(p_h1h, p_B2h, p_part, 1024, 16);
    reduce2_kernel<<<(1024*1024)/256, 256>>>(p_part, fc2_b, p_h2);

    fc_small2_kernel<<<TOPN, 256>>>(p_h2, cls_w, cls_b, bbox_w, bbox_b, p_logits, p_breg);
    final_kernel<<<(TOPN + 127)/128, 128>>>(p_rois, p_logits, p_breg, out);
}